// round 2
// baseline (speedup 1.0000x reference)
#include <cuda_runtime.h>
#include <math.h>

// Problem constants
#define BB 2
#define SS 1024
#define HH 768
#define NH 12
#define DH 64
#define FF 3072
#define NL 4

// ---------------- scratch buffers (device globals: no allocation allowed) ----------------
__device__ float g_h[BB*SS*HH];
__device__ float g_q[BB*SS*HH];
__device__ float g_k[BB*SS*HH];
__device__ float g_v[BB*SS*HH];
__device__ float g_ctx[BB*SS*HH];
__device__ float g_tmp[BB*SS*HH];
__device__ float g_attn[BB*SS*HH];
__device__ float g_inter[BB*SS*FF];
__device__ float g_probs[(long)BB*NH*SS*SS];

// ---------------- generic tiled SGEMM with fused bias / residual / gelu ----------------
// C[M,N] = A[M,K] @ B[K,N] (+bias[N]) (+resid) ; tiles 64x64x16, 4x4 microtile, 256 threads.
// mode 0: single matrix. mode 1: per-(b,h) attention-ctx batch via blockIdx.z.
__global__ __launch_bounds__(256) void gemm_kernel(
    const float* __restrict__ A, const float* __restrict__ Bm,
    const float* __restrict__ bias, const float* __restrict__ resid,
    float* __restrict__ C,
    int M, int N, int K, int lda, int ldb, int ldc,
    int mode, int gelu)
{
    __shared__ __align__(16) float As[16][68];
    __shared__ __align__(16) float Bs[16][68];

    const int tx = threadIdx.x, ty = threadIdx.y;
    const int tid = ty * 16 + tx;
    const int m0 = blockIdx.y * 64, n0 = blockIdx.x * 64;

    long aOff = 0, bOff = 0, cOff = 0;
    if (mode == 1) {
        int z = blockIdx.z;
        aOff = (long)z * M * K;                       // probs contiguous per (b,h)
        int bb = z / NH, hh = z % NH;
        bOff = (long)bb * SS * HH + hh * DH;          // v / ctx slice
        cOff = bOff;
    }

    const int lrow = tid >> 2;   // 0..63  A-tile row
    const int lkq  = tid & 3;    // 0..3   A-tile k quarter
    const int brow = tid >> 4;   // 0..15  B-tile k row
    const int bcol = tid & 15;   // 0..15  B-tile col quarter

    float acc[4][4] = {};

    for (int k0 = 0; k0 < K; k0 += 16) {
        float4 av = *(const float4*)(A + aOff + (long)(m0 + lrow) * lda + k0 + lkq * 4);
        As[lkq*4+0][lrow] = av.x;
        As[lkq*4+1][lrow] = av.y;
        As[lkq*4+2][lrow] = av.z;
        As[lkq*4+3][lrow] = av.w;
        float4 bv = *(const float4*)(Bm + bOff + (long)(k0 + brow) * ldb + n0 + bcol * 4);
        *(float4*)&Bs[brow][bcol*4] = bv;
        __syncthreads();

        #pragma unroll
        for (int kk = 0; kk < 16; kk++) {
            float4 a = *(const float4*)&As[kk][ty*4];
            float4 b = *(const float4*)&Bs[kk][tx*4];
            acc[0][0] += a.x*b.x; acc[0][1] += a.x*b.y; acc[0][2] += a.x*b.z; acc[0][3] += a.x*b.w;
            acc[1][0] += a.y*b.x; acc[1][1] += a.y*b.y; acc[1][2] += a.y*b.z; acc[1][3] += a.y*b.w;
            acc[2][0] += a.z*b.x; acc[2][1] += a.z*b.y; acc[2][2] += a.z*b.z; acc[2][3] += a.z*b.w;
            acc[3][0] += a.w*b.x; acc[3][1] += a.w*b.y; acc[3][2] += a.w*b.z; acc[3][3] += a.w*b.w;
        }
        __syncthreads();
    }

    const int col = n0 + tx * 4;
    float4 bs = bias ? *(const float4*)(bias + col) : make_float4(0.f,0.f,0.f,0.f);
    #pragma unroll
    for (int i = 0; i < 4; i++) {
        int row = m0 + ty * 4 + i;
        float4 rs = resid ? *(const float4*)(resid + (long)row * ldc + col)
                          : make_float4(0.f,0.f,0.f,0.f);
        float4 o;
        o.x = acc[i][0] + bs.x + rs.x;
        o.y = acc[i][1] + bs.y + rs.y;
        o.z = acc[i][2] + bs.z + rs.z;
        o.w = acc[i][3] + bs.w + rs.w;
        if (gelu) {
            o.x = 0.5f * o.x * (1.0f + erff(o.x * 0.70710678118654752f));
            o.y = 0.5f * o.y * (1.0f + erff(o.y * 0.70710678118654752f));
            o.z = 0.5f * o.z * (1.0f + erff(o.z * 0.70710678118654752f));
            o.w = 0.5f * o.w * (1.0f + erff(o.w * 0.70710678118654752f));
        }
        *(float4*)(C + cOff + (long)row * ldc + col) = o;
    }
}

// ---------------- fused attention scores + mask + softmax -> probs ----------------
// Block: (q-tile of 32 rows) x (b,h). 256 threads. Dynamic smem:
//   qs[64][36] transposed q tile, ks[64][66] transposed k tile, sc[32][1024] scores.
__global__ __launch_bounds__(256) void attn_scores_softmax(
    const float* __restrict__ q, const float* __restrict__ k,
    const int* __restrict__ mask, float* __restrict__ probs)
{
    extern __shared__ __align__(16) float sm[];
    float* qs = sm;                      // 64*36
    float* ks = sm + 64*36;              // 64*66
    float* sc = sm + 64*36 + 64*66;      // 32*1024

    const int tid = threadIdx.x;
    const int qt = blockIdx.x;           // 0..31
    const int bh = blockIdx.y;           // 0..23
    const int b = bh / NH, h = bh % NH;
    const int q0 = qt * 32;

    const float* qbase = q + (long)b * SS * HH + h * DH;
    const float* kbase = k + (long)b * SS * HH + h * DH;

    // load q tile (32 rows x 64 dims), transposed to qs[d][row]
    {
        int r = tid >> 4, dq = tid & 15;
        #pragma unroll
        for (int it = 0; it < 2; it++) {
            int row = r + it * 16;
            float4 v = *(const float4*)(qbase + (long)(q0 + row) * HH + dq * 4);
            qs[(dq*4+0)*36 + row] = v.x;
            qs[(dq*4+1)*36 + row] = v.y;
            qs[(dq*4+2)*36 + row] = v.z;
            qs[(dq*4+3)*36 + row] = v.w;
        }
    }

    const int qg = tid >> 5;   // 0..7  -> q rows 4*qg..4*qg+3
    const int kg = tid & 31;   // 0..31 -> k cols 2*kg..2*kg+1

    for (int kt = 0; kt < 16; kt++) {
        const int k0 = kt * 64;
        __syncthreads();  // protect ks reuse (and q-tile on first iter)
        {
            int rk = tid >> 4, dq = tid & 15;
            #pragma unroll
            for (int it = 0; it < 4; it++) {
                int ki = rk + it * 16;
                float4 v = *(const float4*)(kbase + (long)(k0 + ki) * HH + dq * 4);
                ks[(dq*4+0)*66 + ki] = v.x;
                ks[(dq*4+1)*66 + ki] = v.y;
                ks[(dq*4+2)*66 + ki] = v.z;
                ks[(dq*4+3)*66 + ki] = v.w;
            }
        }
        __syncthreads();

        float acc[4][2] = {};
        #pragma unroll 8
        for (int d = 0; d < 64; d++) {
            float4 qv = *(const float4*)&qs[d*36 + qg*4];
            float2 kv = *(const float2*)&ks[d*66 + kg*2];
            acc[0][0] += qv.x * kv.x; acc[0][1] += qv.x * kv.y;
            acc[1][0] += qv.y * kv.x; acc[1][1] += qv.y * kv.y;
            acc[2][0] += qv.z * kv.x; acc[2][1] += qv.z * kv.y;
            acc[3][0] += qv.w * kv.x; acc[3][1] += qv.w * kv.y;
        }
        #pragma unroll
        for (int i = 0; i < 4; i++) {
            float2 st; st.x = acc[i][0]; st.y = acc[i][1];
            *(float2*)&sc[(qg*4+i)*1024 + k0 + kg*2] = st;
        }
    }
    __syncthreads();

    // softmax: 8 warps x 4 rows each
    const int warp = tid >> 5, lane = tid & 31;
    const float scale = 0.125f;  // 1/sqrt(64)
    #pragma unroll
    for (int rr = 0; rr < 4; rr++) {
        int r = warp * 4 + rr;
        float* srow = &sc[r * 1024];
        const int* mrow = mask + (long)b * SS * SS + (long)(q0 + r) * SS;
        float mx = -1e30f;
        for (int c = lane; c < 1024; c += 32) {
            float v = srow[c] * scale + (1.0f - (float)mrow[c]) * (-10000.0f);
            srow[c] = v;
            mx = fmaxf(mx, v);
        }
        #pragma unroll
        for (int o = 16; o; o >>= 1) mx = fmaxf(mx, __shfl_xor_sync(0xffffffffu, mx, o));
        float s = 0.f;
        for (int c = lane; c < 1024; c += 32) {
            float e = __expf(srow[c] - mx);
            srow[c] = e;
            s += e;
        }
        #pragma unroll
        for (int o = 16; o; o >>= 1) s += __shfl_xor_sync(0xffffffffu, s, o);
        float inv = 1.0f / s;
        float* prow = probs + ((long)bh * SS + q0 + r) * SS;
        for (int c = lane; c < 1024; c += 32) prow[c] = srow[c] * inv;
    }
}

// ---------------- LayerNorm (one block per row of 768) ----------------
__global__ __launch_bounds__(256) void ln_kernel(
    const float* __restrict__ x, const float* __restrict__ g,
    const float* __restrict__ b, float* __restrict__ out)
{
    const int row = blockIdx.x;
    const int tid = threadIdx.x;
    const float* xr = x + (long)row * HH;
    float v0 = xr[tid], v1 = xr[tid + 256], v2 = xr[tid + 512];

    __shared__ float red[8];
    float s = v0 + v1 + v2;
    #pragma unroll
    for (int o = 16; o; o >>= 1) s += __shfl_xor_sync(0xffffffffu, s, o);
    if ((tid & 31) == 0) red[tid >> 5] = s;
    __syncthreads();
    float tot = 0.f;
    #pragma unroll
    for (int i = 0; i < 8; i++) tot += red[i];
    float mean = tot * (1.0f / 768.0f);

    float d0 = v0 - mean, d1 = v1 - mean, d2 = v2 - mean;
    float sq = d0*d0 + d1*d1 + d2*d2;
    __syncthreads();
    #pragma unroll
    for (int o = 16; o; o >>= 1) sq += __shfl_xor_sync(0xffffffffu, sq, o);
    if ((tid & 31) == 0) red[tid >> 5] = sq;
    __syncthreads();
    float tot2 = 0.f;
    #pragma unroll
    for (int i = 0; i < 8; i++) tot2 += red[i];
    float rstd = rsqrtf(tot2 * (1.0f / 768.0f) + 1e-12f);

    float* orow = out + (long)row * HH;
    orow[tid]       = d0 * rstd * g[tid]       + b[tid];
    orow[tid + 256] = d1 * rstd * g[tid + 256] + b[tid + 256];
    orow[tid + 512] = d2 * rstd * g[tid + 512] + b[tid + 512];
}

// ---------------- launch ----------------
extern "C" void kernel_launch(void* const* d_in, const int* in_sizes, int n_in,
                              void* d_out, int out_size)
{
    const float* x    = (const float*)d_in[0];
    const int*   mask = (const int*)  d_in[1];
    const float* Wq   = (const float*)d_in[2];
    const float* bq   = (const float*)d_in[3];
    const float* Wk   = (const float*)d_in[4];
    const float* bk   = (const float*)d_in[5];
    const float* Wv   = (const float*)d_in[6];
    const float* bv   = (const float*)d_in[7];
    const float* Wao  = (const float*)d_in[8];
    const float* bao  = (const float*)d_in[9];
    const float* g1   = (const float*)d_in[10];
    const float* b1   = (const float*)d_in[11];
    const float* Wi   = (const float*)d_in[12];
    const float* bi   = (const float*)d_in[13];
    const float* Wfo  = (const float*)d_in[14];
    const float* bfo  = (const float*)d_in[15];
    const float* g2   = (const float*)d_in[16];
    const float* b2   = (const float*)d_in[17];

    float *h_, *q_, *k_, *v_, *ctx_, *tmp_, *attn_, *inter_, *probs_;
    cudaGetSymbolAddress((void**)&h_,     g_h);
    cudaGetSymbolAddress((void**)&q_,     g_q);
    cudaGetSymbolAddress((void**)&k_,     g_k);
    cudaGetSymbolAddress((void**)&v_,     g_v);
    cudaGetSymbolAddress((void**)&ctx_,   g_ctx);
    cudaGetSymbolAddress((void**)&tmp_,   g_tmp);
    cudaGetSymbolAddress((void**)&attn_,  g_attn);
    cudaGetSymbolAddress((void**)&inter_, g_inter);
    cudaGetSymbolAddress((void**)&probs_, g_probs);

    const int smem_scores = (64*36 + 64*66 + 32*1024) * 4;  // 157184 bytes
    cudaFuncSetAttribute(attn_scores_softmax,
                         cudaFuncAttributeMaxDynamicSharedMemorySize, smem_scores);

    const dim3 blk(16, 16);
    const int M = BB * SS;  // 2048

    for (int l = 0; l < NL; l++) {
        const float* hin = (l == 0) ? x : h_;
        const float* wq = Wq + (long)l*HH*HH;
        const float* wk = Wk + (long)l*HH*HH;
        const float* wv = Wv + (long)l*HH*HH;
        const float* wo = Wao + (long)l*HH*HH;
        const float* wi = Wi + (long)l*HH*FF;
        const float* wf = Wfo + (long)l*FF*HH;

        // Q, K, V projections
        gemm_kernel<<<dim3(HH/64, M/64, 1), blk>>>(hin, wq, bq + l*HH, nullptr, q_,
                                                   M, HH, HH, HH, HH, HH, 0, 0);
        gemm_kernel<<<dim3(HH/64, M/64, 1), blk>>>(hin, wk, bk + l*HH, nullptr, k_,
                                                   M, HH, HH, HH, HH, HH, 0, 0);
        gemm_kernel<<<dim3(HH/64, M/64, 1), blk>>>(hin, wv, bv + l*HH, nullptr, v_,
                                                   M, HH, HH, HH, HH, HH, 0, 0);

        // scores + mask + softmax
        attn_scores_softmax<<<dim3(SS/32, BB*NH), 256, smem_scores>>>(q_, k_, mask, probs_);

        // ctx = probs @ v (batched per (b,h))
        gemm_kernel<<<dim3(1, SS/64, BB*NH), blk>>>(probs_, v_, nullptr, nullptr, ctx_,
                                                    SS, DH, SS, SS, HH, HH, 1, 0);

        // attention output proj + residual
        gemm_kernel<<<dim3(HH/64, M/64, 1), blk>>>(ctx_, wo, bao + l*HH, hin, tmp_,
                                                   M, HH, HH, HH, HH, HH, 0, 0);
        ln_kernel<<<M, 256>>>(tmp_, g1 + l*HH, b1 + l*HH, attn_);

        // FFN
        gemm_kernel<<<dim3(FF/64, M/64, 1), blk>>>(attn_, wi, bi + l*FF, nullptr, inter_,
                                                   M, FF, HH, HH, FF, FF, 0, 1);
        gemm_kernel<<<dim3(HH/64, M/64, 1), blk>>>(inter_, wf, bfo + l*HH, attn_, tmp_,
                                                   M, HH, FF, FF, HH, HH, 0, 0);

        float* lnout = (l == NL - 1) ? (float*)d_out : h_;
        ln_kernel<<<M, 256>>>(tmp_, g2 + l*HH, b2 + l*HH, lnout);
    }
}

// round 4
// speedup vs baseline: 1.6705x; 1.6705x over previous
#include <cuda_runtime.h>
#include <cuda_bf16.h>
#include <math.h>
#include <stdint.h>

#define BB 2
#define SS 1024
#define HH 768
#define NH 12
#define DH 64
#define FF 3072
#define NL 4

// ---------------- scratch (device globals; no allocation allowed) ----------------
__device__ float g_h[BB*SS*HH];
__device__ float g_q[BB*SS*HH];
__device__ float g_k[BB*SS*HH];
__device__ float g_v[BB*SS*HH];
__device__ float g_ctx[BB*SS*HH];
__device__ float g_tmp[BB*SS*HH];
__device__ float g_attn[BB*SS*HH];
__device__ float g_inter[BB*SS*FF];
__device__ float g_probs[(long)BB*NH*SS*SS];

// bf16 hi/lo split activations (sized for largest: 2048 x 3072)
__device__ __nv_bfloat16 g_ah[BB*SS*FF];
__device__ __nv_bfloat16 g_al[BB*SS*FF];
// transposed+split weights per layer: [wq wk wv wao wi wfo], each [N][K] row-major
#define WQOFF  0
#define WKOFF  589824
#define WVOFF  1179648
#define WAOOFF 1769472
#define WIOFF  2359296
#define WFOOFF 4718592
#define LSTRIDE 7077888
__device__ __nv_bfloat16 g_wh[(size_t)NL*LSTRIDE];
__device__ __nv_bfloat16 g_wl[(size_t)NL*LSTRIDE];

// ---------------- PTX helpers (arch-neutral: ldmatrix / mma.sync / cp.async) ----------------
__device__ __forceinline__ uint32_t smem_u32(const void* p) {
    uint32_t a;
    asm("{ .reg .u64 t; cvta.to.shared.u64 t, %1; cvt.u32.u64 %0, t; }" : "=r"(a) : "l"(p));
    return a;
}
__device__ __forceinline__ void cpa16(uint32_t dst, const void* src) {
    asm volatile("cp.async.cg.shared.global [%0], [%1], 16;" :: "r"(dst), "l"(src));
}
#define CP_COMMIT() asm volatile("cp.async.commit_group;" ::: "memory")

__device__ __forceinline__ void ldsm4(uint32_t* r, uint32_t a) {
    asm volatile("ldmatrix.sync.aligned.m8n8.x4.shared.b16 {%0,%1,%2,%3}, [%4];"
        : "=r"(r[0]), "=r"(r[1]), "=r"(r[2]), "=r"(r[3]) : "r"(a));
}
__device__ __forceinline__ void mma16816(float* c, const uint32_t* a, const uint32_t* b) {
    asm volatile("mma.sync.aligned.m16n8k16.row.col.f32.bf16.bf16.f32 "
        "{%0,%1,%2,%3}, {%4,%5,%6,%7}, {%8,%9}, {%0,%1,%2,%3};"
        : "+f"(c[0]), "+f"(c[1]), "+f"(c[2]), "+f"(c[3])
        : "r"(a[0]), "r"(a[1]), "r"(a[2]), "r"(a[3]), "r"(b[0]), "r"(b[1]));
}

// ---------------- bf16x3 HMMA GEMM: C = A @ B^T (+bias)(+resid)(gelu) ----------------
// A: hi/lo [M,K] bf16 row-major. B: hi/lo [N,K] bf16 row-major (pre-transposed weight).
// CTA tile 128x128, K-chunk 32, 512 threads (16 warps, 4x4 grid, 32x32 warp tiles).
struct GemmArgs {
    const __nv_bfloat16 *ah, *al;
    const __nv_bfloat16 *bh0, *bh1, *bh2, *bl0, *bl1, *bl2;
    const float *bias0, *bias1, *bias2;
    const float *resid;
    float *c0, *c1, *c2;
    int K, N, gelu;
};

#define ABUF 10240            // 128 rows * 80B (64B data + 16B pad)
#define STGB (4*ABUF)         // Ah, Al, Bh, Bl
#define NSTG 3
#define GEMM_SMEM (NSTG*STGB) // 122880

__global__ __launch_bounds__(512) void gemm_tc(GemmArgs g) {
    extern __shared__ char smem[];
    const uint32_t su = smem_u32(smem);
    const int tid = threadIdx.x;
    const int lane = tid & 31, warp = tid >> 5;
    const int warpM = warp & 3, warpN = warp >> 2;
    const int m0 = blockIdx.y << 7, n0 = blockIdx.x << 7;

    const __nv_bfloat16 *bh, *bl; const float* bias; float* C;
    if (blockIdx.z == 0)      { bh = g.bh0; bl = g.bl0; bias = g.bias0; C = g.c0; }
    else if (blockIdx.z == 1) { bh = g.bh1; bl = g.bl1; bias = g.bias1; C = g.c1; }
    else                      { bh = g.bh2; bl = g.bl2; bias = g.bias2; C = g.c2; }
    const int K = g.K, N = g.N, nk = K >> 5;

    // global load pointers: thread t loads 16B chunk (row = t/4, chunk = t%4) of each buffer
    const int ldg_row = tid >> 2, ldg_c = tid & 3;
    const size_t ldab = (size_t)K * 2;
    const char* pAh = (const char*)g.ah + ((size_t)(m0 + ldg_row)) * ldab + ldg_c * 16;
    const char* pAl = (const char*)g.al + ((size_t)(m0 + ldg_row)) * ldab + ldg_c * 16;
    const char* pBh = (const char*)bh   + ((size_t)(n0 + ldg_row)) * ldab + ldg_c * 16;
    const char* pBl = (const char*)bl   + ((size_t)(n0 + ldg_row)) * ldab + ldg_c * 16;
    const uint32_t sdst = ldg_row * 80 + ldg_c * 16;

    auto load_chunk = [&](int j, int s) {
        uint32_t sb = su + s * STGB + sdst;
        size_t go = (size_t)j * 64;      // 32 bf16 along K = 64 bytes
        cpa16(sb,            pAh + go);
        cpa16(sb +   ABUF,   pAl + go);
        cpa16(sb + 2*ABUF,   pBh + go);
        cpa16(sb + 3*ABUF,   pBl + go);
    };

    load_chunk(0, 0); CP_COMMIT();
    load_chunk(1, 1); CP_COMMIT();

    float acc[2][4][4];
    #pragma unroll
    for (int i = 0; i < 2; i++)
        #pragma unroll
        for (int j = 0; j < 4; j++)
            #pragma unroll
            for (int r = 0; r < 4; r++) acc[i][j][r] = 0.f;

    // ldmatrix lane addressing
    const uint32_t a_off = (uint32_t)(warpM*32 + (lane & 15)) * 80 + (lane >> 4) * 16;
    const uint32_t b_off = (uint32_t)(warpN*32 + (((lane >> 4) & 1) << 3) + (lane & 7)) * 80
                         + ((lane >> 3) & 1) * 16;

    for (int i = 0; i < nk; i++) {
        asm volatile("cp.async.wait_group 1;" ::: "memory");
        __syncthreads();
        int j = i + 2;
        if (j < nk) load_chunk(j, j % NSTG);
        CP_COMMIT();

        uint32_t base = su + (i % NSTG) * STGB;
        #pragma unroll
        for (int ks = 0; ks < 2; ks++) {
            uint32_t ko = ks * 32;
            uint32_t ah0[4], ah1[4], al0[4], al1[4];
            uint32_t bh0[4], bh1[4], bl0[4], bl1[4];
            ldsm4(ah0, base + a_off + ko);
            ldsm4(ah1, base + a_off + 16*80 + ko);
            ldsm4(al0, base + ABUF + a_off + ko);
            ldsm4(al1, base + ABUF + a_off + 16*80 + ko);
            ldsm4(bh0, base + 2*ABUF + b_off + ko);
            ldsm4(bh1, base + 2*ABUF + b_off + 16*80 + ko);
            ldsm4(bl0, base + 3*ABUF + b_off + ko);
            ldsm4(bl1, base + 3*ABUF + b_off + 16*80 + ko);
            // B frags: x4 load covers 16 n; n-tile pairs: {r0,r1} and {r2,r3}
            uint32_t* AH[2] = {ah0, ah1};
            uint32_t* AL[2] = {al0, al1};
            #pragma unroll
            for (int mt = 0; mt < 2; mt++) {
                mma16816(acc[mt][0], AH[mt], bh0);
                mma16816(acc[mt][0], AH[mt], bl0);
                mma16816(acc[mt][0], AL[mt], bh0);
                mma16816(acc[mt][1], AH[mt], bh0+2);
                mma16816(acc[mt][1], AH[mt], bl0+2);
                mma16816(acc[mt][1], AL[mt], bh0+2);
                mma16816(acc[mt][2], AH[mt], bh1);
                mma16816(acc[mt][2], AH[mt], bl1);
                mma16816(acc[mt][2], AL[mt], bh1);
                mma16816(acc[mt][3], AH[mt], bh1+2);
                mma16816(acc[mt][3], AH[mt], bl1+2);
                mma16816(acc[mt][3], AL[mt], bh1+2);
            }
        }
    }

    // epilogue straight from registers
    const int erow = m0 + warpM*32 + (lane >> 2);
    const int ecol = n0 + warpN*32 + (lane & 3)*2;
    #pragma unroll
    for (int mt = 0; mt < 2; mt++) {
        #pragma unroll
        for (int nt = 0; nt < 4; nt++) {
            int c = ecol + nt*8;
            float b0 = bias ? bias[c] : 0.f, b1 = bias ? bias[c+1] : 0.f;
            #pragma unroll
            for (int half = 0; half < 2; half++) {
                int r = erow + mt*16 + half*8;
                float o0 = acc[mt][nt][half*2+0] + b0;
                float o1 = acc[mt][nt][half*2+1] + b1;
                if (g.resid) {
                    float2 rv = *(const float2*)(g.resid + (size_t)r * N + c);
                    o0 += rv.x; o1 += rv.y;
                }
                if (g.gelu) {
                    o0 = 0.5f * o0 * (1.0f + erff(o0 * 0.70710678118654752f));
                    o1 = 0.5f * o1 * (1.0f + erff(o1 * 0.70710678118654752f));
                }
                float2 ov; ov.x = o0; ov.y = o1;
                *(float2*)(C + (size_t)r * N + c) = ov;
            }
        }
    }
}

// ---------------- split fp32 -> bf16 hi/lo ----------------
__global__ __launch_bounds__(256) void split_kernel(const float* __restrict__ x,
    __nv_bfloat16* __restrict__ hi, __nv_bfloat16* __restrict__ lo, int n4)
{
    int i = blockIdx.x * 256 + threadIdx.x;
    if (i >= n4) return;
    float4 v = ((const float4*)x)[i];
    __nv_bfloat16 h0 = __float2bfloat16(v.x), h1 = __float2bfloat16(v.y);
    __nv_bfloat16 h2 = __float2bfloat16(v.z), h3 = __float2bfloat16(v.w);
    __nv_bfloat16 l0 = __float2bfloat16(v.x - __bfloat162float(h0));
    __nv_bfloat16 l1 = __float2bfloat16(v.y - __bfloat162float(h1));
    __nv_bfloat16 l2 = __float2bfloat16(v.z - __bfloat162float(h2));
    __nv_bfloat16 l3 = __float2bfloat16(v.w - __bfloat162float(h3));
    __nv_bfloat162* H = (__nv_bfloat162*)hi;
    __nv_bfloat162* L = (__nv_bfloat162*)lo;
    H[i*2]   = __halves2bfloat162(h0, h1);
    H[i*2+1] = __halves2bfloat162(h2, h3);
    L[i*2]   = __halves2bfloat162(l0, l1);
    L[i*2+1] = __halves2bfloat162(l2, l3);
}

// ---------------- weight transpose + split: W[K][N] -> hi/lo[N][K] ----------------
__global__ __launch_bounds__(256) void wtrans_kernel(const float* __restrict__ W,
    __nv_bfloat16* __restrict__ hi, __nv_bfloat16* __restrict__ lo, int K, int N)
{
    __shared__ float t[32][33];
    int tx = threadIdx.x, ty = threadIdx.y;
    int n0 = blockIdx.x * 32, k0 = blockIdx.y * 32;
    #pragma unroll
    for (int i = 0; i < 4; i++)
        t[ty + i*8][tx] = W[(size_t)(k0 + ty + i*8) * N + n0 + tx];
    __syncthreads();
    #pragma unroll
    for (int i = 0; i < 4; i++) {
        float v = t[tx][ty + i*8];
        size_t o = (size_t)(n0 + ty + i*8) * K + k0 + tx;
        __nv_bfloat16 h = __float2bfloat16(v);
        hi[o] = h;
        lo[o] = __float2bfloat16(v - __bfloat162float(h));
    }
}

// ---------------- fp32 tiled GEMM (ctx = probs @ v, batched per (b,h)) ----------------
__global__ __launch_bounds__(256) void gemm_kernel(
    const float* __restrict__ A, const float* __restrict__ Bm,
    float* __restrict__ C, int M, int N, int K, int lda, int ldb, int ldc)
{
    __shared__ __align__(16) float As[16][68];
    __shared__ __align__(16) float Bs[16][68];
    const int tx = threadIdx.x, ty = threadIdx.y;
    const int tid = ty * 16 + tx;
    const int m0 = blockIdx.y * 64, n0 = blockIdx.x * 64;

    int z = blockIdx.z;
    long aOff = (long)z * M * K;
    int bb = z / NH, hh = z % NH;
    long bOff = (long)bb * SS * HH + hh * DH;
    long cOff = bOff;

    const int lrow = tid >> 2, lkq = tid & 3;
    const int brow = tid >> 4, bcol = tid & 15;
    float acc[4][4] = {};

    for (int k0 = 0; k0 < K; k0 += 16) {
        float4 av = *(const float4*)(A + aOff + (long)(m0 + lrow) * lda + k0 + lkq * 4);
        As[lkq*4+0][lrow] = av.x; As[lkq*4+1][lrow] = av.y;
        As[lkq*4+2][lrow] = av.z; As[lkq*4+3][lrow] = av.w;
        float4 bv = *(const float4*)(Bm + bOff + (long)(k0 + brow) * ldb + n0 + bcol * 4);
        *(float4*)&Bs[brow][bcol*4] = bv;
        __syncthreads();
        #pragma unroll
        for (int kk = 0; kk < 16; kk++) {
            float4 a = *(const float4*)&As[kk][ty*4];
            float4 b = *(const float4*)&Bs[kk][tx*4];
            acc[0][0] += a.x*b.x; acc[0][1] += a.x*b.y; acc[0][2] += a.x*b.z; acc[0][3] += a.x*b.w;
            acc[1][0] += a.y*b.x; acc[1][1] += a.y*b.y; acc[1][2] += a.y*b.z; acc[1][3] += a.y*b.w;
            acc[2][0] += a.z*b.x; acc[2][1] += a.z*b.y; acc[2][2] += a.z*b.z; acc[2][3] += a.z*b.w;
            acc[3][0] += a.w*b.x; acc[3][1] += a.w*b.y; acc[3][2] += a.w*b.z; acc[3][3] += a.w*b.w;
        }
        __syncthreads();
    }
    const int col = n0 + tx * 4;
    #pragma unroll
    for (int i = 0; i < 4; i++) {
        int row = m0 + ty * 4 + i;
        float4 o; o.x = acc[i][0]; o.y = acc[i][1]; o.z = acc[i][2]; o.w = acc[i][3];
        *(float4*)(C + cOff + (long)row * ldc + col) = o;
    }
}

// ---------------- fused attention scores + mask + softmax ----------------
__global__ __launch_bounds__(256) void attn_scores_softmax(
    const float* __restrict__ q, const float* __restrict__ k,
    const int* __restrict__ mask, float* __restrict__ probs)
{
    extern __shared__ __align__(16) float sm[];
    float* qs = sm;
    float* ks = sm + 64*36;
    float* sc = sm + 64*36 + 64*66;

    const int tid = threadIdx.x;
    const int qt = blockIdx.x;
    const int bh = blockIdx.y;
    const int b = bh / NH, h = bh % NH;
    const int q0 = qt * 32;

    const float* qbase = q + (long)b * SS * HH + h * DH;
    const float* kbase = k + (long)b * SS * HH + h * DH;

    {
        int r = tid >> 4, dq = tid & 15;
        #pragma unroll
        for (int it = 0; it < 2; it++) {
            int row = r + it * 16;
            float4 v = *(const float4*)(qbase + (long)(q0 + row) * HH + dq * 4);
            qs[(dq*4+0)*36 + row] = v.x;
            qs[(dq*4+1)*36 + row] = v.y;
            qs[(dq*4+2)*36 + row] = v.z;
            qs[(dq*4+3)*36 + row] = v.w;
        }
    }

    const int qg = tid >> 5;
    const int kg = tid & 31;

    for (int kt = 0; kt < 16; kt++) {
        const int k0 = kt * 64;
        __syncthreads();
        {
            int rk = tid >> 4, dq = tid & 15;
            #pragma unroll
            for (int it = 0; it < 4; it++) {
                int ki = rk + it * 16;
                float4 v = *(const float4*)(kbase + (long)(k0 + ki) * HH + dq * 4);
                ks[(dq*4+0)*66 + ki] = v.x;
                ks[(dq*4+1)*66 + ki] = v.y;
                ks[(dq*4+2)*66 + ki] = v.z;
                ks[(dq*4+3)*66 + ki] = v.w;
            }
        }
        __syncthreads();

        float acc[4][2] = {};
        #pragma unroll 8
        for (int d = 0; d < 64; d++) {
            float4 qv = *(const float4*)&qs[d*36 + qg*4];
            float2 kv = *(const float2*)&ks[d*66 + kg*2];
            acc[0][0] += qv.x * kv.x; acc[0][1] += qv.x * kv.y;
            acc[1][0] += qv.y * kv.x; acc[1][1] += qv.y * kv.y;
            acc[2][0] += qv.z * kv.x; acc[2][1] += qv.z * kv.y;
            acc[3][0] += qv.w * kv.x; acc[3][1] += qv.w * kv.y;
        }
        #pragma unroll
        for (int i = 0; i < 4; i++) {
            float2 st; st.x = acc[i][0]; st.y = acc[i][1];
            *(float2*)&sc[(qg*4+i)*1024 + k0 + kg*2] = st;
        }
    }
    __syncthreads();

    const int warp = tid >> 5, lane = tid & 31;
    const float scale = 0.125f;
    #pragma unroll
    for (int rr = 0; rr < 4; rr++) {
        int r = warp * 4 + rr;
        float* srow = &sc[r * 1024];
        const int* mrow = mask + (long)b * SS * SS + (long)(q0 + r) * SS;
        float mx = -1e30f;
        for (int c = lane; c < 1024; c += 32) {
            float v = srow[c] * scale + (1.0f - (float)mrow[c]) * (-10000.0f);
            srow[c] = v;
            mx = fmaxf(mx, v);
        }
        #pragma unroll
        for (int o = 16; o; o >>= 1) mx = fmaxf(mx, __shfl_xor_sync(0xffffffffu, mx, o));
        float s = 0.f;
        for (int c = lane; c < 1024; c += 32) {
            float e = __expf(srow[c] - mx);
            srow[c] = e;
            s += e;
        }
        #pragma unroll
        for (int o = 16; o; o >>= 1) s += __shfl_xor_sync(0xffffffffu, s, o);
        float inv = 1.0f / s;
        float* prow = probs + ((long)bh * SS + q0 + r) * SS;
        for (int c = lane; c < 1024; c += 32) prow[c] = srow[c] * inv;
    }
}

// ---------------- LayerNorm ----------------
__global__ __launch_bounds__(256) void ln_kernel(
    const float* __restrict__ x, const float* __restrict__ g,
    const float* __restrict__ b, float* __restrict__ out)
{
    const int row = blockIdx.x;
    const int tid = threadIdx.x;
    const float* xr = x + (long)row * HH;
    float v0 = xr[tid], v1 = xr[tid + 256], v2 = xr[tid + 512];

    __shared__ float red[8];
    float s = v0 + v1 + v2;
    #pragma unroll
    for (int o = 16; o; o >>= 1) s += __shfl_xor_sync(0xffffffffu, s, o);
    if ((tid & 31) == 0) red[tid >> 5] = s;
    __syncthreads();
    float tot = 0.f;
    #pragma unroll
    for (int i = 0; i < 8; i++) tot += red[i];
    float mean = tot * (1.0f / 768.0f);

    float d0 = v0 - mean, d1 = v1 - mean, d2 = v2 - mean;
    float sq = d0*d0 + d1*d1 + d2*d2;
    __syncthreads();
    #pragma unroll
    for (int o = 16; o; o >>= 1) sq += __shfl_xor_sync(0xffffffffu, sq, o);
    if ((tid & 31) == 0) red[tid >> 5] = sq;
    __syncthreads();
    float tot2 = 0.f;
    #pragma unroll
    for (int i = 0; i < 8; i++) tot2 += red[i];
    float rstd = rsqrtf(tot2 * (1.0f / 768.0f) + 1e-12f);

    float* orow = out + (long)row * HH;
    orow[tid]       = d0 * rstd * g[tid]       + b[tid];
    orow[tid + 256] = d1 * rstd * g[tid + 256] + b[tid + 256];
    orow[tid + 512] = d2 * rstd * g[tid + 512] + b[tid + 512];
}

// ---------------- launch ----------------
extern "C" void kernel_launch(void* const* d_in, const int* in_sizes, int n_in,
                              void* d_out, int out_size)
{
    const float* x    = (const float*)d_in[0];
    const int*   mask = (const int*)  d_in[1];
    const float* Wq   = (const float*)d_in[2];
    const float* bq   = (const float*)d_in[3];
    const float* Wk   = (const float*)d_in[4];
    const float* bk   = (const float*)d_in[5];
    const float* Wv   = (const float*)d_in[6];
    const float* bv   = (const float*)d_in[7];
    const float* Wao  = (const float*)d_in[8];
    const float* bao  = (const float*)d_in[9];
    const float* g1   = (const float*)d_in[10];
    const float* b1   = (const float*)d_in[11];
    const float* Wi   = (const float*)d_in[12];
    const float* bi   = (const float*)d_in[13];
    const float* Wfo  = (const float*)d_in[14];
    const float* bfo  = (const float*)d_in[15];
    const float* g2   = (const float*)d_in[16];
    const float* b2   = (const float*)d_in[17];

    float *h_, *q_, *k_, *v_, *ctx_, *tmp_, *attn_, *inter_, *probs_;
    __nv_bfloat16 *ah_, *al_, *wh_, *wl_;
    cudaGetSymbolAddress((void**)&h_,     g_h);
    cudaGetSymbolAddress((void**)&q_,     g_q);
    cudaGetSymbolAddress((void**)&k_,     g_k);
    cudaGetSymbolAddress((void**)&v_,     g_v);
    cudaGetSymbolAddress((void**)&ctx_,   g_ctx);
    cudaGetSymbolAddress((void**)&tmp_,   g_tmp);
    cudaGetSymbolAddress((void**)&attn_,  g_attn);
    cudaGetSymbolAddress((void**)&inter_, g_inter);
    cudaGetSymbolAddress((void**)&probs_, g_probs);
    cudaGetSymbolAddress((void**)&ah_,    g_ah);
    cudaGetSymbolAddress((void**)&al_,    g_al);
    cudaGetSymbolAddress((void**)&wh_,    g_wh);
    cudaGetSymbolAddress((void**)&wl_,    g_wl);

    const int smem_scores = (64*36 + 64*66 + 32*1024) * 4;
    cudaFuncSetAttribute(attn_scores_softmax,
                         cudaFuncAttributeMaxDynamicSharedMemorySize, smem_scores);
    cudaFuncSetAttribute(gemm_tc,
                         cudaFuncAttributeMaxDynamicSharedMemorySize, GEMM_SMEM);

    const int M = BB * SS;  // 2048

    // ---- weight prep: transpose + bf16 hi/lo split (replayed in graph; deterministic) ----
    for (int l = 0; l < NL; l++) {
        size_t lo = (size_t)l * LSTRIDE;
        wtrans_kernel<<<dim3(HH/32, HH/32), dim3(32,8)>>>(Wq  + (long)l*HH*HH, wh_+lo+WQOFF,  wl_+lo+WQOFF,  HH, HH);
        wtrans_kernel<<<dim3(HH/32, HH/32), dim3(32,8)>>>(Wk  + (long)l*HH*HH, wh_+lo+WKOFF,  wl_+lo+WKOFF,  HH, HH);
        wtrans_kernel<<<dim3(HH/32, HH/32), dim3(32,8)>>>(Wv  + (long)l*HH*HH, wh_+lo+WVOFF,  wl_+lo+WVOFF,  HH, HH);
        wtrans_kernel<<<dim3(HH/32, HH/32), dim3(32,8)>>>(Wao + (long)l*HH*HH, wh_+lo+WAOOFF, wl_+lo+WAOOFF, HH, HH);
        wtrans_kernel<<<dim3(FF/32, HH/32), dim3(32,8)>>>(Wi  + (long)l*HH*FF, wh_+lo+WIOFF,  wl_+lo+WIOFF,  HH, FF);
        wtrans_kernel<<<dim3(HH/32, FF/32), dim3(32,8)>>>(Wfo + (long)l*FF*HH, wh_+lo+WFOOFF, wl_+lo+WFOOFF, FF, HH);
    }

    for (int l = 0; l < NL; l++) {
        const float* hin = (l == 0) ? x : h_;
        size_t lo = (size_t)l * LSTRIDE;

        split_kernel<<<(M*HH/4 + 255)/256, 256>>>(hin, ah_, al_, M*HH/4);

        // QKV: one kernel, z selects weights/outputs
        {
            GemmArgs a;
            a.ah = ah_; a.al = al_;
            a.bh0 = wh_+lo+WQOFF; a.bh1 = wh_+lo+WKOFF; a.bh2 = wh_+lo+WVOFF;
            a.bl0 = wl_+lo+WQOFF; a.bl1 = wl_+lo+WKOFF; a.bl2 = wl_+lo+WVOFF;
            a.bias0 = bq + l*HH; a.bias1 = bk + l*HH; a.bias2 = bv + l*HH;
            a.resid = nullptr; a.c0 = q_; a.c1 = k_; a.c2 = v_;
            a.K = HH; a.N = HH; a.gelu = 0;
            gemm_tc<<<dim3(HH/128, M/128, 3), 512, GEMM_SMEM>>>(a);
        }

        attn_scores_softmax<<<dim3(SS/32, BB*NH), 256, smem_scores>>>(q_, k_, mask, probs_);
        gemm_kernel<<<dim3(1, SS/64, BB*NH), dim3(16,16)>>>(probs_, v_, ctx_,
                                                            SS, DH, SS, SS, HH, HH);

        // AO proj + residual
        split_kernel<<<(M*HH/4 + 255)/256, 256>>>(ctx_, ah_, al_, M*HH/4);
        {
            GemmArgs a;
            a.ah = ah_; a.al = al_;
            a.bh0 = wh_+lo+WAOOFF; a.bh1 = a.bh0; a.bh2 = a.bh0;
            a.bl0 = wl_+lo+WAOOFF; a.bl1 = a.bl0; a.bl2 = a.bl0;
            a.bias0 = bao + l*HH; a.bias1 = a.bias0; a.bias2 = a.bias0;
            a.resid = hin; a.c0 = tmp_; a.c1 = tmp_; a.c2 = tmp_;
            a.K = HH; a.N = HH; a.gelu = 0;
            gemm_tc<<<dim3(HH/128, M/128, 1), 512, GEMM_SMEM>>>(a);
        }
        ln_kernel<<<M, 256>>>(tmp_, g1 + l*HH, b1 + l*HH, attn_);

        // FFN1 (gelu)
        split_kernel<<<(M*HH/4 + 255)/256, 256>>>(attn_, ah_, al_, M*HH/4);
        {
            GemmArgs a;
            a.ah = ah_; a.al = al_;
            a.bh0 = wh_+lo+WIOFF; a.bh1 = a.bh0; a.bh2 = a.bh0;
            a.bl0 = wl_+lo+WIOFF; a.bl1 = a.bl0; a.bl2 = a.bl0;
            a.bias0 = bi + l*FF; a.bias1 = a.bias0; a.bias2 = a.bias0;
            a.resid = nullptr; a.c0 = inter_; a.c1 = inter_; a.c2 = inter_;
            a.K = HH; a.N = FF; a.gelu = 1;
            gemm_tc<<<dim3(FF/128, M/128, 1), 512, GEMM_SMEM>>>(a);
        }

        // FFN2 + residual
        split_kernel<<<(M*FF/4 + 255)/256, 256>>>(inter_, ah_, al_, M*FF/4);
        {
            GemmArgs a;
            a.ah = ah_; a.al = al_;
            a.bh0 = wh_+lo+WFOOFF; a.bh1 = a.bh0; a.bh2 = a.bh0;
            a.bl0 = wl_+lo+WFOOFF; a.bl1 = a.bl0; a.bl2 = a.bl0;
            a.bias0 = bfo + l*HH; a.bias1 = a.bias0; a.bias2 = a.bias0;
            a.resid = attn_; a.c0 = tmp_; a.c1 = tmp_; a.c2 = tmp_;
            a.K = FF; a.N = HH; a.gelu = 0;
            gemm_tc<<<dim3(HH/128, M/128, 1), 512, GEMM_SMEM>>>(a);
        }

        float* lnout = (l == NL - 1) ? (float*)d_out : h_;
        ln_kernel<<<M, 256>>>(tmp_, g2 + l*HH, b2 + l*HH, lnout);
    }
}

// round 5
// speedup vs baseline: 2.7330x; 1.6360x over previous
#include <cuda_runtime.h>
#include <cuda_bf16.h>
#include <math.h>
#include <stdint.h>

#define BB 2
#define SS 1024
#define HH 768
#define NH 12
#define DH 64
#define FF 3072
#define NL 4

// ---------------- scratch (device globals; no allocation allowed) ----------------
__device__ float g_h[BB*SS*HH];
__device__ float g_tmp[BB*SS*HH];
__device__ float g_attn[BB*SS*HH];

__device__ __nv_bfloat16 g_hh[BB*SS*HH], g_hl[BB*SS*HH];
__device__ __nv_bfloat16 g_qh[BB*SS*HH], g_ql[BB*SS*HH];
__device__ __nv_bfloat16 g_kh[BB*SS*HH], g_kl[BB*SS*HH];
__device__ __nv_bfloat16 g_vh[BB*SS*HH], g_vl[BB*SS*HH];
__device__ __nv_bfloat16 g_vth[BB*SS*HH], g_vtl[BB*SS*HH];
__device__ __nv_bfloat16 g_cth[BB*SS*HH], g_ctl[BB*SS*HH];
__device__ __nv_bfloat16 g_aah[BB*SS*HH], g_aal[BB*SS*HH];
__device__ __nv_bfloat16 g_ih[BB*SS*FF], g_il[BB*SS*FF];

// transposed+split weights per layer: [wq wk wv wao wi wfo], each [N][K] row-major
#define WQOFF  0
#define WKOFF  589824
#define WVOFF  1179648
#define WAOOFF 1769472
#define WIOFF  2359296
#define WFOOFF 4718592
#define LSTRIDE 7077888
__device__ __nv_bfloat16 g_wh[(size_t)NL*LSTRIDE];
__device__ __nv_bfloat16 g_wl[(size_t)NL*LSTRIDE];

// ---------------- PTX helpers (arch-neutral: ldmatrix / mma.sync / cp.async) ----------------
__device__ __forceinline__ uint32_t smem_u32(const void* p) {
    uint32_t a;
    asm("{ .reg .u64 t; cvta.to.shared.u64 t, %1; cvt.u32.u64 %0, t; }" : "=r"(a) : "l"(p));
    return a;
}
__device__ __forceinline__ void cpa16(uint32_t dst, const void* src) {
    asm volatile("cp.async.cg.shared.global [%0], [%1], 16;" :: "r"(dst), "l"(src));
}
#define CP_COMMIT() asm volatile("cp.async.commit_group;" ::: "memory")

__device__ __forceinline__ void ldsm4(uint32_t* r, uint32_t a) {
    asm volatile("ldmatrix.sync.aligned.m8n8.x4.shared.b16 {%0,%1,%2,%3}, [%4];"
        : "=r"(r[0]), "=r"(r[1]), "=r"(r[2]), "=r"(r[3]) : "r"(a));
}
__device__ __forceinline__ void mma16816(float* c, const uint32_t* a, const uint32_t* b) {
    asm volatile("mma.sync.aligned.m16n8k16.row.col.f32.bf16.bf16.f32 "
        "{%0,%1,%2,%3}, {%4,%5,%6,%7}, {%8,%9}, {%0,%1,%2,%3};"
        : "+f"(c[0]), "+f"(c[1]), "+f"(c[2]), "+f"(c[3])
        : "r"(a[0]), "r"(a[1]), "r"(a[2]), "r"(a[3]), "r"(b[0]), "r"(b[1]));
}
__device__ __forceinline__ uint32_t pack_bf2(__nv_bfloat16 a, __nv_bfloat16 b) {
    __nv_bfloat162 t = __halves2bfloat162(a, b);
    return *(uint32_t*)&t;
}

// ---------------- bf16x3 HMMA GEMM: C = A @ B^T (+bias)(+resid)(gelu), fp32 or bf16-split out ----
struct GemmArgs {
    const __nv_bfloat16 *ah, *al;
    const __nv_bfloat16 *bh0, *bh1, *bh2, *bl0, *bl1, *bl2;
    const float *bias0, *bias1, *bias2;
    const float *resid;
    float *c0, *c1, *c2;
    __nv_bfloat16 *ch0, *cl0, *ch1, *cl1, *ch2, *cl2;
    int K, N, gelu, outbf;
};

#define ABUF 10240            // 128 rows * 80B (64B data + 16B pad)
#define STGB (4*ABUF)         // Ah, Al, Bh, Bl
#define NSTG 3
#define GEMM_SMEM (NSTG*STGB) // 122880

__global__ __launch_bounds__(512) void gemm_tc(GemmArgs g) {
    extern __shared__ char smem[];
    const uint32_t su = smem_u32(smem);
    const int tid = threadIdx.x;
    const int lane = tid & 31, warp = tid >> 5;
    const int warpM = warp & 3, warpN = warp >> 2;
    const int m0 = blockIdx.y << 7, n0 = blockIdx.x << 7;

    const __nv_bfloat16 *bh, *bl; const float* bias; float* C;
    __nv_bfloat16 *CH, *CL;
    if (blockIdx.z == 0)      { bh=g.bh0; bl=g.bl0; bias=g.bias0; C=g.c0; CH=g.ch0; CL=g.cl0; }
    else if (blockIdx.z == 1) { bh=g.bh1; bl=g.bl1; bias=g.bias1; C=g.c1; CH=g.ch1; CL=g.cl1; }
    else                      { bh=g.bh2; bl=g.bl2; bias=g.bias2; C=g.c2; CH=g.ch2; CL=g.cl2; }
    const int K = g.K, N = g.N, nk = K >> 5;

    const int ldg_row = tid >> 2, ldg_c = tid & 3;
    const size_t ldab = (size_t)K * 2;
    const char* pAh = (const char*)g.ah + ((size_t)(m0 + ldg_row)) * ldab + ldg_c * 16;
    const char* pAl = (const char*)g.al + ((size_t)(m0 + ldg_row)) * ldab + ldg_c * 16;
    const char* pBh = (const char*)bh   + ((size_t)(n0 + ldg_row)) * ldab + ldg_c * 16;
    const char* pBl = (const char*)bl   + ((size_t)(n0 + ldg_row)) * ldab + ldg_c * 16;
    const uint32_t sdst = ldg_row * 80 + ldg_c * 16;

    auto load_chunk = [&](int j, int s) {
        uint32_t sb = su + s * STGB + sdst;
        size_t go = (size_t)j * 64;
        cpa16(sb,            pAh + go);
        cpa16(sb +   ABUF,   pAl + go);
        cpa16(sb + 2*ABUF,   pBh + go);
        cpa16(sb + 3*ABUF,   pBl + go);
    };

    load_chunk(0, 0); CP_COMMIT();
    load_chunk(1, 1); CP_COMMIT();

    float acc[2][4][4];
    #pragma unroll
    for (int i = 0; i < 2; i++)
        #pragma unroll
        for (int j = 0; j < 4; j++)
            #pragma unroll
            for (int r = 0; r < 4; r++) acc[i][j][r] = 0.f;

    const uint32_t a_off = (uint32_t)(warpM*32 + (lane & 15)) * 80 + (lane >> 4) * 16;
    const uint32_t b_off = (uint32_t)(warpN*32 + (((lane >> 4) & 1) << 3) + (lane & 7)) * 80
                         + ((lane >> 3) & 1) * 16;

    for (int i = 0; i < nk; i++) {
        asm volatile("cp.async.wait_group 1;" ::: "memory");
        __syncthreads();
        int j = i + 2;
        if (j < nk) load_chunk(j, j % NSTG);
        CP_COMMIT();

        uint32_t base = su + (i % NSTG) * STGB;
        #pragma unroll
        for (int ks = 0; ks < 2; ks++) {
            uint32_t ko = ks * 32;
            uint32_t ah0[4], ah1[4], al0[4], al1[4];
            uint32_t bhf0[4], bhf1[4], blf0[4], blf1[4];
            ldsm4(ah0, base + a_off + ko);
            ldsm4(ah1, base + a_off + 16*80 + ko);
            ldsm4(al0, base + ABUF + a_off + ko);
            ldsm4(al1, base + ABUF + a_off + 16*80 + ko);
            ldsm4(bhf0, base + 2*ABUF + b_off + ko);
            ldsm4(bhf1, base + 2*ABUF + b_off + 16*80 + ko);
            ldsm4(blf0, base + 3*ABUF + b_off + ko);
            ldsm4(blf1, base + 3*ABUF + b_off + 16*80 + ko);
            uint32_t* AH[2] = {ah0, ah1};
            uint32_t* AL[2] = {al0, al1};
            #pragma unroll
            for (int mt = 0; mt < 2; mt++) {
                mma16816(acc[mt][0], AH[mt], bhf0);
                mma16816(acc[mt][0], AH[mt], blf0);
                mma16816(acc[mt][0], AL[mt], bhf0);
                mma16816(acc[mt][1], AH[mt], bhf0+2);
                mma16816(acc[mt][1], AH[mt], blf0+2);
                mma16816(acc[mt][1], AL[mt], bhf0+2);
                mma16816(acc[mt][2], AH[mt], bhf1);
                mma16816(acc[mt][2], AH[mt], blf1);
                mma16816(acc[mt][2], AL[mt], bhf1);
                mma16816(acc[mt][3], AH[mt], bhf1+2);
                mma16816(acc[mt][3], AH[mt], blf1+2);
                mma16816(acc[mt][3], AL[mt], bhf1+2);
            }
        }
    }

    const int erow = m0 + warpM*32 + (lane >> 2);
    const int ecol = n0 + warpN*32 + (lane & 3)*2;
    #pragma unroll
    for (int mt = 0; mt < 2; mt++) {
        #pragma unroll
        for (int nt = 0; nt < 4; nt++) {
            int c = ecol + nt*8;
            float b0 = bias ? bias[c] : 0.f, b1 = bias ? bias[c+1] : 0.f;
            #pragma unroll
            for (int half = 0; half < 2; half++) {
                int r = erow + mt*16 + half*8;
                float o0 = acc[mt][nt][half*2+0] + b0;
                float o1 = acc[mt][nt][half*2+1] + b1;
                if (g.resid) {
                    float2 rv = *(const float2*)(g.resid + (size_t)r * N + c);
                    o0 += rv.x; o1 += rv.y;
                }
                if (g.gelu) {
                    o0 = 0.5f * o0 * (1.0f + erff(o0 * 0.70710678118654752f));
                    o1 = 0.5f * o1 * (1.0f + erff(o1 * 0.70710678118654752f));
                }
                if (g.outbf) {
                    __nv_bfloat16 h0 = __float2bfloat16(o0), h1 = __float2bfloat16(o1);
                    __nv_bfloat16 l0 = __float2bfloat16(o0 - __bfloat162float(h0));
                    __nv_bfloat16 l1 = __float2bfloat16(o1 - __bfloat162float(h1));
                    *(uint32_t*)(CH + (size_t)r * N + c) = pack_bf2(h0, h1);
                    *(uint32_t*)(CL + (size_t)r * N + c) = pack_bf2(l0, l1);
                } else {
                    float2 ov; ov.x = o0; ov.y = o1;
                    *(float2*)(C + (size_t)r * N + c) = ov;
                }
            }
        }
    }
}

// ---------------- flash attention: S=QK^T (bf16x3) -> mask/scale/softmax -> O=PV (bf16x3) ----
// Q-tile 64, K-tile 64, 128 threads (4 warps x 16 q rows). V pre-transposed: vt[bh][dh][S].
#define FROW 144
#define FQBUF 9216           // 64*144
#define FSTG  36864          // 4 bufs (kh,kl,vh,vl)
#define FSMEM (2*FQBUF + 2*FSTG)   // 92160

__global__ __launch_bounds__(128) void flashattn(
    const __nv_bfloat16* __restrict__ qh, const __nv_bfloat16* __restrict__ ql,
    const __nv_bfloat16* __restrict__ kh, const __nv_bfloat16* __restrict__ kl,
    const __nv_bfloat16* __restrict__ vth, const __nv_bfloat16* __restrict__ vtl,
    const int* __restrict__ mask,
    __nv_bfloat16* __restrict__ cth, __nv_bfloat16* __restrict__ ctl)
{
    extern __shared__ char smem[];
    const uint32_t su = smem_u32(smem);
    const int tid = threadIdx.x, lane = tid & 31, warp = tid >> 5;
    const int q0 = blockIdx.x * 64, bh = blockIdx.y;
    const int b = bh / NH, h = bh % NH;
    const int wr = warp * 16;

    const char* Qh = (const char*)(qh + ((size_t)b*SS + q0)*HH + h*DH);
    const char* Ql = (const char*)(ql + ((size_t)b*SS + q0)*HH + h*DH);
    const char* Kh = (const char*)(kh + ((size_t)b*SS)*HH + h*DH);
    const char* Kl = (const char*)(kl + ((size_t)b*SS)*HH + h*DH);
    const char* Vh = (const char*)(vth + (size_t)bh*DH*SS);
    const char* Vl = (const char*)(vtl + (size_t)bh*DH*SS);

    // Q: 64 rows x 128B = 512 chunks of 16B per buffer; 4 per thread
    #pragma unroll
    for (int c = 0; c < 4; c++) {
        int idx = tid + c*128;
        int row = idx >> 3, chn = idx & 7;
        uint32_t dst = su + row*FROW + chn*16;
        size_t so = (size_t)row*1536 + chn*16;     // HH*2 bytes/row
        cpa16(dst,         Qh + so);
        cpa16(dst + FQBUF, Ql + so);
    }
    CP_COMMIT();

    auto load_kv = [&](int j, int s) {
        uint32_t sb = su + 2*FQBUF + s*FSTG;
        int k0 = j * 64;
        #pragma unroll
        for (int c = 0; c < 4; c++) {
            int idx = tid + c*128;
            int row = idx >> 3, chn = idx & 7;
            uint32_t dst = sb + row*FROW + chn*16;
            size_t ko = (size_t)(k0 + row)*1536 + chn*16;
            cpa16(dst,           Kh + ko);
            cpa16(dst +   FQBUF, Kl + ko);
            size_t vo = (size_t)row*2048 + (size_t)k0*2 + chn*16;  // vt row = dh, stride SS*2
            cpa16(dst + 2*FQBUF, Vh + vo);
            cpa16(dst + 3*FQBUF, Vl + vo);
        }
    };
    load_kv(0, 0); CP_COMMIT();
    load_kv(1, 1); CP_COMMIT();

    asm volatile("cp.async.wait_group 2;" ::: "memory");
    __syncthreads();

    // Q fragments (kept in regs whole kernel)
    uint32_t qhf[4][4], qlf[4][4];
    {
        uint32_t abase = su + (uint32_t)(wr + (lane & 15))*FROW + (lane >> 4)*16;
        #pragma unroll
        for (int kc = 0; kc < 4; kc++) {
            ldsm4(qhf[kc], abase + kc*32);
            ldsm4(qlf[kc], abase + FQBUF + kc*32);
        }
    }

    float o[8][4];
    #pragma unroll
    for (int j = 0; j < 8; j++)
        #pragma unroll
        for (int r = 0; r < 4; r++) o[j][r] = 0.f;
    float m0 = -1e30f, m1 = -1e30f, l0 = 0.f, l1 = 0.f;

    const int r = lane >> 2;
    const int colb = (lane & 3) * 2;
    const int* mrow0 = mask + ((size_t)b*SS + (q0 + wr + r))*SS;
    const int* mrow8 = mrow0 + 8*SS;
    const uint32_t boff = (uint32_t)((((lane >> 4) & 1) << 3) + (lane & 7))*FROW
                        + ((lane >> 3) & 1)*16;

    for (int i = 0; i < 16; i++) {
        asm volatile("cp.async.wait_group 1;" ::: "memory");
        __syncthreads();
        const uint32_t sb = su + 2*FQBUF + (i & 1)*FSTG;
        const int k0 = i * 64;

        // ---- S = Q K^T (x3) ----
        float sc_[8][4];
        #pragma unroll
        for (int j = 0; j < 8; j++)
            #pragma unroll
            for (int t = 0; t < 4; t++) sc_[j][t] = 0.f;
        #pragma unroll
        for (int nt = 0; nt < 4; nt++) {
            #pragma unroll
            for (int kc = 0; kc < 4; kc++) {
                uint32_t fh[4], fl[4];
                ldsm4(fh, sb + nt*16*FROW + boff + kc*32);
                ldsm4(fl, sb + FQBUF + nt*16*FROW + boff + kc*32);
                mma16816(sc_[2*nt],   qhf[kc], fh);
                mma16816(sc_[2*nt],   qhf[kc], fl);
                mma16816(sc_[2*nt],   qlf[kc], fh);
                mma16816(sc_[2*nt+1], qhf[kc], fh+2);
                mma16816(sc_[2*nt+1], qhf[kc], fl+2);
                mma16816(sc_[2*nt+1], qlf[kc], fh+2);
            }
        }
        // ---- mask + scale ----
        #pragma unroll
        for (int j = 0; j < 8; j++) {
            int kc2 = k0 + j*8 + colb;
            int2 ma = *(const int2*)(mrow0 + kc2);
            int2 mb = *(const int2*)(mrow8 + kc2);
            sc_[j][0] = sc_[j][0]*0.125f + (1.f - (float)ma.x)*(-10000.f);
            sc_[j][1] = sc_[j][1]*0.125f + (1.f - (float)ma.y)*(-10000.f);
            sc_[j][2] = sc_[j][2]*0.125f + (1.f - (float)mb.x)*(-10000.f);
            sc_[j][3] = sc_[j][3]*0.125f + (1.f - (float)mb.y)*(-10000.f);
        }
        // ---- online softmax ----
        float mx0 = -1e30f, mx1 = -1e30f;
        #pragma unroll
        for (int j = 0; j < 8; j++) {
            mx0 = fmaxf(mx0, fmaxf(sc_[j][0], sc_[j][1]));
            mx1 = fmaxf(mx1, fmaxf(sc_[j][2], sc_[j][3]));
        }
        mx0 = fmaxf(mx0, __shfl_xor_sync(0xffffffffu, mx0, 1));
        mx0 = fmaxf(mx0, __shfl_xor_sync(0xffffffffu, mx0, 2));
        mx1 = fmaxf(mx1, __shfl_xor_sync(0xffffffffu, mx1, 1));
        mx1 = fmaxf(mx1, __shfl_xor_sync(0xffffffffu, mx1, 2));
        float mn0 = fmaxf(m0, mx0), mn1 = fmaxf(m1, mx1);
        float sf0 = __expf(m0 - mn0), sf1 = __expf(m1 - mn1);
        m0 = mn0; m1 = mn1;
        float rs0 = 0.f, rs1 = 0.f;
        #pragma unroll
        for (int j = 0; j < 8; j++) {
            sc_[j][0] = __expf(sc_[j][0] - mn0);
            sc_[j][1] = __expf(sc_[j][1] - mn0);
            sc_[j][2] = __expf(sc_[j][2] - mn1);
            sc_[j][3] = __expf(sc_[j][3] - mn1);
            rs0 += sc_[j][0] + sc_[j][1];
            rs1 += sc_[j][2] + sc_[j][3];
        }
        rs0 += __shfl_xor_sync(0xffffffffu, rs0, 1);
        rs0 += __shfl_xor_sync(0xffffffffu, rs0, 2);
        rs1 += __shfl_xor_sync(0xffffffffu, rs1, 1);
        rs1 += __shfl_xor_sync(0xffffffffu, rs1, 2);
        l0 = l0*sf0 + rs0;
        l1 = l1*sf1 + rs1;
        #pragma unroll
        for (int j = 0; j < 8; j++) {
            o[j][0] *= sf0; o[j][1] *= sf0; o[j][2] *= sf1; o[j][3] *= sf1;
        }
        // ---- P -> bf16 hi/lo A-fragments ----
        uint32_t phf[4][4], plf[4][4];
        #pragma unroll
        for (int kc = 0; kc < 4; kc++) {
            #pragma unroll
            for (int half = 0; half < 2; half++) {   // half 0: tile 2kc, half 1: tile 2kc+1
                int j = 2*kc + half;
                __nv_bfloat16 h0 = __float2bfloat16(sc_[j][0]);
                __nv_bfloat16 h1 = __float2bfloat16(sc_[j][1]);
                __nv_bfloat16 h2 = __float2bfloat16(sc_[j][2]);
                __nv_bfloat16 h3 = __float2bfloat16(sc_[j][3]);
                phf[kc][half*2+0] = pack_bf2(h0, h1);
                phf[kc][half*2+1] = pack_bf2(h2, h3);
                plf[kc][half*2+0] = pack_bf2(
                    __float2bfloat16(sc_[j][0] - __bfloat162float(h0)),
                    __float2bfloat16(sc_[j][1] - __bfloat162float(h1)));
                plf[kc][half*2+1] = pack_bf2(
                    __float2bfloat16(sc_[j][2] - __bfloat162float(h2)),
                    __float2bfloat16(sc_[j][3] - __bfloat162float(h3)));
            }
        }
        // ---- O += P V (x3) ----
        #pragma unroll
        for (int nt = 0; nt < 4; nt++) {
            #pragma unroll
            for (int kc = 0; kc < 4; kc++) {
                uint32_t fh[4], fl[4];
                ldsm4(fh, sb + 2*FQBUF + nt*16*FROW + boff + kc*32);
                ldsm4(fl, sb + 3*FQBUF + nt*16*FROW + boff + kc*32);
                mma16816(o[2*nt],   phf[kc], fh);
                mma16816(o[2*nt],   phf[kc], fl);
                mma16816(o[2*nt],   plf[kc], fh);
                mma16816(o[2*nt+1], phf[kc], fh+2);
                mma16816(o[2*nt+1], phf[kc], fl+2);
                mma16816(o[2*nt+1], plf[kc], fh+2);
            }
        }
        __syncthreads();
        if (i + 2 < 16) load_kv(i + 2, i & 1);
        CP_COMMIT();
    }

    // ---- finalize + store ctx (bf16 hi/lo) ----
    float inv0 = 1.f / l0, inv1 = 1.f / l1;
    size_t base0 = ((size_t)b*SS + (q0 + wr + r))*HH + h*DH;
    size_t base8 = base0 + (size_t)8*HH;
    #pragma unroll
    for (int j = 0; j < 8; j++) {
        int col = j*8 + colb;
        float a0 = o[j][0]*inv0, a1 = o[j][1]*inv0;
        float a2 = o[j][2]*inv1, a3 = o[j][3]*inv1;
        __nv_bfloat16 h0 = __float2bfloat16(a0), h1 = __float2bfloat16(a1);
        __nv_bfloat16 h2 = __float2bfloat16(a2), h3 = __float2bfloat16(a3);
        *(uint32_t*)(cth + base0 + col) = pack_bf2(h0, h1);
        *(uint32_t*)(ctl + base0 + col) = pack_bf2(
            __float2bfloat16(a0 - __bfloat162float(h0)),
            __float2bfloat16(a1 - __bfloat162float(h1)));
        *(uint32_t*)(cth + base8 + col) = pack_bf2(h2, h3);
        *(uint32_t*)(ctl + base8 + col) = pack_bf2(
            __float2bfloat16(a2 - __bfloat162float(h2)),
            __float2bfloat16(a3 - __bfloat162float(h3)));
    }
}

// ---------------- V transpose: v[b,s,h*64+d] -> vt[(bh*64+d)][s] ----------------
__global__ __launch_bounds__(256) void vtrans_kernel(
    const __nv_bfloat16* __restrict__ vh, const __nv_bfloat16* __restrict__ vl,
    __nv_bfloat16* __restrict__ oh, __nv_bfloat16* __restrict__ ol)
{
    __shared__ __nv_bfloat16 th[32][33], tl[32][33];
    int tx = threadIdx.x, ty = threadIdx.y;
    int bh = blockIdx.y >> 1, dblk = blockIdx.y & 1;
    int b = bh / NH, h = bh % NH;
    int s0 = blockIdx.x * 32, d0 = dblk * 32;
    #pragma unroll
    for (int i = 0; i < 4; i++) {
        int s = ty + i*8;
        size_t off = ((size_t)b*SS + s0 + s)*HH + h*DH + d0 + tx;
        th[s][tx] = vh[off];
        tl[s][tx] = vl[off];
    }
    __syncthreads();
    #pragma unroll
    for (int i = 0; i < 4; i++) {
        int d = ty + i*8;
        size_t off = ((size_t)bh*DH + d0 + d)*SS + s0 + tx;
        oh[off] = th[tx][d];
        ol[off] = tl[tx][d];
    }
}

// ---------------- split fp32 -> bf16 hi/lo (only for initial x) ----------------
__global__ __launch_bounds__(256) void split_kernel(const float* __restrict__ x,
    __nv_bfloat16* __restrict__ hi, __nv_bfloat16* __restrict__ lo, int n4)
{
    int i = blockIdx.x * 256 + threadIdx.x;
    if (i >= n4) return;
    float4 v = ((const float4*)x)[i];
    __nv_bfloat16 h0 = __float2bfloat16(v.x), h1 = __float2bfloat16(v.y);
    __nv_bfloat16 h2 = __float2bfloat16(v.z), h3 = __float2bfloat16(v.w);
    __nv_bfloat162* H = (__nv_bfloat162*)hi;
    __nv_bfloat162* L = (__nv_bfloat162*)lo;
    H[i*2]   = __halves2bfloat162(h0, h1);
    H[i*2+1] = __halves2bfloat162(h2, h3);
    L[i*2]   = __halves2bfloat162(
        __float2bfloat16(v.x - __bfloat162float(h0)),
        __float2bfloat16(v.y - __bfloat162float(h1)));
    L[i*2+1] = __halves2bfloat162(
        __float2bfloat16(v.z - __bfloat162float(h2)),
        __float2bfloat16(v.w - __bfloat162float(h3)));
}

// ---------------- weight transpose + split: W[K][N] -> hi/lo[N][K] ----------------
__global__ __launch_bounds__(256) void wtrans_kernel(const float* __restrict__ W,
    __nv_bfloat16* __restrict__ hi, __nv_bfloat16* __restrict__ lo, int K, int N)
{
    __shared__ float t[32][33];
    int tx = threadIdx.x, ty = threadIdx.y;
    int n0 = blockIdx.x * 32, k0 = blockIdx.y * 32;
    #pragma unroll
    for (int i = 0; i < 4; i++)
        t[ty + i*8][tx] = W[(size_t)(k0 + ty + i*8) * N + n0 + tx];
    __syncthreads();
    #pragma unroll
    for (int i = 0; i < 4; i++) {
        float v = t[tx][ty + i*8];
        size_t o = (size_t)(n0 + ty + i*8) * K + k0 + tx;
        __nv_bfloat16 h = __float2bfloat16(v);
        hi[o] = h;
        lo[o] = __float2bfloat16(v - __bfloat162float(h));
    }
}

// ---------------- LayerNorm with optional bf16 hi/lo dual output ----------------
__global__ __launch_bounds__(256) void ln_kernel(
    const float* __restrict__ x, const float* __restrict__ g,
    const float* __restrict__ b, float* __restrict__ out,
    __nv_bfloat16* __restrict__ oh, __nv_bfloat16* __restrict__ ol)
{
    const int row = blockIdx.x;
    const int tid = threadIdx.x;
    const float* xr = x + (long)row * HH;
    float v0 = xr[tid], v1 = xr[tid + 256], v2 = xr[tid + 512];

    __shared__ float red[8];
    float s = v0 + v1 + v2;
    #pragma unroll
    for (int o2 = 16; o2; o2 >>= 1) s += __shfl_xor_sync(0xffffffffu, s, o2);
    if ((tid & 31) == 0) red[tid >> 5] = s;
    __syncthreads();
    float tot = 0.f;
    #pragma unroll
    for (int i = 0; i < 8; i++) tot += red[i];
    float mean = tot * (1.0f / 768.0f);

    float d0 = v0 - mean, d1 = v1 - mean, d2 = v2 - mean;
    float sq = d0*d0 + d1*d1 + d2*d2;
    __syncthreads();
    #pragma unroll
    for (int o2 = 16; o2; o2 >>= 1) sq += __shfl_xor_sync(0xffffffffu, sq, o2);
    if ((tid & 31) == 0) red[tid >> 5] = sq;
    __syncthreads();
    float tot2 = 0.f;
    #pragma unroll
    for (int i = 0; i < 8; i++) tot2 += red[i];
    float rstd = rsqrtf(tot2 * (1.0f / 768.0f) + 1e-12f);

    float* orow = out + (long)row * HH;
    float r0 = d0 * rstd * g[tid]       + b[tid];
    float r1 = d1 * rstd * g[tid + 256] + b[tid + 256];
    float r2 = d2 * rstd * g[tid + 512] + b[tid + 512];
    orow[tid] = r0; orow[tid + 256] = r1; orow[tid + 512] = r2;
    if (oh) {
        size_t base = (size_t)row * HH;
        __nv_bfloat16 h0 = __float2bfloat16(r0);
        __nv_bfloat16 h1 = __float2bfloat16(r1);
        __nv_bfloat16 h2 = __float2bfloat16(r2);
        oh[base + tid] = h0;       ol[base + tid]       = __float2bfloat16(r0 - __bfloat162float(h0));
        oh[base + tid + 256] = h1; ol[base + tid + 256] = __float2bfloat16(r1 - __bfloat162float(h1));
        oh[base + tid + 512] = h2; ol[base + tid + 512] = __float2bfloat16(r2 - __bfloat162float(h2));
    }
}

// ---------------- launch ----------------
extern "C" void kernel_launch(void* const* d_in, const int* in_sizes, int n_in,
                              void* d_out, int out_size)
{
    const float* x    = (const float*)d_in[0];
    const int*   mask = (const int*)  d_in[1];
    const float* Wq   = (const float*)d_in[2];
    const float* bq   = (const float*)d_in[3];
    const float* Wk   = (const float*)d_in[4];
    const float* bk   = (const float*)d_in[5];
    const float* Wv   = (const float*)d_in[6];
    const float* bv   = (const float*)d_in[7];
    const float* Wao  = (const float*)d_in[8];
    const float* bao  = (const float*)d_in[9];
    const float* g1   = (const float*)d_in[10];
    const float* b1   = (const float*)d_in[11];
    const float* Wi   = (const float*)d_in[12];
    const float* bi   = (const float*)d_in[13];
    const float* Wfo  = (const float*)d_in[14];
    const float* bfo  = (const float*)d_in[15];
    const float* g2   = (const float*)d_in[16];
    const float* b2   = (const float*)d_in[17];

    float *h_, *tmp_, *attn_;
    __nv_bfloat16 *hh_, *hl_, *qh_, *ql_, *kh_, *kl_, *vh_, *vl_;
    __nv_bfloat16 *vth_, *vtl_, *cth_, *ctl_, *aah_, *aal_, *ih_, *il_, *wh_, *wl_;
    cudaGetSymbolAddress((void**)&h_,    g_h);
    cudaGetSymbolAddress((void**)&tmp_,  g_tmp);
    cudaGetSymbolAddress((void**)&attn_, g_attn);
    cudaGetSymbolAddress((void**)&hh_,   g_hh);
    cudaGetSymbolAddress((void**)&hl_,   g_hl);
    cudaGetSymbolAddress((void**)&qh_,   g_qh);
    cudaGetSymbolAddress((void**)&ql_,   g_ql);
    cudaGetSymbolAddress((void**)&kh_,   g_kh);
    cudaGetSymbolAddress((void**)&kl_,   g_kl);
    cudaGetSymbolAddress((void**)&vh_,   g_vh);
    cudaGetSymbolAddress((void**)&vl_,   g_vl);
    cudaGetSymbolAddress((void**)&vth_,  g_vth);
    cudaGetSymbolAddress((void**)&vtl_,  g_vtl);
    cudaGetSymbolAddress((void**)&cth_,  g_cth);
    cudaGetSymbolAddress((void**)&ctl_,  g_ctl);
    cudaGetSymbolAddress((void**)&aah_,  g_aah);
    cudaGetSymbolAddress((void**)&aal_,  g_aal);
    cudaGetSymbolAddress((void**)&ih_,   g_ih);
    cudaGetSymbolAddress((void**)&il_,   g_il);
    cudaGetSymbolAddress((void**)&wh_,   g_wh);
    cudaGetSymbolAddress((void**)&wl_,   g_wl);

    cudaFuncSetAttribute(gemm_tc,
                         cudaFuncAttributeMaxDynamicSharedMemorySize, GEMM_SMEM);
    cudaFuncSetAttribute(flashattn,
                         cudaFuncAttributeMaxDynamicSharedMemorySize, FSMEM);

    const int M = BB * SS;  // 2048

    // ---- weight prep: transpose + bf16 hi/lo split ----
    for (int l = 0; l < NL; l++) {
        size_t lo = (size_t)l * LSTRIDE;
        wtrans_kernel<<<dim3(HH/32, HH/32), dim3(32,8)>>>(Wq  + (long)l*HH*HH, wh_+lo+WQOFF,  wl_+lo+WQOFF,  HH, HH);
        wtrans_kernel<<<dim3(HH/32, HH/32), dim3(32,8)>>>(Wk  + (long)l*HH*HH, wh_+lo+WKOFF,  wl_+lo+WKOFF,  HH, HH);
        wtrans_kernel<<<dim3(HH/32, HH/32), dim3(32,8)>>>(Wv  + (long)l*HH*HH, wh_+lo+WVOFF,  wl_+lo+WVOFF,  HH, HH);
        wtrans_kernel<<<dim3(HH/32, HH/32), dim3(32,8)>>>(Wao + (long)l*HH*HH, wh_+lo+WAOOFF, wl_+lo+WAOOFF, HH, HH);
        wtrans_kernel<<<dim3(FF/32, HH/32), dim3(32,8)>>>(Wi  + (long)l*HH*FF, wh_+lo+WIOFF,  wl_+lo+WIOFF,  HH, FF);
        wtrans_kernel<<<dim3(HH/32, FF/32), dim3(32,8)>>>(Wfo + (long)l*FF*HH, wh_+lo+WFOOFF, wl_+lo+WFOOFF, FF, HH);
    }

    split_kernel<<<(M*HH/4 + 255)/256, 256>>>(x, hh_, hl_, M*HH/4);

    for (int l = 0; l < NL; l++) {
        const float* hin = (l == 0) ? x : h_;
        size_t lo = (size_t)l * LSTRIDE;

        // QKV -> bf16 hi/lo outputs
        {
            GemmArgs a = {};
            a.ah = hh_; a.al = hl_;
            a.bh0 = wh_+lo+WQOFF; a.bh1 = wh_+lo+WKOFF; a.bh2 = wh_+lo+WVOFF;
            a.bl0 = wl_+lo+WQOFF; a.bl1 = wl_+lo+WKOFF; a.bl2 = wl_+lo+WVOFF;
            a.bias0 = bq + l*HH; a.bias1 = bk + l*HH; a.bias2 = bv + l*HH;
            a.ch0 = qh_; a.cl0 = ql_; a.ch1 = kh_; a.cl1 = kl_; a.ch2 = vh_; a.cl2 = vl_;
            a.K = HH; a.N = HH; a.gelu = 0; a.outbf = 1;
            gemm_tc<<<dim3(HH/128, M/128, 3), 512, GEMM_SMEM>>>(a);
        }

        vtrans_kernel<<<dim3(SS/32, BB*NH*2), dim3(32,8)>>>(vh_, vl_, vth_, vtl_);
        flashattn<<<dim3(SS/64, BB*NH), 128, FSMEM>>>(qh_, ql_, kh_, kl_, vth_, vtl_,
                                                      mask, cth_, ctl_);

        // AO proj + residual (fp32 out)
        {
            GemmArgs a = {};
            a.ah = cth_; a.al = ctl_;
            a.bh0 = wh_+lo+WAOOFF; a.bh1 = a.bh0; a.bh2 = a.bh0;
            a.bl0 = wl_+lo+WAOOFF; a.bl1 = a.bl0; a.bl2 = a.bl0;
            a.bias0 = bao + l*HH; a.bias1 = a.bias0; a.bias2 = a.bias0;
            a.resid = hin; a.c0 = tmp_; a.c1 = tmp_; a.c2 = tmp_;
            a.K = HH; a.N = HH; a.gelu = 0; a.outbf = 0;
            gemm_tc<<<dim3(HH/128, M/128, 1), 512, GEMM_SMEM>>>(a);
        }
        ln_kernel<<<M, 256>>>(tmp_, g1 + l*HH, b1 + l*HH, attn_, aah_, aal_);

        // FFN1 (gelu) -> bf16 hi/lo
        {
            GemmArgs a = {};
            a.ah = aah_; a.al = aal_;
            a.bh0 = wh_+lo+WIOFF; a.bh1 = a.bh0; a.bh2 = a.bh0;
            a.bl0 = wl_+lo+WIOFF; a.bl1 = a.bl0; a.bl2 = a.bl0;
            a.bias0 = bi + l*FF; a.bias1 = a.bias0; a.bias2 = a.bias0;
            a.ch0 = ih_; a.cl0 = il_; a.ch1 = ih_; a.cl1 = il_; a.ch2 = ih_; a.cl2 = il_;
            a.K = HH; a.N = FF; a.gelu = 1; a.outbf = 1;
            gemm_tc<<<dim3(FF/128, M/128, 1), 512, GEMM_SMEM>>>(a);
        }

        // FFN2 + residual (fp32 out)
        {
            GemmArgs a = {};
            a.ah = ih_; a.al = il_;
            a.bh0 = wh_+lo+WFOOFF; a.bh1 = a.bh0; a.bh2 = a.bh0;
            a.bl0 = wl_+lo+WFOOFF; a.bl1 = a.bl0; a.bl2 = a.bl0;
            a.bias0 = bfo + l*HH; a.bias1 = a.bias0; a.bias2 = a.bias0;
            a.resid = attn_; a.c0 = tmp_; a.c1 = tmp_; a.c2 = tmp_;
            a.K = FF; a.N = HH; a.gelu = 0; a.outbf = 0;
            gemm_tc<<<dim3(HH/128, M/128, 1), 512, GEMM_SMEM>>>(a);
        }

        if (l == NL - 1) {
            ln_kernel<<<M, 256>>>(tmp_, g2 + l*HH, b2 + l*HH, (float*)d_out,
                                  (__nv_bfloat16*)nullptr, (__nv_bfloat16*)nullptr);
        } else {
            ln_kernel<<<M, 256>>>(tmp_, g2 + l*HH, b2 + l*HH, h_, hh_, hl_);
        }
    }
}

// round 6
// speedup vs baseline: 2.9579x; 1.0823x over previous
#include <cuda_runtime.h>
#include <cuda_bf16.h>
#include <math.h>
#include <stdint.h>

#define BB 2
#define SS 1024
#define HH 768
#define NH 12
#define DH 64
#define FF 3072
#define NL 4

// ---------------- scratch (device globals; no allocation allowed) ----------------
__device__ float g_h[BB*SS*HH];
__device__ float g_tmp[BB*SS*HH];
__device__ float g_attn[BB*SS*HH];
__device__ float g_p0[BB*SS*HH];
__device__ float g_p1[BB*SS*HH];
__device__ float g_p2[BB*SS*HH];

__device__ __nv_bfloat16 g_hh[BB*SS*HH], g_hl[BB*SS*HH];
__device__ __nv_bfloat16 g_qh[BB*SS*HH], g_ql[BB*SS*HH];
__device__ __nv_bfloat16 g_kh[BB*SS*HH], g_kl[BB*SS*HH];
__device__ __nv_bfloat16 g_vh[BB*SS*HH], g_vl[BB*SS*HH];
__device__ __nv_bfloat16 g_vth[BB*SS*HH], g_vtl[BB*SS*HH];
__device__ __nv_bfloat16 g_cth[BB*SS*HH], g_ctl[BB*SS*HH];
__device__ __nv_bfloat16 g_aah[BB*SS*HH], g_aal[BB*SS*HH];
__device__ __nv_bfloat16 g_ih[BB*SS*FF], g_il[BB*SS*FF];

// transposed+split weights per layer: [wq wk wv wao wi wfo], each [N][K] row-major
#define WQOFF  0
#define WKOFF  589824
#define WVOFF  1179648
#define WAOOFF 1769472
#define WIOFF  2359296
#define WFOOFF 4718592
#define LSTRIDE 7077888
__device__ __nv_bfloat16 g_wh[(size_t)NL*LSTRIDE];
__device__ __nv_bfloat16 g_wl[(size_t)NL*LSTRIDE];

// ---------------- PTX helpers (arch-neutral: ldmatrix / mma.sync / cp.async) ----------------
__device__ __forceinline__ uint32_t smem_u32(const void* p) {
    uint32_t a;
    asm("{ .reg .u64 t; cvta.to.shared.u64 t, %1; cvt.u32.u64 %0, t; }" : "=r"(a) : "l"(p));
    return a;
}
__device__ __forceinline__ void cpa16(uint32_t dst, const void* src) {
    asm volatile("cp.async.cg.shared.global [%0], [%1], 16;" :: "r"(dst), "l"(src));
}
#define CP_COMMIT() asm volatile("cp.async.commit_group;" ::: "memory")

__device__ __forceinline__ void ldsm4(uint32_t* r, uint32_t a) {
    asm volatile("ldmatrix.sync.aligned.m8n8.x4.shared.b16 {%0,%1,%2,%3}, [%4];"
        : "=r"(r[0]), "=r"(r[1]), "=r"(r[2]), "=r"(r[3]) : "r"(a));
}
__device__ __forceinline__ void mma16816(float* c, const uint32_t* a, const uint32_t* b) {
    asm volatile("mma.sync.aligned.m16n8k16.row.col.f32.bf16.bf16.f32 "
        "{%0,%1,%2,%3}, {%4,%5,%6,%7}, {%8,%9}, {%0,%1,%2,%3};"
        : "+f"(c[0]), "+f"(c[1]), "+f"(c[2]), "+f"(c[3])
        : "r"(a[0]), "r"(a[1]), "r"(a[2]), "r"(a[3]), "r"(b[0]), "r"(b[1]));
}
__device__ __forceinline__ uint32_t pack_bf2(__nv_bfloat16 a, __nv_bfloat16 b) {
    __nv_bfloat162 t = __halves2bfloat162(a, b);
    return *(uint32_t*)&t;
}

// ---------------- bf16x3 HMMA GEMM: C = A @ B^T (+bias)(+resid)(gelu), fp32/bf16-split out,
// optional split-K (z = K-slice) ----
struct GemmArgs {
    const __nv_bfloat16 *ah, *al;
    const __nv_bfloat16 *bh0, *bh1, *bh2, *bl0, *bl1, *bl2;
    const float *bias0, *bias1, *bias2;
    const float *resid;
    float *c0, *c1, *c2;
    __nv_bfloat16 *ch0, *cl0, *ch1, *cl1, *ch2, *cl2;
    int K, N, gelu, outbf, Kld, ksplit;
};

#define ABUF 10240            // 128 rows * 80B (64B data + 16B pad)
#define STGB (4*ABUF)         // Ah, Al, Bh, Bl
#define NSTG 3
#define GEMM_SMEM (NSTG*STGB) // 122880

__global__ __launch_bounds__(512) void gemm_tc(GemmArgs g) {
    extern __shared__ char smem[];
    const uint32_t su = smem_u32(smem);
    const int tid = threadIdx.x;
    const int lane = tid & 31, warp = tid >> 5;
    const int warpM = warp & 3, warpN = warp >> 2;
    const int m0 = blockIdx.y << 7, n0 = blockIdx.x << 7;

    const __nv_bfloat16 *bh, *bl; const float* bias; float* C;
    __nv_bfloat16 *CH, *CL;
    if (blockIdx.z == 0)      { bh=g.bh0; bl=g.bl0; bias=g.bias0; C=g.c0; CH=g.ch0; CL=g.cl0; }
    else if (blockIdx.z == 1) { bh=g.bh1; bl=g.bl1; bias=g.bias1; C=g.c1; CH=g.ch1; CL=g.cl1; }
    else                      { bh=g.bh2; bl=g.bl2; bias=g.bias2; C=g.c2; CH=g.ch2; CL=g.cl2; }
    const int K = g.K, N = g.N, nk = K >> 5;
    const int kbase = g.ksplit ? (int)blockIdx.z * K : 0;

    const int ldg_row = tid >> 2, ldg_c = tid & 3;
    const size_t ldab = (size_t)g.Kld * 2;
    const char* pAh = (const char*)g.ah + ((size_t)(m0 + ldg_row)) * ldab + (size_t)kbase*2 + ldg_c * 16;
    const char* pAl = (const char*)g.al + ((size_t)(m0 + ldg_row)) * ldab + (size_t)kbase*2 + ldg_c * 16;
    const char* pBh = (const char*)bh   + ((size_t)(n0 + ldg_row)) * ldab + (size_t)kbase*2 + ldg_c * 16;
    const char* pBl = (const char*)bl   + ((size_t)(n0 + ldg_row)) * ldab + (size_t)kbase*2 + ldg_c * 16;
    const uint32_t sdst = ldg_row * 80 + ldg_c * 16;

    auto load_chunk = [&](int j, int s) {
        uint32_t sb = su + s * STGB + sdst;
        size_t go = (size_t)j * 64;
        cpa16(sb,            pAh + go);
        cpa16(sb +   ABUF,   pAl + go);
        cpa16(sb + 2*ABUF,   pBh + go);
        cpa16(sb + 3*ABUF,   pBl + go);
    };

    load_chunk(0, 0); CP_COMMIT();
    load_chunk(1, 1); CP_COMMIT();

    float acc[2][4][4];
    #pragma unroll
    for (int i = 0; i < 2; i++)
        #pragma unroll
        for (int j = 0; j < 4; j++)
            #pragma unroll
            for (int r = 0; r < 4; r++) acc[i][j][r] = 0.f;

    const uint32_t a_off = (uint32_t)(warpM*32 + (lane & 15)) * 80 + (lane >> 4) * 16;
    const uint32_t b_off = (uint32_t)(warpN*32 + (((lane >> 4) & 1) << 3) + (lane & 7)) * 80
                         + ((lane >> 3) & 1) * 16;

    for (int i = 0; i < nk; i++) {
        asm volatile("cp.async.wait_group 1;" ::: "memory");
        __syncthreads();
        int j = i + 2;
        if (j < nk) load_chunk(j, j % NSTG);
        CP_COMMIT();

        uint32_t base = su + (i % NSTG) * STGB;
        #pragma unroll
        for (int ks = 0; ks < 2; ks++) {
            uint32_t ko = ks * 32;
            uint32_t ah0[4], ah1[4], al0[4], al1[4];
            uint32_t bhf0[4], bhf1[4], blf0[4], blf1[4];
            ldsm4(ah0, base + a_off + ko);
            ldsm4(ah1, base + a_off + 16*80 + ko);
            ldsm4(al0, base + ABUF + a_off + ko);
            ldsm4(al1, base + ABUF + a_off + 16*80 + ko);
            ldsm4(bhf0, base + 2*ABUF + b_off + ko);
            ldsm4(bhf1, base + 2*ABUF + b_off + 16*80 + ko);
            ldsm4(blf0, base + 3*ABUF + b_off + ko);
            ldsm4(blf1, base + 3*ABUF + b_off + 16*80 + ko);
            uint32_t* AH[2] = {ah0, ah1};
            uint32_t* AL[2] = {al0, al1};
            #pragma unroll
            for (int mt = 0; mt < 2; mt++) {
                mma16816(acc[mt][0], AH[mt], bhf0);
                mma16816(acc[mt][0], AH[mt], blf0);
                mma16816(acc[mt][0], AL[mt], bhf0);
                mma16816(acc[mt][1], AH[mt], bhf0+2);
                mma16816(acc[mt][1], AH[mt], blf0+2);
                mma16816(acc[mt][1], AL[mt], bhf0+2);
                mma16816(acc[mt][2], AH[mt], bhf1);
                mma16816(acc[mt][2], AH[mt], blf1);
                mma16816(acc[mt][2], AL[mt], bhf1);
                mma16816(acc[mt][3], AH[mt], bhf1+2);
                mma16816(acc[mt][3], AH[mt], blf1+2);
                mma16816(acc[mt][3], AL[mt], bhf1+2);
            }
        }
    }

    const int erow = m0 + warpM*32 + (lane >> 2);
    const int ecol = n0 + warpN*32 + (lane & 3)*2;
    #pragma unroll
    for (int mt = 0; mt < 2; mt++) {
        #pragma unroll
        for (int nt = 0; nt < 4; nt++) {
            int c = ecol + nt*8;
            float b0 = bias ? bias[c] : 0.f, b1 = bias ? bias[c+1] : 0.f;
            #pragma unroll
            for (int half = 0; half < 2; half++) {
                int r = erow + mt*16 + half*8;
                float o0 = acc[mt][nt][half*2+0] + b0;
                float o1 = acc[mt][nt][half*2+1] + b1;
                if (g.resid) {
                    float2 rv = *(const float2*)(g.resid + (size_t)r * N + c);
                    o0 += rv.x; o1 += rv.y;
                }
                if (g.gelu) {
                    o0 = 0.5f * o0 * (1.0f + erff(o0 * 0.70710678118654752f));
                    o1 = 0.5f * o1 * (1.0f + erff(o1 * 0.70710678118654752f));
                }
                if (g.outbf) {
                    __nv_bfloat16 h0 = __float2bfloat16(o0), h1 = __float2bfloat16(o1);
                    __nv_bfloat16 l0 = __float2bfloat16(o0 - __bfloat162float(h0));
                    __nv_bfloat16 l1 = __float2bfloat16(o1 - __bfloat162float(h1));
                    *(uint32_t*)(CH + (size_t)r * N + c) = pack_bf2(h0, h1);
                    *(uint32_t*)(CL + (size_t)r * N + c) = pack_bf2(l0, l1);
                } else {
                    float2 ov; ov.x = o0; ov.y = o1;
                    *(float2*)(C + (size_t)r * N + c) = ov;
                }
            }
        }
    }
}

// ---------------- split-K reduce: out = p0+p1+p2 + bias + resid ----------------
__global__ __launch_bounds__(256) void reduce3(
    const float4* __restrict__ p0, const float4* __restrict__ p1,
    const float4* __restrict__ p2, const float* __restrict__ bias,
    const float4* __restrict__ resid, float4* __restrict__ out)
{
    int i = blockIdx.x * 256 + threadIdx.x;       // of 2048*768/4
    int col = (i % (HH/4)) * 4;
    float4 a = p0[i], b = p1[i], c = p2[i], r = resid[i];
    float4 o;
    o.x = a.x + b.x + c.x + bias[col+0] + r.x;
    o.y = a.y + b.y + c.y + bias[col+1] + r.y;
    o.z = a.z + b.z + c.z + bias[col+2] + r.z;
    o.w = a.w + b.w + c.w + bias[col+3] + r.w;
    out[i] = o;
}

// ---------------- flash attention: S=QK^T (bf16x3) -> mask/scale/softmax -> O=PV (bf16x3) ----
// Q-tile 64, K-tile 64, 128 threads (4 warps x 16 q rows). V pre-transposed: vt[bh][dh][S].
#define FROW 144
#define FQBUF 9216           // 64*144
#define FSTG  36864          // 4 bufs (kh,kl,vh,vl)
#define FSMEM (2*FQBUF + 2*FSTG)   // 92160

__global__ __launch_bounds__(128) void flashattn(
    const __nv_bfloat16* __restrict__ qh, const __nv_bfloat16* __restrict__ ql,
    const __nv_bfloat16* __restrict__ kh, const __nv_bfloat16* __restrict__ kl,
    const __nv_bfloat16* __restrict__ vth, const __nv_bfloat16* __restrict__ vtl,
    const int* __restrict__ mask,
    __nv_bfloat16* __restrict__ cth, __nv_bfloat16* __restrict__ ctl)
{
    extern __shared__ char smem[];
    const uint32_t su = smem_u32(smem);
    const int tid = threadIdx.x, lane = tid & 31, warp = tid >> 5;
    const int q0 = blockIdx.x * 64, bh = blockIdx.y;
    const int b = bh / NH, h = bh % NH;
    const int wr = warp * 16;

    const char* Qh = (const char*)(qh + ((size_t)b*SS + q0)*HH + h*DH);
    const char* Ql = (const char*)(ql + ((size_t)b*SS + q0)*HH + h*DH);
    const char* Kh = (const char*)(kh + ((size_t)b*SS)*HH + h*DH);
    const char* Kl = (const char*)(kl + ((size_t)b*SS)*HH + h*DH);
    const char* Vh = (const char*)(vth + (size_t)bh*DH*SS);
    const char* Vl = (const char*)(vtl + (size_t)bh*DH*SS);

    #pragma unroll
    for (int c = 0; c < 4; c++) {
        int idx = tid + c*128;
        int row = idx >> 3, chn = idx & 7;
        uint32_t dst = su + row*FROW + chn*16;
        size_t so = (size_t)row*1536 + chn*16;
        cpa16(dst,         Qh + so);
        cpa16(dst + FQBUF, Ql + so);
    }
    CP_COMMIT();

    auto load_kv = [&](int j, int s) {
        uint32_t sb = su + 2*FQBUF + s*FSTG;
        int k0 = j * 64;
        #pragma unroll
        for (int c = 0; c < 4; c++) {
            int idx = tid + c*128;
            int row = idx >> 3, chn = idx & 7;
            uint32_t dst = sb + row*FROW + chn*16;
            size_t ko = (size_t)(k0 + row)*1536 + chn*16;
            cpa16(dst,           Kh + ko);
            cpa16(dst +   FQBUF, Kl + ko);
            size_t vo = (size_t)row*2048 + (size_t)k0*2 + chn*16;
            cpa16(dst + 2*FQBUF, Vh + vo);
            cpa16(dst + 3*FQBUF, Vl + vo);
        }
    };
    load_kv(0, 0); CP_COMMIT();
    load_kv(1, 1); CP_COMMIT();

    asm volatile("cp.async.wait_group 2;" ::: "memory");
    __syncthreads();

    uint32_t qhf[4][4], qlf[4][4];
    {
        uint32_t abase = su + (uint32_t)(wr + (lane & 15))*FROW + (lane >> 4)*16;
        #pragma unroll
        for (int kc = 0; kc < 4; kc++) {
            ldsm4(qhf[kc], abase + kc*32);
            ldsm4(qlf[kc], abase + FQBUF + kc*32);
        }
    }

    float o[8][4];
    #pragma unroll
    for (int j = 0; j < 8; j++)
        #pragma unroll
        for (int r = 0; r < 4; r++) o[j][r] = 0.f;
    float m0 = -1e30f, m1 = -1e30f, l0 = 0.f, l1 = 0.f;

    const int r = lane >> 2;
    const int colb = (lane & 3) * 2;
    const int* mrow0 = mask + ((size_t)b*SS + (q0 + wr + r))*SS;
    const int* mrow8 = mrow0 + 8*SS;
    const uint32_t boff = (uint32_t)((((lane >> 4) & 1) << 3) + (lane & 7))*FROW
                        + ((lane >> 3) & 1)*16;

    for (int i = 0; i < 16; i++) {
        asm volatile("cp.async.wait_group 1;" ::: "memory");
        __syncthreads();
        const uint32_t sb = su + 2*FQBUF + (i & 1)*FSTG;
        const int k0 = i * 64;

        float sc_[8][4];
        #pragma unroll
        for (int j = 0; j < 8; j++)
            #pragma unroll
            for (int t = 0; t < 4; t++) sc_[j][t] = 0.f;
        #pragma unroll
        for (int nt = 0; nt < 4; nt++) {
            #pragma unroll
            for (int kc = 0; kc < 4; kc++) {
                uint32_t fh[4], fl[4];
                ldsm4(fh, sb + nt*16*FROW + boff + kc*32);
                ldsm4(fl, sb + FQBUF + nt*16*FROW + boff + kc*32);
                mma16816(sc_[2*nt],   qhf[kc], fh);
                mma16816(sc_[2*nt],   qhf[kc], fl);
                mma16816(sc_[2*nt],   qlf[kc], fh);
                mma16816(sc_[2*nt+1], qhf[kc], fh+2);
                mma16816(sc_[2*nt+1], qhf[kc], fl+2);
                mma16816(sc_[2*nt+1], qlf[kc], fh+2);
            }
        }
        #pragma unroll
        for (int j = 0; j < 8; j++) {
            int kc2 = k0 + j*8 + colb;
            int2 ma = *(const int2*)(mrow0 + kc2);
            int2 mb = *(const int2*)(mrow8 + kc2);
            sc_[j][0] = sc_[j][0]*0.125f + (1.f - (float)ma.x)*(-10000.f);
            sc_[j][1] = sc_[j][1]*0.125f + (1.f - (float)ma.y)*(-10000.f);
            sc_[j][2] = sc_[j][2]*0.125f + (1.f - (float)mb.x)*(-10000.f);
            sc_[j][3] = sc_[j][3]*0.125f + (1.f - (float)mb.y)*(-10000.f);
        }
        float mx0 = -1e30f, mx1 = -1e30f;
        #pragma unroll
        for (int j = 0; j < 8; j++) {
            mx0 = fmaxf(mx0, fmaxf(sc_[j][0], sc_[j][1]));
            mx1 = fmaxf(mx1, fmaxf(sc_[j][2], sc_[j][3]));
        }
        mx0 = fmaxf(mx0, __shfl_xor_sync(0xffffffffu, mx0, 1));
        mx0 = fmaxf(mx0, __shfl_xor_sync(0xffffffffu, mx0, 2));
        mx1 = fmaxf(mx1, __shfl_xor_sync(0xffffffffu, mx1, 1));
        mx1 = fmaxf(mx1, __shfl_xor_sync(0xffffffffu, mx1, 2));
        float mn0 = fmaxf(m0, mx0), mn1 = fmaxf(m1, mx1);
        float sf0 = __expf(m0 - mn0), sf1 = __expf(m1 - mn1);
        m0 = mn0; m1 = mn1;
        float rs0 = 0.f, rs1 = 0.f;
        #pragma unroll
        for (int j = 0; j < 8; j++) {
            sc_[j][0] = __expf(sc_[j][0] - mn0);
            sc_[j][1] = __expf(sc_[j][1] - mn0);
            sc_[j][2] = __expf(sc_[j][2] - mn1);
            sc_[j][3] = __expf(sc_[j][3] - mn1);
            rs0 += sc_[j][0] + sc_[j][1];
            rs1 += sc_[j][2] + sc_[j][3];
        }
        rs0 += __shfl_xor_sync(0xffffffffu, rs0, 1);
        rs0 += __shfl_xor_sync(0xffffffffu, rs0, 2);
        rs1 += __shfl_xor_sync(0xffffffffu, rs1, 1);
        rs1 += __shfl_xor_sync(0xffffffffu, rs1, 2);
        l0 = l0*sf0 + rs0;
        l1 = l1*sf1 + rs1;
        #pragma unroll
        for (int j = 0; j < 8; j++) {
            o[j][0] *= sf0; o[j][1] *= sf0; o[j][2] *= sf1; o[j][3] *= sf1;
        }
        uint32_t phf[4][4], plf[4][4];
        #pragma unroll
        for (int kc = 0; kc < 4; kc++) {
            #pragma unroll
            for (int half = 0; half < 2; half++) {
                int j = 2*kc + half;
                __nv_bfloat16 h0 = __float2bfloat16(sc_[j][0]);
                __nv_bfloat16 h1 = __float2bfloat16(sc_[j][1]);
                __nv_bfloat16 h2 = __float2bfloat16(sc_[j][2]);
                __nv_bfloat16 h3 = __float2bfloat16(sc_[j][3]);
                phf[kc][half*2+0] = pack_bf2(h0, h1);
                phf[kc][half*2+1] = pack_bf2(h2, h3);
                plf[kc][half*2+0] = pack_bf2(
                    __float2bfloat16(sc_[j][0] - __bfloat162float(h0)),
                    __float2bfloat16(sc_[j][1] - __bfloat162float(h1)));
                plf[kc][half*2+1] = pack_bf2(
                    __float2bfloat16(sc_[j][2] - __bfloat162float(h2)),
                    __float2bfloat16(sc_[j][3] - __bfloat162float(h3)));
            }
        }
        #pragma unroll
        for (int nt = 0; nt < 4; nt++) {
            #pragma unroll
            for (int kc = 0; kc < 4; kc++) {
                uint32_t fh[4], fl[4];
                ldsm4(fh, sb + 2*FQBUF + nt*16*FROW + boff + kc*32);
                ldsm4(fl, sb + 3*FQBUF + nt*16*FROW + boff + kc*32);
                mma16816(o[2*nt],   phf[kc], fh);
                mma16816(o[2*nt],   phf[kc], fl);
                mma16816(o[2*nt],   plf[kc], fh);
                mma16816(o[2*nt+1], phf[kc], fh+2);
                mma16816(o[2*nt+1], phf[kc], fl+2);
                mma16816(o[2*nt+1], plf[kc], fh+2);
            }
        }
        __syncthreads();
        if (i + 2 < 16) load_kv(i + 2, i & 1);
        CP_COMMIT();
    }

    float inv0 = 1.f / l0, inv1 = 1.f / l1;
    size_t base0 = ((size_t)b*SS + (q0 + wr + r))*HH + h*DH;
    size_t base8 = base0 + (size_t)8*HH;
    #pragma unroll
    for (int j = 0; j < 8; j++) {
        int col = j*8 + colb;
        float a0 = o[j][0]*inv0, a1 = o[j][1]*inv0;
        float a2 = o[j][2]*inv1, a3 = o[j][3]*inv1;
        __nv_bfloat16 h0 = __float2bfloat16(a0), h1 = __float2bfloat16(a1);
        __nv_bfloat16 h2 = __float2bfloat16(a2), h3 = __float2bfloat16(a3);
        *(uint32_t*)(cth + base0 + col) = pack_bf2(h0, h1);
        *(uint32_t*)(ctl + base0 + col) = pack_bf2(
            __float2bfloat16(a0 - __bfloat162float(h0)),
            __float2bfloat16(a1 - __bfloat162float(h1)));
        *(uint32_t*)(cth + base8 + col) = pack_bf2(h2, h3);
        *(uint32_t*)(ctl + base8 + col) = pack_bf2(
            __float2bfloat16(a2 - __bfloat162float(h2)),
            __float2bfloat16(a3 - __bfloat162float(h3)));
    }
}

// ---------------- V transpose: v[b,s,h*64+d] -> vt[(bh*64+d)][s] ----------------
__global__ __launch_bounds__(256) void vtrans_kernel(
    const __nv_bfloat16* __restrict__ vh, const __nv_bfloat16* __restrict__ vl,
    __nv_bfloat16* __restrict__ oh, __nv_bfloat16* __restrict__ ol)
{
    __shared__ __nv_bfloat16 th[32][33], tl[32][33];
    int tx = threadIdx.x, ty = threadIdx.y;
    int bh = blockIdx.y >> 1, dblk = blockIdx.y & 1;
    int b = bh / NH, h = bh % NH;
    int s0 = blockIdx.x * 32, d0 = dblk * 32;
    #pragma unroll
    for (int i = 0; i < 4; i++) {
        int s = ty + i*8;
        size_t off = ((size_t)b*SS + s0 + s)*HH + h*DH + d0 + tx;
        th[s][tx] = vh[off];
        tl[s][tx] = vl[off];
    }
    __syncthreads();
    #pragma unroll
    for (int i = 0; i < 4; i++) {
        int d = ty + i*8;
        size_t off = ((size_t)bh*DH + d0 + d)*SS + s0 + tx;
        oh[off] = th[tx][d];
        ol[off] = tl[tx][d];
    }
}

// ---------------- split fp32 -> bf16 hi/lo (only for initial x) ----------------
__global__ __launch_bounds__(256) void split_kernel(const float* __restrict__ x,
    __nv_bfloat16* __restrict__ hi, __nv_bfloat16* __restrict__ lo, int n4)
{
    int i = blockIdx.x * 256 + threadIdx.x;
    if (i >= n4) return;
    float4 v = ((const float4*)x)[i];
    __nv_bfloat16 h0 = __float2bfloat16(v.x), h1 = __float2bfloat16(v.y);
    __nv_bfloat16 h2 = __float2bfloat16(v.z), h3 = __float2bfloat16(v.w);
    __nv_bfloat162* H = (__nv_bfloat162*)hi;
    __nv_bfloat162* L = (__nv_bfloat162*)lo;
    H[i*2]   = __halves2bfloat162(h0, h1);
    H[i*2+1] = __halves2bfloat162(h2, h3);
    L[i*2]   = __halves2bfloat162(
        __float2bfloat16(v.x - __bfloat162float(h0)),
        __float2bfloat16(v.y - __bfloat162float(h1)));
    L[i*2+1] = __halves2bfloat162(
        __float2bfloat16(v.z - __bfloat162float(h2)),
        __float2bfloat16(v.w - __bfloat162float(h3)));
}

// ---------------- batched weight transpose + split: ALL layers/matrices in one launch ----
// Tile: 64 k x 32 n. W[K][N] -> hi/lo[N][K]. blockIdx.z = layer.
__global__ __launch_bounds__(256) void wtrans_all(
    const float* __restrict__ Wq, const float* __restrict__ Wk,
    const float* __restrict__ Wv, const float* __restrict__ Wao,
    const float* __restrict__ Wi, const float* __restrict__ Wfo,
    __nv_bfloat16* __restrict__ wh, __nv_bfloat16* __restrict__ wl)
{
    __shared__ float t[64][33];
    const int tid = threadIdx.x;
    const int l = blockIdx.z;
    int x = blockIdx.x;

    const float* W; int K_, N_; size_t off;
    if (x < 1152) {
        int m = x / 288; x -= m * 288;
        K_ = HH; N_ = HH;
        W = (m == 0 ? Wq : m == 1 ? Wk : m == 2 ? Wv : Wao) + (size_t)l * HH * HH;
        off = (m == 0 ? WQOFF : m == 1 ? WKOFF : m == 2 ? WVOFF : WAOOFF);
    } else if (x < 2304) {
        x -= 1152; K_ = HH; N_ = FF;
        W = Wi + (size_t)l * HH * FF; off = WIOFF;
    } else {
        x -= 2304; K_ = FF; N_ = HH;
        W = Wfo + (size_t)l * FF * HH; off = WFOOFF;
    }
    const int ntn = N_ >> 5;
    const int k0 = (x / ntn) << 6, n0 = (x % ntn) << 5;

    // load 64x32 floats, coalesced along n
    {
        int r = tid >> 5, c = tid & 31;
        #pragma unroll
        for (int i = 0; i < 8; i++)
            t[r + i*8][c] = W[(size_t)(k0 + r + i*8) * N_ + n0 + c];
    }
    __syncthreads();

    // write out: 512 items (32 n x 16 k-quads), 2 per thread; 8B vectorized stores
    __nv_bfloat16* hi = wh + (size_t)l * LSTRIDE + off;
    __nv_bfloat16* lo = wl + (size_t)l * LSTRIDE + off;
    #pragma unroll
    for (int it = 0; it < 2; it++) {
        int idx = tid + it * 256;
        int nl = idx >> 4, kq = idx & 15;
        float v0 = t[kq*4+0][nl], v1 = t[kq*4+1][nl];
        float v2 = t[kq*4+2][nl], v3 = t[kq*4+3][nl];
        __nv_bfloat16 h0 = __float2bfloat16(v0), h1 = __float2bfloat16(v1);
        __nv_bfloat16 h2 = __float2bfloat16(v2), h3 = __float2bfloat16(v3);
        uint2 hv, lv;
        hv.x = pack_bf2(h0, h1); hv.y = pack_bf2(h2, h3);
        lv.x = pack_bf2(__float2bfloat16(v0 - __bfloat162float(h0)),
                        __float2bfloat16(v1 - __bfloat162float(h1)));
        lv.y = pack_bf2(__float2bfloat16(v2 - __bfloat162float(h2)),
                        __float2bfloat16(v3 - __bfloat162float(h3)));
        size_t base = (size_t)(n0 + nl) * K_ + k0 + kq*4;
        *(uint2*)(hi + base) = hv;
        *(uint2*)(lo + base) = lv;
    }
}

// ---------------- LayerNorm with optional bf16 hi/lo dual output ----------------
__global__ __launch_bounds__(256) void ln_kernel(
    const float* __restrict__ x, const float* __restrict__ g,
    const float* __restrict__ b, float* __restrict__ out,
    __nv_bfloat16* __restrict__ oh, __nv_bfloat16* __restrict__ ol)
{
    const int row = blockIdx.x;
    const int tid = threadIdx.x;
    const float* xr = x + (long)row * HH;
    float v0 = xr[tid], v1 = xr[tid + 256], v2 = xr[tid + 512];

    __shared__ float red[8];
    float s = v0 + v1 + v2;
    #pragma unroll
    for (int o2 = 16; o2; o2 >>= 1) s += __shfl_xor_sync(0xffffffffu, s, o2);
    if ((tid & 31) == 0) red[tid >> 5] = s;
    __syncthreads();
    float tot = 0.f;
    #pragma unroll
    for (int i = 0; i < 8; i++) tot += red[i];
    float mean = tot * (1.0f / 768.0f);

    float d0 = v0 - mean, d1 = v1 - mean, d2 = v2 - mean;
    float sq = d0*d0 + d1*d1 + d2*d2;
    __syncthreads();
    #pragma unroll
    for (int o2 = 16; o2; o2 >>= 1) sq += __shfl_xor_sync(0xffffffffu, sq, o2);
    if ((tid & 31) == 0) red[tid >> 5] = sq;
    __syncthreads();
    float tot2 = 0.f;
    #pragma unroll
    for (int i = 0; i < 8; i++) tot2 += red[i];
    float rstd = rsqrtf(tot2 * (1.0f / 768.0f) + 1e-12f);

    float* orow = out + (long)row * HH;
    float r0 = d0 * rstd * g[tid]       + b[tid];
    float r1 = d1 * rstd * g[tid + 256] + b[tid + 256];
    float r2 = d2 * rstd * g[tid + 512] + b[tid + 512];
    orow[tid] = r0; orow[tid + 256] = r1; orow[tid + 512] = r2;
    if (oh) {
        size_t base = (size_t)row * HH;
        __nv_bfloat16 h0 = __float2bfloat16(r0);
        __nv_bfloat16 h1 = __float2bfloat16(r1);
        __nv_bfloat16 h2 = __float2bfloat16(r2);
        oh[base + tid] = h0;       ol[base + tid]       = __float2bfloat16(r0 - __bfloat162float(h0));
        oh[base + tid + 256] = h1; ol[base + tid + 256] = __float2bfloat16(r1 - __bfloat162float(h1));
        oh[base + tid + 512] = h2; ol[base + tid + 512] = __float2bfloat16(r2 - __bfloat162float(h2));
    }
}

// ---------------- launch ----------------
extern "C" void kernel_launch(void* const* d_in, const int* in_sizes, int n_in,
                              void* d_out, int out_size)
{
    const float* x    = (const float*)d_in[0];
    const int*   mask = (const int*)  d_in[1];
    const float* Wq   = (const float*)d_in[2];
    const float* bq   = (const float*)d_in[3];
    const float* Wk   = (const float*)d_in[4];
    const float* bk   = (const float*)d_in[5];
    const float* Wv   = (const float*)d_in[6];
    const float* bv   = (const float*)d_in[7];
    const float* Wao  = (const float*)d_in[8];
    const float* bao  = (const float*)d_in[9];
    const float* g1   = (const float*)d_in[10];
    const float* b1   = (const float*)d_in[11];
    const float* Wi   = (const float*)d_in[12];
    const float* bi   = (const float*)d_in[13];
    const float* Wfo  = (const float*)d_in[14];
    const float* bfo  = (const float*)d_in[15];
    const float* g2   = (const float*)d_in[16];
    const float* b2   = (const float*)d_in[17];

    float *h_, *tmp_, *attn_, *p0_, *p1_, *p2_;
    __nv_bfloat16 *hh_, *hl_, *qh_, *ql_, *kh_, *kl_, *vh_, *vl_;
    __nv_bfloat16 *vth_, *vtl_, *cth_, *ctl_, *aah_, *aal_, *ih_, *il_, *wh_, *wl_;
    cudaGetSymbolAddress((void**)&h_,    g_h);
    cudaGetSymbolAddress((void**)&tmp_,  g_tmp);
    cudaGetSymbolAddress((void**)&attn_, g_attn);
    cudaGetSymbolAddress((void**)&p0_,   g_p0);
    cudaGetSymbolAddress((void**)&p1_,   g_p1);
    cudaGetSymbolAddress((void**)&p2_,   g_p2);
    cudaGetSymbolAddress((void**)&hh_,   g_hh);
    cudaGetSymbolAddress((void**)&hl_,   g_hl);
    cudaGetSymbolAddress((void**)&qh_,   g_qh);
    cudaGetSymbolAddress((void**)&ql_,   g_ql);
    cudaGetSymbolAddress((void**)&kh_,   g_kh);
    cudaGetSymbolAddress((void**)&kl_,   g_kl);
    cudaGetSymbolAddress((void**)&vh_,   g_vh);
    cudaGetSymbolAddress((void**)&vl_,   g_vl);
    cudaGetSymbolAddress((void**)&vth_,  g_vth);
    cudaGetSymbolAddress((void**)&vtl_,  g_vtl);
    cudaGetSymbolAddress((void**)&cth_,  g_cth);
    cudaGetSymbolAddress((void**)&ctl_,  g_ctl);
    cudaGetSymbolAddress((void**)&aah_,  g_aah);
    cudaGetSymbolAddress((void**)&aal_,  g_aal);
    cudaGetSymbolAddress((void**)&ih_,   g_ih);
    cudaGetSymbolAddress((void**)&il_,   g_il);
    cudaGetSymbolAddress((void**)&wh_,   g_wh);
    cudaGetSymbolAddress((void**)&wl_,   g_wl);

    cudaFuncSetAttribute(gemm_tc,
                         cudaFuncAttributeMaxDynamicSharedMemorySize, GEMM_SMEM);
    cudaFuncSetAttribute(flashattn,
                         cudaFuncAttributeMaxDynamicSharedMemorySize, FSMEM);

    const int M = BB * SS;  // 2048
    const int n4 = M * HH / 4;

    // ---- weight prep: one batched launch ----
    wtrans_all<<<dim3(3456, 1, NL), 256>>>(Wq, Wk, Wv, Wao, Wi, Wfo, wh_, wl_);
    split_kernel<<<(n4 + 255)/256, 256>>>(x, hh_, hl_, n4);

    for (int l = 0; l < NL; l++) {
        const float* hin = (l == 0) ? x : h_;
        size_t lo = (size_t)l * LSTRIDE;

        // QKV -> bf16 hi/lo outputs
        {
            GemmArgs a = {};
            a.ah = hh_; a.al = hl_;
            a.bh0 = wh_+lo+WQOFF; a.bh1 = wh_+lo+WKOFF; a.bh2 = wh_+lo+WVOFF;
            a.bl0 = wl_+lo+WQOFF; a.bl1 = wl_+lo+WKOFF; a.bl2 = wl_+lo+WVOFF;
            a.bias0 = bq + l*HH; a.bias1 = bk + l*HH; a.bias2 = bv + l*HH;
            a.ch0 = qh_; a.cl0 = ql_; a.ch1 = kh_; a.cl1 = kl_; a.ch2 = vh_; a.cl2 = vl_;
            a.K = HH; a.N = HH; a.gelu = 0; a.outbf = 1; a.Kld = HH; a.ksplit = 0;
            gemm_tc<<<dim3(HH/128, M/128, 3), 512, GEMM_SMEM>>>(a);
        }

        vtrans_kernel<<<dim3(SS/32, BB*NH*2), dim3(32,8)>>>(vh_, vl_, vth_, vtl_);
        flashattn<<<dim3(SS/64, BB*NH), 128, FSMEM>>>(qh_, ql_, kh_, kl_, vth_, vtl_,
                                                      mask, cth_, ctl_);

        // AO proj: split-K=3 (256 each) -> partials -> reduce(+bias+resid)
        {
            GemmArgs a = {};
            a.ah = cth_; a.al = ctl_;
            a.bh0 = wh_+lo+WAOOFF; a.bh1 = a.bh0; a.bh2 = a.bh0;
            a.bl0 = wl_+lo+WAOOFF; a.bl1 = a.bl0; a.bl2 = a.bl0;
            a.c0 = p0_; a.c1 = p1_; a.c2 = p2_;
            a.K = 256; a.N = HH; a.gelu = 0; a.outbf = 0; a.Kld = HH; a.ksplit = 1;
            gemm_tc<<<dim3(HH/128, M/128, 3), 512, GEMM_SMEM>>>(a);
        }
        reduce3<<<n4/256, 256>>>((const float4*)p0_, (const float4*)p1_, (const float4*)p2_,
                                 bao + l*HH, (const float4*)hin, (float4*)tmp_);
        ln_kernel<<<M, 256>>>(tmp_, g1 + l*HH, b1 + l*HH, attn_, aah_, aal_);

        // FFN1 (gelu) -> bf16 hi/lo
        {
            GemmArgs a = {};
            a.ah = aah_; a.al = aal_;
            a.bh0 = wh_+lo+WIOFF; a.bh1 = a.bh0; a.bh2 = a.bh0;
            a.bl0 = wl_+lo+WIOFF; a.bl1 = a.bl0; a.bl2 = a.bl0;
            a.bias0 = bi + l*FF; a.bias1 = a.bias0; a.bias2 = a.bias0;
            a.ch0 = ih_; a.cl0 = il_; a.ch1 = ih_; a.cl1 = il_; a.ch2 = ih_; a.cl2 = il_;
            a.K = HH; a.N = FF; a.gelu = 1; a.outbf = 1; a.Kld = HH; a.ksplit = 0;
            gemm_tc<<<dim3(FF/128, M/128, 1), 512, GEMM_SMEM>>>(a);
        }

        // FFN2: split-K=3 (1024 each) -> partials -> reduce(+bias+resid)
        {
            GemmArgs a = {};
            a.ah = ih_; a.al = il_;
            a.bh0 = wh_+lo+WFOOFF; a.bh1 = a.bh0; a.bh2 = a.bh0;
            a.bl0 = wl_+lo+WFOOFF; a.bl1 = a.bl0; a.bl2 = a.bl0;
            a.c0 = p0_; a.c1 = p1_; a.c2 = p2_;
            a.K = 1024; a.N = HH; a.gelu = 0; a.outbf = 0; a.Kld = FF; a.ksplit = 1;
            gemm_tc<<<dim3(HH/128, M/128, 3), 512, GEMM_SMEM>>>(a);
        }
        reduce3<<<n4/256, 256>>>((const float4*)p0_, (const float4*)p1_, (const float4*)p2_,
                                 bfo + l*HH, (const float4*)attn_, (float4*)tmp_);

        if (l == NL - 1) {
            ln_kernel<<<M, 256>>>(tmp_, g2 + l*HH, b2 + l*HH, (float*)d_out,
                                  (__nv_bfloat16*)nullptr, (__nv_bfloat16*)nullptr);
        } else {
            ln_kernel<<<M, 256>>>(tmp_, g2 + l*HH, b2 + l*HH, h_, hh_, hl_);
        }
    }
}

// round 7
// speedup vs baseline: 3.1296x; 1.0581x over previous
#include <cuda_runtime.h>
#include <cuda_bf16.h>
#include <math.h>
#include <stdint.h>

#define BB 2
#define SS 1024
#define HH 768
#define NH 12
#define DH 64
#define FF 3072
#define NL 4

// ---------------- scratch (device globals; no allocation allowed) ----------------
__device__ float g_h[BB*SS*HH];
__device__ float g_attn[BB*SS*HH];
__device__ float g_p0[BB*SS*HH];
__device__ float g_p1[BB*SS*HH];
__device__ float g_p2[BB*SS*HH];

__device__ __nv_bfloat16 g_hh[BB*SS*HH], g_hl[BB*SS*HH];
__device__ __nv_bfloat16 g_qh[BB*SS*HH], g_ql[BB*SS*HH];
__device__ __nv_bfloat16 g_kh[BB*SS*HH], g_kl[BB*SS*HH];
__device__ __nv_bfloat16 g_vh[BB*SS*HH], g_vl[BB*SS*HH];
__device__ __nv_bfloat16 g_vth[BB*SS*HH], g_vtl[BB*SS*HH];
__device__ __nv_bfloat16 g_cth[BB*SS*HH], g_ctl[BB*SS*HH];
__device__ __nv_bfloat16 g_aah[BB*SS*HH], g_aal[BB*SS*HH];
__device__ __nv_bfloat16 g_ih[BB*SS*FF], g_il[BB*SS*FF];

// transposed+split weights per layer: [wq wk wv wao wi wfo], each [N][K] row-major
#define WQOFF  0
#define WKOFF  589824
#define WVOFF  1179648
#define WAOOFF 1769472
#define WIOFF  2359296
#define WFOOFF 4718592
#define LSTRIDE 7077888
__device__ __nv_bfloat16 g_wh[(size_t)NL*LSTRIDE];
__device__ __nv_bfloat16 g_wl[(size_t)NL*LSTRIDE];

// ---------------- PTX helpers (arch-neutral: ldmatrix / mma.sync / cp.async) ----------------
__device__ __forceinline__ uint32_t smem_u32(const void* p) {
    uint32_t a;
    asm("{ .reg .u64 t; cvta.to.shared.u64 t, %1; cvt.u32.u64 %0, t; }" : "=r"(a) : "l"(p));
    return a;
}
__device__ __forceinline__ void cpa16(uint32_t dst, const void* src) {
    asm volatile("cp.async.cg.shared.global [%0], [%1], 16;" :: "r"(dst), "l"(src));
}
#define CP_COMMIT() asm volatile("cp.async.commit_group;" ::: "memory")

__device__ __forceinline__ void ldsm4(uint32_t* r, uint32_t a) {
    asm volatile("ldmatrix.sync.aligned.m8n8.x4.shared.b16 {%0,%1,%2,%3}, [%4];"
        : "=r"(r[0]), "=r"(r[1]), "=r"(r[2]), "=r"(r[3]) : "r"(a));
}
__device__ __forceinline__ void mma16816(float* c, const uint32_t* a, const uint32_t* b) {
    asm volatile("mma.sync.aligned.m16n8k16.row.col.f32.bf16.bf16.f32 "
        "{%0,%1,%2,%3}, {%4,%5,%6,%7}, {%8,%9}, {%0,%1,%2,%3};"
        : "+f"(c[0]), "+f"(c[1]), "+f"(c[2]), "+f"(c[3])
        : "r"(a[0]), "r"(a[1]), "r"(a[2]), "r"(a[3]), "r"(b[0]), "r"(b[1]));
}
__device__ __forceinline__ uint32_t pack_bf2(__nv_bfloat16 a, __nv_bfloat16 b) {
    __nv_bfloat162 t = __halves2bfloat162(a, b);
    return *(uint32_t*)&t;
}

// ---------------- bf16x3 HMMA GEMM: C = A @ B^T (+bias)(+resid)(gelu), fp32/bf16-split out,
// optional split-K (z = K-slice) ----
struct GemmArgs {
    const __nv_bfloat16 *ah, *al;
    const __nv_bfloat16 *bh0, *bh1, *bh2, *bl0, *bl1, *bl2;
    const float *bias0, *bias1, *bias2;
    const float *resid;
    float *c0, *c1, *c2;
    __nv_bfloat16 *ch0, *cl0, *ch1, *cl1, *ch2, *cl2;
    int K, N, gelu, outbf, Kld, ksplit;
};

#define ABUF 10240            // 128 rows * 80B (64B data + 16B pad)
#define STGB (4*ABUF)         // Ah, Al, Bh, Bl
#define NSTG 3
#define GEMM_SMEM (NSTG*STGB) // 122880

__global__ __launch_bounds__(512) void gemm_tc(GemmArgs g) {
    extern __shared__ char smem[];
    const uint32_t su = smem_u32(smem);
    const int tid = threadIdx.x;
    const int lane = tid & 31, warp = tid >> 5;
    const int warpM = warp & 3, warpN = warp >> 2;
    const int m0 = blockIdx.y << 7, n0 = blockIdx.x << 7;

    const __nv_bfloat16 *bh, *bl; const float* bias; float* C;
    __nv_bfloat16 *CH, *CL;
    if (blockIdx.z == 0)      { bh=g.bh0; bl=g.bl0; bias=g.bias0; C=g.c0; CH=g.ch0; CL=g.cl0; }
    else if (blockIdx.z == 1) { bh=g.bh1; bl=g.bl1; bias=g.bias1; C=g.c1; CH=g.ch1; CL=g.cl1; }
    else                      { bh=g.bh2; bl=g.bl2; bias=g.bias2; C=g.c2; CH=g.ch2; CL=g.cl2; }
    const int K = g.K, N = g.N, nk = K >> 5;
    const int kbase = g.ksplit ? (int)blockIdx.z * K : 0;

    const int ldg_row = tid >> 2, ldg_c = tid & 3;
    const size_t ldab = (size_t)g.Kld * 2;
    const char* pAh = (const char*)g.ah + ((size_t)(m0 + ldg_row)) * ldab + (size_t)kbase*2 + ldg_c * 16;
    const char* pAl = (const char*)g.al + ((size_t)(m0 + ldg_row)) * ldab + (size_t)kbase*2 + ldg_c * 16;
    const char* pBh = (const char*)bh   + ((size_t)(n0 + ldg_row)) * ldab + (size_t)kbase*2 + ldg_c * 16;
    const char* pBl = (const char*)bl   + ((size_t)(n0 + ldg_row)) * ldab + (size_t)kbase*2 + ldg_c * 16;
    const uint32_t sdst = ldg_row * 80 + ldg_c * 16;

    auto load_chunk = [&](int j, int s) {
        uint32_t sb = su + s * STGB + sdst;
        size_t go = (size_t)j * 64;
        cpa16(sb,            pAh + go);
        cpa16(sb +   ABUF,   pAl + go);
        cpa16(sb + 2*ABUF,   pBh + go);
        cpa16(sb + 3*ABUF,   pBl + go);
    };

    load_chunk(0, 0); CP_COMMIT();
    load_chunk(1, 1); CP_COMMIT();

    float acc[2][4][4];
    #pragma unroll
    for (int i = 0; i < 2; i++)
        #pragma unroll
        for (int j = 0; j < 4; j++)
            #pragma unroll
            for (int r = 0; r < 4; r++) acc[i][j][r] = 0.f;

    const uint32_t a_off = (uint32_t)(warpM*32 + (lane & 15)) * 80 + (lane >> 4) * 16;
    const uint32_t b_off = (uint32_t)(warpN*32 + (((lane >> 4) & 1) << 3) + (lane & 7)) * 80
                         + ((lane >> 3) & 1) * 16;

    for (int i = 0; i < nk; i++) {
        asm volatile("cp.async.wait_group 1;" ::: "memory");
        __syncthreads();
        int j = i + 2;
        if (j < nk) load_chunk(j, j % NSTG);
        CP_COMMIT();

        uint32_t base = su + (i % NSTG) * STGB;
        #pragma unroll
        for (int ks = 0; ks < 2; ks++) {
            uint32_t ko = ks * 32;
            uint32_t ah0[4], ah1[4], al0[4], al1[4];
            uint32_t bhf0[4], bhf1[4], blf0[4], blf1[4];
            ldsm4(ah0, base + a_off + ko);
            ldsm4(ah1, base + a_off + 16*80 + ko);
            ldsm4(al0, base + ABUF + a_off + ko);
            ldsm4(al1, base + ABUF + a_off + 16*80 + ko);
            ldsm4(bhf0, base + 2*ABUF + b_off + ko);
            ldsm4(bhf1, base + 2*ABUF + b_off + 16*80 + ko);
            ldsm4(blf0, base + 3*ABUF + b_off + ko);
            ldsm4(blf1, base + 3*ABUF + b_off + 16*80 + ko);
            uint32_t* AH[2] = {ah0, ah1};
            uint32_t* AL[2] = {al0, al1};
            #pragma unroll
            for (int mt = 0; mt < 2; mt++) {
                mma16816(acc[mt][0], AH[mt], bhf0);
                mma16816(acc[mt][0], AH[mt], blf0);
                mma16816(acc[mt][0], AL[mt], bhf0);
                mma16816(acc[mt][1], AH[mt], bhf0+2);
                mma16816(acc[mt][1], AH[mt], blf0+2);
                mma16816(acc[mt][1], AL[mt], bhf0+2);
                mma16816(acc[mt][2], AH[mt], bhf1);
                mma16816(acc[mt][2], AH[mt], blf1);
                mma16816(acc[mt][2], AL[mt], bhf1);
                mma16816(acc[mt][3], AH[mt], bhf1+2);
                mma16816(acc[mt][3], AH[mt], blf1+2);
                mma16816(acc[mt][3], AL[mt], bhf1+2);
            }
        }
    }

    const int erow = m0 + warpM*32 + (lane >> 2);
    const int ecol = n0 + warpN*32 + (lane & 3)*2;
    #pragma unroll
    for (int mt = 0; mt < 2; mt++) {
        #pragma unroll
        for (int nt = 0; nt < 4; nt++) {
            int c = ecol + nt*8;
            float b0 = bias ? bias[c] : 0.f, b1 = bias ? bias[c+1] : 0.f;
            #pragma unroll
            for (int half = 0; half < 2; half++) {
                int r = erow + mt*16 + half*8;
                float o0 = acc[mt][nt][half*2+0] + b0;
                float o1 = acc[mt][nt][half*2+1] + b1;
                if (g.resid) {
                    float2 rv = *(const float2*)(g.resid + (size_t)r * N + c);
                    o0 += rv.x; o1 += rv.y;
                }
                if (g.gelu) {
                    o0 = 0.5f * o0 * (1.0f + erff(o0 * 0.70710678118654752f));
                    o1 = 0.5f * o1 * (1.0f + erff(o1 * 0.70710678118654752f));
                }
                if (g.outbf) {
                    __nv_bfloat16 h0 = __float2bfloat16(o0), h1 = __float2bfloat16(o1);
                    __nv_bfloat16 l0 = __float2bfloat16(o0 - __bfloat162float(h0));
                    __nv_bfloat16 l1 = __float2bfloat16(o1 - __bfloat162float(h1));
                    *(uint32_t*)(CH + (size_t)r * N + c) = pack_bf2(h0, h1);
                    *(uint32_t*)(CL + (size_t)r * N + c) = pack_bf2(l0, l1);
                } else {
                    float2 ov; ov.x = o0; ov.y = o1;
                    *(float2*)(C + (size_t)r * N + c) = ov;
                }
            }
        }
    }
}

// ---------------- fused split-K reduce + LayerNorm (+ optional bf16 hi/lo out) ----------------
__global__ __launch_bounds__(256) void reduce_ln(
    const float* __restrict__ p0, const float* __restrict__ p1,
    const float* __restrict__ p2, const float* __restrict__ bias,
    const float* __restrict__ resid,
    const float* __restrict__ g, const float* __restrict__ b,
    float* __restrict__ out,
    __nv_bfloat16* __restrict__ oh, __nv_bfloat16* __restrict__ ol)
{
    const int row = blockIdx.x;
    const int tid = threadIdx.x;
    const size_t base = (size_t)row * HH;

    float v0, v1, v2;
    {
        int i0 = tid, i1 = tid + 256, i2 = tid + 512;
        v0 = p0[base+i0] + p1[base+i0] + p2[base+i0] + bias[i0] + resid[base+i0];
        v1 = p0[base+i1] + p1[base+i1] + p2[base+i1] + bias[i1] + resid[base+i1];
        v2 = p0[base+i2] + p1[base+i2] + p2[base+i2] + bias[i2] + resid[base+i2];
    }

    __shared__ float red[8];
    float s = v0 + v1 + v2;
    #pragma unroll
    for (int o2 = 16; o2; o2 >>= 1) s += __shfl_xor_sync(0xffffffffu, s, o2);
    if ((tid & 31) == 0) red[tid >> 5] = s;
    __syncthreads();
    float tot = 0.f;
    #pragma unroll
    for (int i = 0; i < 8; i++) tot += red[i];
    float mean = tot * (1.0f / 768.0f);

    float d0 = v0 - mean, d1 = v1 - mean, d2 = v2 - mean;
    float sq = d0*d0 + d1*d1 + d2*d2;
    __syncthreads();
    #pragma unroll
    for (int o2 = 16; o2; o2 >>= 1) sq += __shfl_xor_sync(0xffffffffu, sq, o2);
    if ((tid & 31) == 0) red[tid >> 5] = sq;
    __syncthreads();
    float tot2 = 0.f;
    #pragma unroll
    for (int i = 0; i < 8; i++) tot2 += red[i];
    float rstd = rsqrtf(tot2 * (1.0f / 768.0f) + 1e-12f);

    float r0 = d0 * rstd * g[tid]       + b[tid];
    float r1 = d1 * rstd * g[tid + 256] + b[tid + 256];
    float r2 = d2 * rstd * g[tid + 512] + b[tid + 512];
    out[base + tid] = r0; out[base + tid + 256] = r1; out[base + tid + 512] = r2;
    if (oh) {
        __nv_bfloat16 h0 = __float2bfloat16(r0);
        __nv_bfloat16 h1 = __float2bfloat16(r1);
        __nv_bfloat16 h2 = __float2bfloat16(r2);
        oh[base + tid] = h0;       ol[base + tid]       = __float2bfloat16(r0 - __bfloat162float(h0));
        oh[base + tid + 256] = h1; ol[base + tid + 256] = __float2bfloat16(r1 - __bfloat162float(h1));
        oh[base + tid + 512] = h2; ol[base + tid + 512] = __float2bfloat16(r2 - __bfloat162float(h2));
    }
}

// ---------------- flash attention: K-tile 32, 3-stage pipeline, 3 CTAs/SM ----------------
// Q-tile 64, 128 threads (4 warps x 16 q rows). V pre-transposed: vt[bh][dh][S].
#define QROW 144
#define FQBUF 9216            // 64*144
#define KROW 144
#define VROW 80
#define KSZ  4608             // 32*144
#define VSZ  5120             // 64*80
#define FSTG2 (2*KSZ + 2*VSZ) // 19456
#define FNSTG 3
#define FSMEM (2*FQBUF + FNSTG*FSTG2)  // 76800

__global__ __launch_bounds__(128, 3) void flashattn(
    const __nv_bfloat16* __restrict__ qh, const __nv_bfloat16* __restrict__ ql,
    const __nv_bfloat16* __restrict__ kh, const __nv_bfloat16* __restrict__ kl,
    const __nv_bfloat16* __restrict__ vth, const __nv_bfloat16* __restrict__ vtl,
    const int* __restrict__ mask,
    __nv_bfloat16* __restrict__ cth, __nv_bfloat16* __restrict__ ctl)
{
    extern __shared__ char smem[];
    const uint32_t su = smem_u32(smem);
    const int tid = threadIdx.x, lane = tid & 31, warp = tid >> 5;
    const int q0 = blockIdx.x * 64, bh = blockIdx.y;
    const int b = bh / NH, h = bh % NH;
    const int wr = warp * 16;

    const char* Qh = (const char*)(qh + ((size_t)b*SS + q0)*HH + h*DH);
    const char* Ql = (const char*)(ql + ((size_t)b*SS + q0)*HH + h*DH);
    const char* Kh = (const char*)(kh + ((size_t)b*SS)*HH + h*DH);
    const char* Kl = (const char*)(kl + ((size_t)b*SS)*HH + h*DH);
    const char* Vh = (const char*)(vth + (size_t)bh*DH*SS);
    const char* Vl = (const char*)(vtl + (size_t)bh*DH*SS);

    // Q: 64 rows x 128B per buffer
    #pragma unroll
    for (int c = 0; c < 4; c++) {
        int idx = tid + c*128;
        int row = idx >> 3, chn = idx & 7;
        uint32_t dst = su + row*QROW + chn*16;
        size_t so = (size_t)row*1536 + chn*16;
        cpa16(dst,         Qh + so);
        cpa16(dst + FQBUF, Ql + so);
    }
    CP_COMMIT();

    auto load_kv = [&](int j, int s) {
        uint32_t sb = su + 2*FQBUF + s*FSTG2;
        int k0 = j * 32;
        #pragma unroll
        for (int c = 0; c < 2; c++) {
            int idx = tid + c*128;
            int krow = idx >> 3, kchn = idx & 7;      // K: 32 rows x 128B
            uint32_t kdst = sb + krow*KROW + kchn*16;
            size_t ko = (size_t)(k0 + krow)*1536 + kchn*16;
            cpa16(kdst,       Kh + ko);
            cpa16(kdst + KSZ, Kl + ko);
            int vrow = idx >> 2, vchn = idx & 3;      // V: 64 rows x 64B
            uint32_t vdst = sb + 2*KSZ + vrow*VROW + vchn*16;
            size_t vo = (size_t)vrow*2048 + (size_t)k0*2 + vchn*16;
            cpa16(vdst,       Vh + vo);
            cpa16(vdst + VSZ, Vl + vo);
        }
    };
    load_kv(0, 0); CP_COMMIT();
    load_kv(1, 1); CP_COMMIT();

    asm volatile("cp.async.wait_group 2;" ::: "memory");
    __syncthreads();

    // Q fragments (kept in regs whole kernel)
    uint32_t qhf[4][4], qlf[4][4];
    {
        uint32_t abase = su + (uint32_t)(wr + (lane & 15))*QROW + (lane >> 4)*16;
        #pragma unroll
        for (int kc = 0; kc < 4; kc++) {
            ldsm4(qhf[kc], abase + kc*32);
            ldsm4(qlf[kc], abase + FQBUF + kc*32);
        }
    }

    float o[8][4];
    #pragma unroll
    for (int j = 0; j < 8; j++)
        #pragma unroll
        for (int r = 0; r < 4; r++) o[j][r] = 0.f;
    float m0 = -1e30f, m1 = -1e30f, l0 = 0.f, l1 = 0.f;

    const int r = lane >> 2;
    const int colb = (lane & 3) * 2;
    const int* mrow0 = mask + ((size_t)b*SS + (q0 + wr + r))*SS;
    const int* mrow8 = mrow0 + 8*SS;
    const uint32_t rowsel = (uint32_t)((((lane >> 4) & 1) << 3) + (lane & 7));
    const uint32_t bKoff = rowsel*KROW + ((lane >> 3) & 1)*16;
    const uint32_t bVoff = rowsel*VROW + ((lane >> 3) & 1)*16;

    for (int i = 0; i < 32; i++) {
        asm volatile("cp.async.wait_group 1;" ::: "memory");
        __syncthreads();
        // early prefetch of stage i+2 (overwrites stage consumed at iter i-1)
        if (i + 2 < 32) load_kv(i + 2, (i + 2) % 3);
        CP_COMMIT();

        const uint32_t sb = su + 2*FQBUF + (i % 3)*FSTG2;
        const int k0 = i * 32;

        // ---- S = Q K^T (x3): 64 q x 32 s ----
        float sc_[4][4];
        #pragma unroll
        for (int j = 0; j < 4; j++)
            #pragma unroll
            for (int t = 0; t < 4; t++) sc_[j][t] = 0.f;
        #pragma unroll
        for (int nt = 0; nt < 2; nt++) {
            #pragma unroll
            for (int kc = 0; kc < 4; kc++) {
                uint32_t fh[4], fl[4];
                ldsm4(fh, sb + nt*16*KROW + bKoff + kc*32);
                ldsm4(fl, sb + KSZ + nt*16*KROW + bKoff + kc*32);
                mma16816(sc_[2*nt],   qhf[kc], fh);
                mma16816(sc_[2*nt],   qhf[kc], fl);
                mma16816(sc_[2*nt],   qlf[kc], fh);
                mma16816(sc_[2*nt+1], qhf[kc], fh+2);
                mma16816(sc_[2*nt+1], qhf[kc], fl+2);
                mma16816(sc_[2*nt+1], qlf[kc], fh+2);
            }
        }
        // ---- mask + scale ----
        #pragma unroll
        for (int j = 0; j < 4; j++) {
            int kc2 = k0 + j*8 + colb;
            int2 ma = *(const int2*)(mrow0 + kc2);
            int2 mb = *(const int2*)(mrow8 + kc2);
            sc_[j][0] = sc_[j][0]*0.125f + (1.f - (float)ma.x)*(-10000.f);
            sc_[j][1] = sc_[j][1]*0.125f + (1.f - (float)ma.y)*(-10000.f);
            sc_[j][2] = sc_[j][2]*0.125f + (1.f - (float)mb.x)*(-10000.f);
            sc_[j][3] = sc_[j][3]*0.125f + (1.f - (float)mb.y)*(-10000.f);
        }
        // ---- online softmax ----
        float mx0 = -1e30f, mx1 = -1e30f;
        #pragma unroll
        for (int j = 0; j < 4; j++) {
            mx0 = fmaxf(mx0, fmaxf(sc_[j][0], sc_[j][1]));
            mx1 = fmaxf(mx1, fmaxf(sc_[j][2], sc_[j][3]));
        }
        mx0 = fmaxf(mx0, __shfl_xor_sync(0xffffffffu, mx0, 1));
        mx0 = fmaxf(mx0, __shfl_xor_sync(0xffffffffu, mx0, 2));
        mx1 = fmaxf(mx1, __shfl_xor_sync(0xffffffffu, mx1, 1));
        mx1 = fmaxf(mx1, __shfl_xor_sync(0xffffffffu, mx1, 2));
        float mn0 = fmaxf(m0, mx0), mn1 = fmaxf(m1, mx1);
        float sf0 = __expf(m0 - mn0), sf1 = __expf(m1 - mn1);
        m0 = mn0; m1 = mn1;
        float rs0 = 0.f, rs1 = 0.f;
        #pragma unroll
        for (int j = 0; j < 4; j++) {
            sc_[j][0] = __expf(sc_[j][0] - mn0);
            sc_[j][1] = __expf(sc_[j][1] - mn0);
            sc_[j][2] = __expf(sc_[j][2] - mn1);
            sc_[j][3] = __expf(sc_[j][3] - mn1);
            rs0 += sc_[j][0] + sc_[j][1];
            rs1 += sc_[j][2] + sc_[j][3];
        }
        rs0 += __shfl_xor_sync(0xffffffffu, rs0, 1);
        rs0 += __shfl_xor_sync(0xffffffffu, rs0, 2);
        rs1 += __shfl_xor_sync(0xffffffffu, rs1, 1);
        rs1 += __shfl_xor_sync(0xffffffffu, rs1, 2);
        l0 = l0*sf0 + rs0;
        l1 = l1*sf1 + rs1;
        #pragma unroll
        for (int j = 0; j < 8; j++) {
            o[j][0] *= sf0; o[j][1] *= sf0; o[j][2] *= sf1; o[j][3] *= sf1;
        }
        // ---- P -> bf16 hi/lo A-fragments (2 k16 chunks) ----
        uint32_t phf[2][4], plf[2][4];
        #pragma unroll
        for (int kc = 0; kc < 2; kc++) {
            #pragma unroll
            for (int half = 0; half < 2; half++) {
                int j = 2*kc + half;
                __nv_bfloat16 h0 = __float2bfloat16(sc_[j][0]);
                __nv_bfloat16 h1 = __float2bfloat16(sc_[j][1]);
                __nv_bfloat16 h2 = __float2bfloat16(sc_[j][2]);
                __nv_bfloat16 h3 = __float2bfloat16(sc_[j][3]);
                phf[kc][half*2+0] = pack_bf2(h0, h1);
                phf[kc][half*2+1] = pack_bf2(h2, h3);
                plf[kc][half*2+0] = pack_bf2(
                    __float2bfloat16(sc_[j][0] - __bfloat162float(h0)),
                    __float2bfloat16(sc_[j][1] - __bfloat162float(h1)));
                plf[kc][half*2+1] = pack_bf2(
                    __float2bfloat16(sc_[j][2] - __bfloat162float(h2)),
                    __float2bfloat16(sc_[j][3] - __bfloat162float(h3)));
            }
        }
        // ---- O += P V (x3): n = dh (4 tiles of 16), k = s (2 chunks of 16) ----
        #pragma unroll
        for (int nt = 0; nt < 4; nt++) {
            #pragma unroll
            for (int kc = 0; kc < 2; kc++) {
                uint32_t fh[4], fl[4];
                ldsm4(fh, sb + 2*KSZ + nt*16*VROW + bVoff + kc*32);
                ldsm4(fl, sb + 2*KSZ + VSZ + nt*16*VROW + bVoff + kc*32);
                mma16816(o[2*nt],   phf[kc], fh);
                mma16816(o[2*nt],   phf[kc], fl);
                mma16816(o[2*nt],   plf[kc], fh);
                mma16816(o[2*nt+1], phf[kc], fh+2);
                mma16816(o[2*nt+1], phf[kc], fl+2);
                mma16816(o[2*nt+1], plf[kc], fh+2);
            }
        }
    }

    float inv0 = 1.f / l0, inv1 = 1.f / l1;
    size_t base0 = ((size_t)b*SS + (q0 + wr + r))*HH + h*DH;
    size_t base8 = base0 + (size_t)8*HH;
    #pragma unroll
    for (int j = 0; j < 8; j++) {
        int col = j*8 + colb;
        float a0 = o[j][0]*inv0, a1 = o[j][1]*inv0;
        float a2 = o[j][2]*inv1, a3 = o[j][3]*inv1;
        __nv_bfloat16 h0 = __float2bfloat16(a0), h1 = __float2bfloat16(a1);
        __nv_bfloat16 h2 = __float2bfloat16(a2), h3 = __float2bfloat16(a3);
        *(uint32_t*)(cth + base0 + col) = pack_bf2(h0, h1);
        *(uint32_t*)(ctl + base0 + col) = pack_bf2(
            __float2bfloat16(a0 - __bfloat162float(h0)),
            __float2bfloat16(a1 - __bfloat162float(h1)));
        *(uint32_t*)(cth + base8 + col) = pack_bf2(h2, h3);
        *(uint32_t*)(ctl + base8 + col) = pack_bf2(
            __float2bfloat16(a2 - __bfloat162float(h2)),
            __float2bfloat16(a3 - __bfloat162float(h3)));
    }
}

// ---------------- V transpose: v[b,s,h*64+d] -> vt[(bh*64+d)][s] ----------------
__global__ __launch_bounds__(256) void vtrans_kernel(
    const __nv_bfloat16* __restrict__ vh, const __nv_bfloat16* __restrict__ vl,
    __nv_bfloat16* __restrict__ oh, __nv_bfloat16* __restrict__ ol)
{
    __shared__ __nv_bfloat16 th[32][33], tl[32][33];
    int tx = threadIdx.x, ty = threadIdx.y;
    int bh = blockIdx.y >> 1, dblk = blockIdx.y & 1;
    int b = bh / NH, h = bh % NH;
    int s0 = blockIdx.x * 32, d0 = dblk * 32;
    #pragma unroll
    for (int i = 0; i < 4; i++) {
        int s = ty + i*8;
        size_t off = ((size_t)b*SS + s0 + s)*HH + h*DH + d0 + tx;
        th[s][tx] = vh[off];
        tl[s][tx] = vl[off];
    }
    __syncthreads();
    #pragma unroll
    for (int i = 0; i < 4; i++) {
        int d = ty + i*8;
        size_t off = ((size_t)bh*DH + d0 + d)*SS + s0 + tx;
        oh[off] = th[tx][d];
        ol[off] = tl[tx][d];
    }
}

// ---------------- split fp32 -> bf16 hi/lo (only for initial x) ----------------
__global__ __launch_bounds__(256) void split_kernel(const float* __restrict__ x,
    __nv_bfloat16* __restrict__ hi, __nv_bfloat16* __restrict__ lo, int n4)
{
    int i = blockIdx.x * 256 + threadIdx.x;
    if (i >= n4) return;
    float4 v = ((const float4*)x)[i];
    __nv_bfloat16 h0 = __float2bfloat16(v.x), h1 = __float2bfloat16(v.y);
    __nv_bfloat16 h2 = __float2bfloat16(v.z), h3 = __float2bfloat16(v.w);
    __nv_bfloat162* H = (__nv_bfloat162*)hi;
    __nv_bfloat162* L = (__nv_bfloat162*)lo;
    H[i*2]   = __halves2bfloat162(h0, h1);
    H[i*2+1] = __halves2bfloat162(h2, h3);
    L[i*2]   = __halves2bfloat162(
        __float2bfloat16(v.x - __bfloat162float(h0)),
        __float2bfloat16(v.y - __bfloat162float(h1)));
    L[i*2+1] = __halves2bfloat162(
        __float2bfloat16(v.z - __bfloat162float(h2)),
        __float2bfloat16(v.w - __bfloat162float(h3)));
}

// ---------------- batched weight transpose + split: ALL layers/matrices in one launch ----
__global__ __launch_bounds__(256) void wtrans_all(
    const float* __restrict__ Wq, const float* __restrict__ Wk,
    const float* __restrict__ Wv, const float* __restrict__ Wao,
    const float* __restrict__ Wi, const float* __restrict__ Wfo,
    __nv_bfloat16* __restrict__ wh, __nv_bfloat16* __restrict__ wl)
{
    __shared__ float t[64][33];
    const int tid = threadIdx.x;
    const int l = blockIdx.z;
    int x = blockIdx.x;

    const float* W; int K_, N_; size_t off;
    if (x < 1152) {
        int m = x / 288; x -= m * 288;
        K_ = HH; N_ = HH;
        W = (m == 0 ? Wq : m == 1 ? Wk : m == 2 ? Wv : Wao) + (size_t)l * HH * HH;
        off = (m == 0 ? WQOFF : m == 1 ? WKOFF : m == 2 ? WVOFF : WAOOFF);
    } else if (x < 2304) {
        x -= 1152; K_ = HH; N_ = FF;
        W = Wi + (size_t)l * HH * FF; off = WIOFF;
    } else {
        x -= 2304; K_ = FF; N_ = HH;
        W = Wfo + (size_t)l * FF * HH; off = WFOOFF;
    }
    const int ntn = N_ >> 5;
    const int k0 = (x / ntn) << 6, n0 = (x % ntn) << 5;

    {
        int r = tid >> 5, c = tid & 31;
        #pragma unroll
        for (int i = 0; i < 8; i++)
            t[r + i*8][c] = W[(size_t)(k0 + r + i*8) * N_ + n0 + c];
    }
    __syncthreads();

    __nv_bfloat16* hi = wh + (size_t)l * LSTRIDE + off;
    __nv_bfloat16* lo = wl + (size_t)l * LSTRIDE + off;
    #pragma unroll
    for (int it = 0; it < 2; it++) {
        int idx = tid + it * 256;
        int nl = idx >> 4, kq = idx & 15;
        float v0 = t[kq*4+0][nl], v1 = t[kq*4+1][nl];
        float v2 = t[kq*4+2][nl], v3 = t[kq*4+3][nl];
        __nv_bfloat16 h0 = __float2bfloat16(v0), h1 = __float2bfloat16(v1);
        __nv_bfloat16 h2 = __float2bfloat16(v2), h3 = __float2bfloat16(v3);
        uint2 hv, lv;
        hv.x = pack_bf2(h0, h1); hv.y = pack_bf2(h2, h3);
        lv.x = pack_bf2(__float2bfloat16(v0 - __bfloat162float(h0)),
                        __float2bfloat16(v1 - __bfloat162float(h1)));
        lv.y = pack_bf2(__float2bfloat16(v2 - __bfloat162float(h2)),
                        __float2bfloat16(v3 - __bfloat162float(h3)));
        size_t base = (size_t)(n0 + nl) * K_ + k0 + kq*4;
        *(uint2*)(hi + base) = hv;
        *(uint2*)(lo + base) = lv;
    }
}

// ---------------- launch ----------------
extern "C" void kernel_launch(void* const* d_in, const int* in_sizes, int n_in,
                              void* d_out, int out_size)
{
    const float* x    = (const float*)d_in[0];
    const int*   mask = (const int*)  d_in[1];
    const float* Wq   = (const float*)d_in[2];
    const float* bq   = (const float*)d_in[3];
    const float* Wk   = (const float*)d_in[4];
    const float* bk   = (const float*)d_in[5];
    const float* Wv   = (const float*)d_in[6];
    const float* bv   = (const float*)d_in[7];
    const float* Wao  = (const float*)d_in[8];
    const float* bao  = (const float*)d_in[9];
    const float* g1   = (const float*)d_in[10];
    const float* b1   = (const float*)d_in[11];
    const float* Wi   = (const float*)d_in[12];
    const float* bi   = (const float*)d_in[13];
    const float* Wfo  = (const float*)d_in[14];
    const float* bfo  = (const float*)d_in[15];
    const float* g2   = (const float*)d_in[16];
    const float* b2   = (const float*)d_in[17];

    float *h_, *attn_, *p0_, *p1_, *p2_;
    __nv_bfloat16 *hh_, *hl_, *qh_, *ql_, *kh_, *kl_, *vh_, *vl_;
    __nv_bfloat16 *vth_, *vtl_, *cth_, *ctl_, *aah_, *aal_, *ih_, *il_, *wh_, *wl_;
    cudaGetSymbolAddress((void**)&h_,    g_h);
    cudaGetSymbolAddress((void**)&attn_, g_attn);
    cudaGetSymbolAddress((void**)&p0_,   g_p0);
    cudaGetSymbolAddress((void**)&p1_,   g_p1);
    cudaGetSymbolAddress((void**)&p2_,   g_p2);
    cudaGetSymbolAddress((void**)&hh_,   g_hh);
    cudaGetSymbolAddress((void**)&hl_,   g_hl);
    cudaGetSymbolAddress((void**)&qh_,   g_qh);
    cudaGetSymbolAddress((void**)&ql_,   g_ql);
    cudaGetSymbolAddress((void**)&kh_,   g_kh);
    cudaGetSymbolAddress((void**)&kl_,   g_kl);
    cudaGetSymbolAddress((void**)&vh_,   g_vh);
    cudaGetSymbolAddress((void**)&vl_,   g_vl);
    cudaGetSymbolAddress((void**)&vth_,  g_vth);
    cudaGetSymbolAddress((void**)&vtl_,  g_vtl);
    cudaGetSymbolAddress((void**)&cth_,  g_cth);
    cudaGetSymbolAddress((void**)&ctl_,  g_ctl);
    cudaGetSymbolAddress((void**)&aah_,  g_aah);
    cudaGetSymbolAddress((void**)&aal_,  g_aal);
    cudaGetSymbolAddress((void**)&ih_,   g_ih);
    cudaGetSymbolAddress((void**)&il_,   g_il);
    cudaGetSymbolAddress((void**)&wh_,   g_wh);
    cudaGetSymbolAddress((void**)&wl_,   g_wl);

    cudaFuncSetAttribute(gemm_tc,
                         cudaFuncAttributeMaxDynamicSharedMemorySize, GEMM_SMEM);
    cudaFuncSetAttribute(flashattn,
                         cudaFuncAttributeMaxDynamicSharedMemorySize, FSMEM);

    const int M = BB * SS;  // 2048
    const int n4 = M * HH / 4;

    wtrans_all<<<dim3(3456, 1, NL), 256>>>(Wq, Wk, Wv, Wao, Wi, Wfo, wh_, wl_);
    split_kernel<<<(n4 + 255)/256, 256>>>(x, hh_, hl_, n4);

    for (int l = 0; l < NL; l++) {
        const float* hin = (l == 0) ? x : h_;
        size_t lo = (size_t)l * LSTRIDE;

        // QKV -> bf16 hi/lo outputs
        {
            GemmArgs a = {};
            a.ah = hh_; a.al = hl_;
            a.bh0 = wh_+lo+WQOFF; a.bh1 = wh_+lo+WKOFF; a.bh2 = wh_+lo+WVOFF;
            a.bl0 = wl_+lo+WQOFF; a.bl1 = wl_+lo+WKOFF; a.bl2 = wl_+lo+WVOFF;
            a.bias0 = bq + l*HH; a.bias1 = bk + l*HH; a.bias2 = bv + l*HH;
            a.ch0 = qh_; a.cl0 = ql_; a.ch1 = kh_; a.cl1 = kl_; a.ch2 = vh_; a.cl2 = vl_;
            a.K = HH; a.N = HH; a.gelu = 0; a.outbf = 1; a.Kld = HH; a.ksplit = 0;
            gemm_tc<<<dim3(HH/128, M/128, 3), 512, GEMM_SMEM>>>(a);
        }

        vtrans_kernel<<<dim3(SS/32, BB*NH*2), dim3(32,8)>>>(vh_, vl_, vth_, vtl_);
        flashattn<<<dim3(SS/64, BB*NH), 128, FSMEM>>>(qh_, ql_, kh_, kl_, vth_, vtl_,
                                                      mask, cth_, ctl_);

        // AO proj: split-K=3 -> partials -> fused reduce+LN
        {
            GemmArgs a = {};
            a.ah = cth_; a.al = ctl_;
            a.bh0 = wh_+lo+WAOOFF; a.bh1 = a.bh0; a.bh2 = a.bh0;
            a.bl0 = wl_+lo+WAOOFF; a.bl1 = a.bl0; a.bl2 = a.bl0;
            a.c0 = p0_; a.c1 = p1_; a.c2 = p2_;
            a.K = 256; a.N = HH; a.gelu = 0; a.outbf = 0; a.Kld = HH; a.ksplit = 1;
            gemm_tc<<<dim3(HH/128, M/128, 3), 512, GEMM_SMEM>>>(a);
        }
        reduce_ln<<<M, 256>>>(p0_, p1_, p2_, bao + l*HH, hin,
                              g1 + l*HH, b1 + l*HH, attn_, aah_, aal_);

        // FFN1 (gelu) -> bf16 hi/lo
        {
            GemmArgs a = {};
            a.ah = aah_; a.al = aal_;
            a.bh0 = wh_+lo+WIOFF; a.bh1 = a.bh0; a.bh2 = a.bh0;
            a.bl0 = wl_+lo+WIOFF; a.bl1 = a.bl0; a.bl2 = a.bl0;
            a.bias0 = bi + l*FF; a.bias1 = a.bias0; a.bias2 = a.bias0;
            a.ch0 = ih_; a.cl0 = il_; a.ch1 = ih_; a.cl1 = il_; a.ch2 = ih_; a.cl2 = il_;
            a.K = HH; a.N = FF; a.gelu = 1; a.outbf = 1; a.Kld = HH; a.ksplit = 0;
            gemm_tc<<<dim3(FF/128, M/128, 1), 512, GEMM_SMEM>>>(a);
        }

        // FFN2: split-K=3 -> partials -> fused reduce+LN
        {
            GemmArgs a = {};
            a.ah = ih_; a.al = il_;
            a.bh0 = wh_+lo+WFOOFF; a.bh1 = a.bh0; a.bh2 = a.bh0;
            a.bl0 = wl_+lo+WFOOFF; a.bl1 = a.bl0; a.bl2 = a.bl0;
            a.c0 = p0_; a.c1 = p1_; a.c2 = p2_;
            a.K = 1024; a.N = HH; a.gelu = 0; a.outbf = 0; a.Kld = FF; a.ksplit = 1;
            gemm_tc<<<dim3(HH/128, M/128, 3), 512, GEMM_SMEM>>>(a);
        }
        if (l == NL - 1) {
            reduce_ln<<<M, 256>>>(p0_, p1_, p2_, bfo + l*HH, attn_,
                                  g2 + l*HH, b2 + l*HH, (float*)d_out,
                                  (__nv_bfloat16*)nullptr, (__nv_bfloat16*)nullptr);
        } else {
            reduce_ln<<<M, 256>>>(p0_, p1_, p2_, bfo + l*HH, attn_,
                                  g2 + l*HH, b2 + l*HH, h_, hh_, hl_);
        }
    }
}

// round 8
// speedup vs baseline: 3.1805x; 1.0162x over previous
#include <cuda_runtime.h>
#include <cuda_bf16.h>
#include <math.h>
#include <stdint.h>

#define BB 2
#define SS 1024
#define HH 768
#define NH 12
#define DH 64
#define FF 3072
#define NL 4

// ---------------- scratch (device globals; no allocation allowed) ----------------
__device__ float g_h[BB*SS*HH];
__device__ float g_attn[BB*SS*HH];
__device__ float g_p0[BB*SS*HH];
__device__ float g_p1[BB*SS*HH];
__device__ float g_p2[BB*SS*HH];

__device__ __nv_bfloat16 g_hh[BB*SS*HH], g_hl[BB*SS*HH];
__device__ __nv_bfloat16 g_qh[BB*SS*HH], g_ql[BB*SS*HH];
__device__ __nv_bfloat16 g_kh[BB*SS*HH], g_kl[BB*SS*HH];
__device__ __nv_bfloat16 g_vh[BB*SS*HH], g_vl[BB*SS*HH];
__device__ __nv_bfloat16 g_cth[BB*SS*HH], g_ctl[BB*SS*HH];
__device__ __nv_bfloat16 g_aah[BB*SS*HH], g_aal[BB*SS*HH];
__device__ __nv_bfloat16 g_ih[BB*SS*FF], g_il[BB*SS*FF];
__device__ __nv_bfloat16 g_madd[(size_t)BB*SS*SS];   // (1-mask)*-10000 as bf16

// transposed+split weights per layer: [wq wk wv wao wi wfo], each [N][K] row-major
#define WQOFF  0
#define WKOFF  589824
#define WVOFF  1179648
#define WAOOFF 1769472
#define WIOFF  2359296
#define WFOOFF 4718592
#define LSTRIDE 7077888
__device__ __nv_bfloat16 g_wh[(size_t)NL*LSTRIDE];
__device__ __nv_bfloat16 g_wl[(size_t)NL*LSTRIDE];

// ---------------- PTX helpers (arch-neutral: ldmatrix / mma.sync / cp.async) ----------------
__device__ __forceinline__ uint32_t smem_u32(const void* p) {
    uint32_t a;
    asm("{ .reg .u64 t; cvta.to.shared.u64 t, %1; cvt.u32.u64 %0, t; }" : "=r"(a) : "l"(p));
    return a;
}
__device__ __forceinline__ void cpa16(uint32_t dst, const void* src) {
    asm volatile("cp.async.cg.shared.global [%0], [%1], 16;" :: "r"(dst), "l"(src));
}
#define CP_COMMIT() asm volatile("cp.async.commit_group;" ::: "memory")

__device__ __forceinline__ void ldsm4(uint32_t* r, uint32_t a) {
    asm volatile("ldmatrix.sync.aligned.m8n8.x4.shared.b16 {%0,%1,%2,%3}, [%4];"
        : "=r"(r[0]), "=r"(r[1]), "=r"(r[2]), "=r"(r[3]) : "r"(a));
}
__device__ __forceinline__ void ldsm4t(uint32_t* r, uint32_t a) {
    asm volatile("ldmatrix.sync.aligned.m8n8.x4.trans.shared.b16 {%0,%1,%2,%3}, [%4];"
        : "=r"(r[0]), "=r"(r[1]), "=r"(r[2]), "=r"(r[3]) : "r"(a));
}
__device__ __forceinline__ void mma16816(float* c, const uint32_t* a, const uint32_t* b) {
    asm volatile("mma.sync.aligned.m16n8k16.row.col.f32.bf16.bf16.f32 "
        "{%0,%1,%2,%3}, {%4,%5,%6,%7}, {%8,%9}, {%0,%1,%2,%3};"
        : "+f"(c[0]), "+f"(c[1]), "+f"(c[2]), "+f"(c[3])
        : "r"(a[0]), "r"(a[1]), "r"(a[2]), "r"(a[3]), "r"(b[0]), "r"(b[1]));
}
__device__ __forceinline__ uint32_t pack_bf2(__nv_bfloat16 a, __nv_bfloat16 b) {
    __nv_bfloat162 t = __halves2bfloat162(a, b);
    return *(uint32_t*)&t;
}

// ---------------- bf16x3 HMMA GEMM ----------------
struct GemmArgs {
    const __nv_bfloat16 *ah, *al;
    const __nv_bfloat16 *bh0, *bh1, *bh2, *bl0, *bl1, *bl2;
    const float *bias0, *bias1, *bias2;
    const float *resid;
    float *c0, *c1, *c2;
    __nv_bfloat16 *ch0, *cl0, *ch1, *cl1, *ch2, *cl2;
    int K, N, gelu, outbf, Kld, ksplit;
};

#define ABUF 10240            // 128 rows * 80B (64B data + 16B pad)
#define STGB (4*ABUF)         // Ah, Al, Bh, Bl
#define NSTG 3
#define GEMM_SMEM (NSTG*STGB) // 122880

__global__ __launch_bounds__(512) void gemm_tc(GemmArgs g) {
    extern __shared__ char smem[];
    const uint32_t su = smem_u32(smem);
    const int tid = threadIdx.x;
    const int lane = tid & 31, warp = tid >> 5;
    const int warpM = warp & 3, warpN = warp >> 2;
    const int m0 = blockIdx.y << 7, n0 = blockIdx.x << 7;

    const __nv_bfloat16 *bh, *bl; const float* bias; float* C;
    __nv_bfloat16 *CH, *CL;
    if (blockIdx.z == 0)      { bh=g.bh0; bl=g.bl0; bias=g.bias0; C=g.c0; CH=g.ch0; CL=g.cl0; }
    else if (blockIdx.z == 1) { bh=g.bh1; bl=g.bl1; bias=g.bias1; C=g.c1; CH=g.ch1; CL=g.cl1; }
    else                      { bh=g.bh2; bl=g.bl2; bias=g.bias2; C=g.c2; CH=g.ch2; CL=g.cl2; }
    const int K = g.K, N = g.N, nk = K >> 5;
    const int kbase = g.ksplit ? (int)blockIdx.z * K : 0;

    const int ldg_row = tid >> 2, ldg_c = tid & 3;
    const size_t ldab = (size_t)g.Kld * 2;
    const char* pAh = (const char*)g.ah + ((size_t)(m0 + ldg_row)) * ldab + (size_t)kbase*2 + ldg_c * 16;
    const char* pAl = (const char*)g.al + ((size_t)(m0 + ldg_row)) * ldab + (size_t)kbase*2 + ldg_c * 16;
    const char* pBh = (const char*)bh   + ((size_t)(n0 + ldg_row)) * ldab + (size_t)kbase*2 + ldg_c * 16;
    const char* pBl = (const char*)bl   + ((size_t)(n0 + ldg_row)) * ldab + (size_t)kbase*2 + ldg_c * 16;
    const uint32_t sdst = ldg_row * 80 + ldg_c * 16;

    auto load_chunk = [&](int j, int s) {
        uint32_t sb = su + s * STGB + sdst;
        size_t go = (size_t)j * 64;
        cpa16(sb,            pAh + go);
        cpa16(sb +   ABUF,   pAl + go);
        cpa16(sb + 2*ABUF,   pBh + go);
        cpa16(sb + 3*ABUF,   pBl + go);
    };

    load_chunk(0, 0); CP_COMMIT();
    load_chunk(1, 1); CP_COMMIT();

    float acc[2][4][4];
    #pragma unroll
    for (int i = 0; i < 2; i++)
        #pragma unroll
        for (int j = 0; j < 4; j++)
            #pragma unroll
            for (int r = 0; r < 4; r++) acc[i][j][r] = 0.f;

    const uint32_t a_off = (uint32_t)(warpM*32 + (lane & 15)) * 80 + (lane >> 4) * 16;
    const uint32_t b_off = (uint32_t)(warpN*32 + (((lane >> 4) & 1) << 3) + (lane & 7)) * 80
                         + ((lane >> 3) & 1) * 16;

    for (int i = 0; i < nk; i++) {
        asm volatile("cp.async.wait_group 1;" ::: "memory");
        __syncthreads();
        int j = i + 2;
        if (j < nk) load_chunk(j, j % NSTG);
        CP_COMMIT();

        uint32_t base = su + (i % NSTG) * STGB;
        #pragma unroll
        for (int ks = 0; ks < 2; ks++) {
            uint32_t ko = ks * 32;
            uint32_t ah0[4], ah1[4], al0[4], al1[4];
            uint32_t bhf0[4], bhf1[4], blf0[4], blf1[4];
            ldsm4(ah0, base + a_off + ko);
            ldsm4(ah1, base + a_off + 16*80 + ko);
            ldsm4(al0, base + ABUF + a_off + ko);
            ldsm4(al1, base + ABUF + a_off + 16*80 + ko);
            ldsm4(bhf0, base + 2*ABUF + b_off + ko);
            ldsm4(bhf1, base + 2*ABUF + b_off + 16*80 + ko);
            ldsm4(blf0, base + 3*ABUF + b_off + ko);
            ldsm4(blf1, base + 3*ABUF + b_off + 16*80 + ko);
            uint32_t* AH[2] = {ah0, ah1};
            uint32_t* AL[2] = {al0, al1};
            #pragma unroll
            for (int mt = 0; mt < 2; mt++) {
                mma16816(acc[mt][0], AH[mt], bhf0);
                mma16816(acc[mt][0], AH[mt], blf0);
                mma16816(acc[mt][0], AL[mt], bhf0);
                mma16816(acc[mt][1], AH[mt], bhf0+2);
                mma16816(acc[mt][1], AH[mt], blf0+2);
                mma16816(acc[mt][1], AL[mt], bhf0+2);
                mma16816(acc[mt][2], AH[mt], bhf1);
                mma16816(acc[mt][2], AH[mt], blf1);
                mma16816(acc[mt][2], AL[mt], bhf1);
                mma16816(acc[mt][3], AH[mt], bhf1+2);
                mma16816(acc[mt][3], AH[mt], blf1+2);
                mma16816(acc[mt][3], AL[mt], bhf1+2);
            }
        }
    }

    const int erow = m0 + warpM*32 + (lane >> 2);
    const int ecol = n0 + warpN*32 + (lane & 3)*2;
    #pragma unroll
    for (int mt = 0; mt < 2; mt++) {
        #pragma unroll
        for (int nt = 0; nt < 4; nt++) {
            int c = ecol + nt*8;
            float b0 = bias ? bias[c] : 0.f, b1 = bias ? bias[c+1] : 0.f;
            #pragma unroll
            for (int half = 0; half < 2; half++) {
                int r = erow + mt*16 + half*8;
                float o0 = acc[mt][nt][half*2+0] + b0;
                float o1 = acc[mt][nt][half*2+1] + b1;
                if (g.resid) {
                    float2 rv = *(const float2*)(g.resid + (size_t)r * N + c);
                    o0 += rv.x; o1 += rv.y;
                }
                if (g.gelu) {
                    o0 = 0.5f * o0 * (1.0f + erff(o0 * 0.70710678118654752f));
                    o1 = 0.5f * o1 * (1.0f + erff(o1 * 0.70710678118654752f));
                }
                if (g.outbf) {
                    __nv_bfloat16 h0 = __float2bfloat16(o0), h1 = __float2bfloat16(o1);
                    __nv_bfloat16 l0 = __float2bfloat16(o0 - __bfloat162float(h0));
                    __nv_bfloat16 l1 = __float2bfloat16(o1 - __bfloat162float(h1));
                    *(uint32_t*)(CH + (size_t)r * N + c) = pack_bf2(h0, h1);
                    *(uint32_t*)(CL + (size_t)r * N + c) = pack_bf2(l0, l1);
                } else {
                    float2 ov; ov.x = o0; ov.y = o1;
                    *(float2*)(C + (size_t)r * N + c) = ov;
                }
            }
        }
    }
}

// ---------------- fused split-K reduce + LayerNorm (+ optional bf16 hi/lo out) ----------------
__global__ __launch_bounds__(256) void reduce_ln(
    const float* __restrict__ p0, const float* __restrict__ p1,
    const float* __restrict__ p2, const float* __restrict__ bias,
    const float* __restrict__ resid,
    const float* __restrict__ g, const float* __restrict__ b,
    float* __restrict__ out,
    __nv_bfloat16* __restrict__ oh, __nv_bfloat16* __restrict__ ol)
{
    const int row = blockIdx.x;
    const int tid = threadIdx.x;
    const size_t base = (size_t)row * HH;

    float v0, v1, v2;
    {
        int i0 = tid, i1 = tid + 256, i2 = tid + 512;
        v0 = p0[base+i0] + p1[base+i0] + p2[base+i0] + bias[i0] + resid[base+i0];
        v1 = p0[base+i1] + p1[base+i1] + p2[base+i1] + bias[i1] + resid[base+i1];
        v2 = p0[base+i2] + p1[base+i2] + p2[base+i2] + bias[i2] + resid[base+i2];
    }

    __shared__ float red[8];
    float s = v0 + v1 + v2;
    #pragma unroll
    for (int o2 = 16; o2; o2 >>= 1) s += __shfl_xor_sync(0xffffffffu, s, o2);
    if ((tid & 31) == 0) red[tid >> 5] = s;
    __syncthreads();
    float tot = 0.f;
    #pragma unroll
    for (int i = 0; i < 8; i++) tot += red[i];
    float mean = tot * (1.0f / 768.0f);

    float d0 = v0 - mean, d1 = v1 - mean, d2 = v2 - mean;
    float sq = d0*d0 + d1*d1 + d2*d2;
    __syncthreads();
    #pragma unroll
    for (int o2 = 16; o2; o2 >>= 1) sq += __shfl_xor_sync(0xffffffffu, sq, o2);
    if ((tid & 31) == 0) red[tid >> 5] = sq;
    __syncthreads();
    float tot2 = 0.f;
    #pragma unroll
    for (int i = 0; i < 8; i++) tot2 += red[i];
    float rstd = rsqrtf(tot2 * (1.0f / 768.0f) + 1e-12f);

    float r0 = d0 * rstd * g[tid]       + b[tid];
    float r1 = d1 * rstd * g[tid + 256] + b[tid + 256];
    float r2 = d2 * rstd * g[tid + 512] + b[tid + 512];
    out[base + tid] = r0; out[base + tid + 256] = r1; out[base + tid + 512] = r2;
    if (oh) {
        __nv_bfloat16 h0 = __float2bfloat16(r0);
        __nv_bfloat16 h1 = __float2bfloat16(r1);
        __nv_bfloat16 h2 = __float2bfloat16(r2);
        oh[base + tid] = h0;       ol[base + tid]       = __float2bfloat16(r0 - __bfloat162float(h0));
        oh[base + tid + 256] = h1; ol[base + tid + 256] = __float2bfloat16(r1 - __bfloat162float(h1));
        oh[base + tid + 512] = h2; ol[base + tid + 512] = __float2bfloat16(r2 - __bfloat162float(h2));
    }
}

// ---------------- flash attention: K-tile 32, 3-stage pipeline, 3 CTAs/SM ----------------
// Q-tile 64, 128 threads (4 warps x 16 q rows). V row-major, PV uses ldmatrix.trans.
#define QROW 144
#define FQBUF 9216            // 64*144
#define KROW 144
#define KSZ  4608             // 32*144
#define FSTG2 (4*KSZ)         // Kh, Kl, Vh, Vl = 18432
#define FNSTG 3
#define FSMEM (2*FQBUF + FNSTG*FSTG2)  // 73728

__global__ __launch_bounds__(128, 3) void flashattn(
    const __nv_bfloat16* __restrict__ qh, const __nv_bfloat16* __restrict__ ql,
    const __nv_bfloat16* __restrict__ kh, const __nv_bfloat16* __restrict__ kl,
    const __nv_bfloat16* __restrict__ vh, const __nv_bfloat16* __restrict__ vl,
    const __nv_bfloat16* __restrict__ madd,
    __nv_bfloat16* __restrict__ cth, __nv_bfloat16* __restrict__ ctl)
{
    extern __shared__ char smem[];
    const uint32_t su = smem_u32(smem);
    const int tid = threadIdx.x, lane = tid & 31, warp = tid >> 5;
    const int q0 = blockIdx.x * 64, bh = blockIdx.y;
    const int b = bh / NH, h = bh % NH;
    const int wr = warp * 16;

    const char* Qh = (const char*)(qh + ((size_t)b*SS + q0)*HH + h*DH);
    const char* Ql = (const char*)(ql + ((size_t)b*SS + q0)*HH + h*DH);
    const char* Kh = (const char*)(kh + ((size_t)b*SS)*HH + h*DH);
    const char* Kl = (const char*)(kl + ((size_t)b*SS)*HH + h*DH);
    const char* Vh = (const char*)(vh + ((size_t)b*SS)*HH + h*DH);
    const char* Vl = (const char*)(vl + ((size_t)b*SS)*HH + h*DH);

    // Q: 64 rows x 128B per buffer
    #pragma unroll
    for (int c = 0; c < 4; c++) {
        int idx = tid + c*128;
        int row = idx >> 3, chn = idx & 7;
        uint32_t dst = su + row*QROW + chn*16;
        size_t so = (size_t)row*1536 + chn*16;
        cpa16(dst,         Qh + so);
        cpa16(dst + FQBUF, Ql + so);
    }
    CP_COMMIT();

    auto load_kv = [&](int j, int s) {
        uint32_t sb = su + 2*FQBUF + s*FSTG2;
        int k0 = j * 32;
        #pragma unroll
        for (int c = 0; c < 2; c++) {
            int idx = tid + c*128;
            int row = idx >> 3, chn = idx & 7;      // 32 rows x 128B each buffer
            uint32_t dst = sb + row*KROW + chn*16;
            size_t ko = (size_t)(k0 + row)*1536 + chn*16;
            cpa16(dst,         Kh + ko);
            cpa16(dst +   KSZ, Kl + ko);
            cpa16(dst + 2*KSZ, Vh + ko);
            cpa16(dst + 3*KSZ, Vl + ko);
        }
    };
    load_kv(0, 0); CP_COMMIT();
    load_kv(1, 1); CP_COMMIT();

    asm volatile("cp.async.wait_group 2;" ::: "memory");
    __syncthreads();

    // Q fragments (kept in regs whole kernel)
    uint32_t qhf[4][4], qlf[4][4];
    {
        uint32_t abase = su + (uint32_t)(wr + (lane & 15))*QROW + (lane >> 4)*16;
        #pragma unroll
        for (int kc = 0; kc < 4; kc++) {
            ldsm4(qhf[kc], abase + kc*32);
            ldsm4(qlf[kc], abase + FQBUF + kc*32);
        }
    }

    float o[8][4];
    #pragma unroll
    for (int j = 0; j < 8; j++)
        #pragma unroll
        for (int r = 0; r < 4; r++) o[j][r] = 0.f;
    float m0 = -1e30f, m1 = -1e30f, l0 = 0.f, l1 = 0.f;

    const int r = lane >> 2;
    const int colb = (lane & 3) * 2;
    const __nv_bfloat16* mrow0 = madd + ((size_t)b*SS + (q0 + wr + r))*SS;
    const __nv_bfloat16* mrow8 = mrow0 + 8*SS;
    const uint32_t rowsel = (uint32_t)((((lane >> 4) & 1) << 3) + (lane & 7));
    const uint32_t bKoff = rowsel*KROW + ((lane >> 3) & 1)*16;
    // trans-ldmatrix addressing for V (row-major): lanes give 16 k-rows, +16B for n8 tile 2
    const uint32_t bVoff = (uint32_t)(lane & 15)*KROW + ((lane >> 4) & 1)*16;

    for (int i = 0; i < 32; i++) {
        asm volatile("cp.async.wait_group 1;" ::: "memory");
        __syncthreads();
        if (i + 2 < 32) load_kv(i + 2, (i + 2) % 3);
        CP_COMMIT();

        const uint32_t sb = su + 2*FQBUF + (i % 3)*FSTG2;
        const int k0 = i * 32;

        // ---- S = Q K^T (x3): 64 q x 32 s ----
        float sc_[4][4];
        #pragma unroll
        for (int j = 0; j < 4; j++)
            #pragma unroll
            for (int t = 0; t < 4; t++) sc_[j][t] = 0.f;
        #pragma unroll
        for (int nt = 0; nt < 2; nt++) {
            #pragma unroll
            for (int kc = 0; kc < 4; kc++) {
                uint32_t fh[4], fl[4];
                ldsm4(fh, sb + nt*16*KROW + bKoff + kc*32);
                ldsm4(fl, sb + KSZ + nt*16*KROW + bKoff + kc*32);
                mma16816(sc_[2*nt],   qhf[kc], fh);
                mma16816(sc_[2*nt],   qhf[kc], fl);
                mma16816(sc_[2*nt],   qlf[kc], fh);
                mma16816(sc_[2*nt+1], qhf[kc], fh+2);
                mma16816(sc_[2*nt+1], qhf[kc], fl+2);
                mma16816(sc_[2*nt+1], qlf[kc], fh+2);
            }
        }
        // ---- mask + scale (bf16 additive mask, prebaked) ----
        #pragma unroll
        for (int j = 0; j < 4; j++) {
            int kc2 = k0 + j*8 + colb;
            __nv_bfloat162 ma = *(const __nv_bfloat162*)(mrow0 + kc2);
            __nv_bfloat162 mb = *(const __nv_bfloat162*)(mrow8 + kc2);
            float2 fa = __bfloat1622float2(ma);
            float2 fb = __bfloat1622float2(mb);
            sc_[j][0] = sc_[j][0]*0.125f + fa.x;
            sc_[j][1] = sc_[j][1]*0.125f + fa.y;
            sc_[j][2] = sc_[j][2]*0.125f + fb.x;
            sc_[j][3] = sc_[j][3]*0.125f + fb.y;
        }
        // ---- online softmax ----
        float mx0 = -1e30f, mx1 = -1e30f;
        #pragma unroll
        for (int j = 0; j < 4; j++) {
            mx0 = fmaxf(mx0, fmaxf(sc_[j][0], sc_[j][1]));
            mx1 = fmaxf(mx1, fmaxf(sc_[j][2], sc_[j][3]));
        }
        mx0 = fmaxf(mx0, __shfl_xor_sync(0xffffffffu, mx0, 1));
        mx0 = fmaxf(mx0, __shfl_xor_sync(0xffffffffu, mx0, 2));
        mx1 = fmaxf(mx1, __shfl_xor_sync(0xffffffffu, mx1, 1));
        mx1 = fmaxf(mx1, __shfl_xor_sync(0xffffffffu, mx1, 2));
        float mn0 = fmaxf(m0, mx0), mn1 = fmaxf(m1, mx1);
        float sf0 = __expf(m0 - mn0), sf1 = __expf(m1 - mn1);
        m0 = mn0; m1 = mn1;
        float rs0 = 0.f, rs1 = 0.f;
        #pragma unroll
        for (int j = 0; j < 4; j++) {
            sc_[j][0] = __expf(sc_[j][0] - mn0);
            sc_[j][1] = __expf(sc_[j][1] - mn0);
            sc_[j][2] = __expf(sc_[j][2] - mn1);
            sc_[j][3] = __expf(sc_[j][3] - mn1);
            rs0 += sc_[j][0] + sc_[j][1];
            rs1 += sc_[j][2] + sc_[j][3];
        }
        rs0 += __shfl_xor_sync(0xffffffffu, rs0, 1);
        rs0 += __shfl_xor_sync(0xffffffffu, rs0, 2);
        rs1 += __shfl_xor_sync(0xffffffffu, rs1, 1);
        rs1 += __shfl_xor_sync(0xffffffffu, rs1, 2);
        l0 = l0*sf0 + rs0;
        l1 = l1*sf1 + rs1;
        #pragma unroll
        for (int j = 0; j < 8; j++) {
            o[j][0] *= sf0; o[j][1] *= sf0; o[j][2] *= sf1; o[j][3] *= sf1;
        }
        // ---- P -> bf16 hi/lo A-fragments (2 k16 chunks) ----
        uint32_t phf[2][4], plf[2][4];
        #pragma unroll
        for (int kc = 0; kc < 2; kc++) {
            #pragma unroll
            for (int half = 0; half < 2; half++) {
                int j = 2*kc + half;
                __nv_bfloat16 h0 = __float2bfloat16(sc_[j][0]);
                __nv_bfloat16 h1 = __float2bfloat16(sc_[j][1]);
                __nv_bfloat16 h2 = __float2bfloat16(sc_[j][2]);
                __nv_bfloat16 h3 = __float2bfloat16(sc_[j][3]);
                phf[kc][half*2+0] = pack_bf2(h0, h1);
                phf[kc][half*2+1] = pack_bf2(h2, h3);
                plf[kc][half*2+0] = pack_bf2(
                    __float2bfloat16(sc_[j][0] - __bfloat162float(h0)),
                    __float2bfloat16(sc_[j][1] - __bfloat162float(h1)));
                plf[kc][half*2+1] = pack_bf2(
                    __float2bfloat16(sc_[j][2] - __bfloat162float(h2)),
                    __float2bfloat16(sc_[j][3] - __bfloat162float(h3)));
            }
        }
        // ---- O += P V (x3): trans-ldmatrix B frags from row-major V ----
        #pragma unroll
        for (int nt = 0; nt < 4; nt++) {
            #pragma unroll
            for (int kc = 0; kc < 2; kc++) {
                uint32_t fh[4], fl[4];
                ldsm4t(fh, sb + 2*KSZ + kc*16*KROW + bVoff + nt*32);
                ldsm4t(fl, sb + 3*KSZ + kc*16*KROW + bVoff + nt*32);
                mma16816(o[2*nt],   phf[kc], fh);
                mma16816(o[2*nt],   phf[kc], fl);
                mma16816(o[2*nt],   plf[kc], fh);
                mma16816(o[2*nt+1], phf[kc], fh+2);
                mma16816(o[2*nt+1], phf[kc], fl+2);
                mma16816(o[2*nt+1], plf[kc], fh+2);
            }
        }
    }

    float inv0 = 1.f / l0, inv1 = 1.f / l1;
    size_t base0 = ((size_t)b*SS + (q0 + wr + r))*HH + h*DH;
    size_t base8 = base0 + (size_t)8*HH;
    #pragma unroll
    for (int j = 0; j < 8; j++) {
        int col = j*8 + colb;
        float a0 = o[j][0]*inv0, a1 = o[j][1]*inv0;
        float a2 = o[j][2]*inv1, a3 = o[j][3]*inv1;
        __nv_bfloat16 h0 = __float2bfloat16(a0), h1 = __float2bfloat16(a1);
        __nv_bfloat16 h2 = __float2bfloat16(a2), h3 = __float2bfloat16(a3);
        *(uint32_t*)(cth + base0 + col) = pack_bf2(h0, h1);
        *(uint32_t*)(ctl + base0 + col) = pack_bf2(
            __float2bfloat16(a0 - __bfloat162float(h0)),
            __float2bfloat16(a1 - __bfloat162float(h1)));
        *(uint32_t*)(cth + base8 + col) = pack_bf2(h2, h3);
        *(uint32_t*)(ctl + base8 + col) = pack_bf2(
            __float2bfloat16(a2 - __bfloat162float(h2)),
            __float2bfloat16(a3 - __bfloat162float(h3)));
    }
}

// ---------------- mask -> bf16 additive prebake ----------------
__global__ __launch_bounds__(256) void maskprep(const int* __restrict__ mask,
                                                __nv_bfloat16* __restrict__ madd, int n4)
{
    int i = blockIdx.x * 256 + threadIdx.x;
    if (i >= n4) return;
    int4 m = ((const int4*)mask)[i];
    __nv_bfloat16 z = __float2bfloat16(0.f), neg = __float2bfloat16(-10000.f);
    uint2 o;
    o.x = pack_bf2(m.x ? z : neg, m.y ? z : neg);
    o.y = pack_bf2(m.z ? z : neg, m.w ? z : neg);
    *(uint2*)(madd + (size_t)i*4) = o;
}

// ---------------- split fp32 -> bf16 hi/lo (only for initial x) ----------------
__global__ __launch_bounds__(256) void split_kernel(const float* __restrict__ x,
    __nv_bfloat16* __restrict__ hi, __nv_bfloat16* __restrict__ lo, int n4)
{
    int i = blockIdx.x * 256 + threadIdx.x;
    if (i >= n4) return;
    float4 v = ((const float4*)x)[i];
    __nv_bfloat16 h0 = __float2bfloat16(v.x), h1 = __float2bfloat16(v.y);
    __nv_bfloat16 h2 = __float2bfloat16(v.z), h3 = __float2bfloat16(v.w);
    __nv_bfloat162* H = (__nv_bfloat162*)hi;
    __nv_bfloat162* L = (__nv_bfloat162*)lo;
    H[i*2]   = __halves2bfloat162(h0, h1);
    H[i*2+1] = __halves2bfloat162(h2, h3);
    L[i*2]   = __halves2bfloat162(
        __float2bfloat16(v.x - __bfloat162float(h0)),
        __float2bfloat16(v.y - __bfloat162float(h1)));
    L[i*2+1] = __halves2bfloat162(
        __float2bfloat16(v.z - __bfloat162float(h2)),
        __float2bfloat16(v.w - __bfloat162float(h3)));
}

// ---------------- batched weight transpose + split: ALL layers/matrices in one launch ----
__global__ __launch_bounds__(256) void wtrans_all(
    const float* __restrict__ Wq, const float* __restrict__ Wk,
    const float* __restrict__ Wv, const float* __restrict__ Wao,
    const float* __restrict__ Wi, const float* __restrict__ Wfo,
    __nv_bfloat16* __restrict__ wh, __nv_bfloat16* __restrict__ wl)
{
    __shared__ float t[64][33];
    const int tid = threadIdx.x;
    const int l = blockIdx.z;
    int x = blockIdx.x;

    const float* W; int K_, N_; size_t off;
    if (x < 1152) {
        int m = x / 288; x -= m * 288;
        K_ = HH; N_ = HH;
        W = (m == 0 ? Wq : m == 1 ? Wk : m == 2 ? Wv : Wao) + (size_t)l * HH * HH;
        off = (m == 0 ? WQOFF : m == 1 ? WKOFF : m == 2 ? WVOFF : WAOOFF);
    } else if (x < 2304) {
        x -= 1152; K_ = HH; N_ = FF;
        W = Wi + (size_t)l * HH * FF; off = WIOFF;
    } else {
        x -= 2304; K_ = FF; N_ = HH;
        W = Wfo + (size_t)l * FF * HH; off = WFOOFF;
    }
    const int ntn = N_ >> 5;
    const int k0 = (x / ntn) << 6, n0 = (x % ntn) << 5;

    {
        int r = tid >> 5, c = tid & 31;
        #pragma unroll
        for (int i = 0; i < 8; i++)
            t[r + i*8][c] = W[(size_t)(k0 + r + i*8) * N_ + n0 + c];
    }
    __syncthreads();

    __nv_bfloat16* hi = wh + (size_t)l * LSTRIDE + off;
    __nv_bfloat16* lo = wl + (size_t)l * LSTRIDE + off;
    #pragma unroll
    for (int it = 0; it < 2; it++) {
        int idx = tid + it * 256;
        int nl = idx >> 4, kq = idx & 15;
        float v0 = t[kq*4+0][nl], v1 = t[kq*4+1][nl];
        float v2 = t[kq*4+2][nl], v3 = t[kq*4+3][nl];
        __nv_bfloat16 h0 = __float2bfloat16(v0), h1 = __float2bfloat16(v1);
        __nv_bfloat16 h2 = __float2bfloat16(v2), h3 = __float2bfloat16(v3);
        uint2 hv, lv;
        hv.x = pack_bf2(h0, h1); hv.y = pack_bf2(h2, h3);
        lv.x = pack_bf2(__float2bfloat16(v0 - __bfloat162float(h0)),
                        __float2bfloat16(v1 - __bfloat162float(h1)));
        lv.y = pack_bf2(__float2bfloat16(v2 - __bfloat162float(h2)),
                        __float2bfloat16(v3 - __bfloat162float(h3)));
        size_t base = (size_t)(n0 + nl) * K_ + k0 + kq*4;
        *(uint2*)(hi + base) = hv;
        *(uint2*)(lo + base) = lv;
    }
}

// ---------------- launch ----------------
extern "C" void kernel_launch(void* const* d_in, const int* in_sizes, int n_in,
                              void* d_out, int out_size)
{
    const float* x    = (const float*)d_in[0];
    const int*   mask = (const int*)  d_in[1];
    const float* Wq   = (const float*)d_in[2];
    const float* bq   = (const float*)d_in[3];
    const float* Wk   = (const float*)d_in[4];
    const float* bk   = (const float*)d_in[5];
    const float* Wv   = (const float*)d_in[6];
    const float* bv   = (const float*)d_in[7];
    const float* Wao  = (const float*)d_in[8];
    const float* bao  = (const float*)d_in[9];
    const float* g1   = (const float*)d_in[10];
    const float* b1   = (const float*)d_in[11];
    const float* Wi   = (const float*)d_in[12];
    const float* bi   = (const float*)d_in[13];
    const float* Wfo  = (const float*)d_in[14];
    const float* bfo  = (const float*)d_in[15];
    const float* g2   = (const float*)d_in[16];
    const float* b2   = (const float*)d_in[17];

    float *h_, *attn_, *p0_, *p1_, *p2_;
    __nv_bfloat16 *hh_, *hl_, *qh_, *ql_, *kh_, *kl_, *vh_, *vl_;
    __nv_bfloat16 *cth_, *ctl_, *aah_, *aal_, *ih_, *il_, *wh_, *wl_, *madd_;
    cudaGetSymbolAddress((void**)&h_,    g_h);
    cudaGetSymbolAddress((void**)&attn_, g_attn);
    cudaGetSymbolAddress((void**)&p0_,   g_p0);
    cudaGetSymbolAddress((void**)&p1_,   g_p1);
    cudaGetSymbolAddress((void**)&p2_,   g_p2);
    cudaGetSymbolAddress((void**)&hh_,   g_hh);
    cudaGetSymbolAddress((void**)&hl_,   g_hl);
    cudaGetSymbolAddress((void**)&qh_,   g_qh);
    cudaGetSymbolAddress((void**)&ql_,   g_ql);
    cudaGetSymbolAddress((void**)&kh_,   g_kh);
    cudaGetSymbolAddress((void**)&kl_,   g_kl);
    cudaGetSymbolAddress((void**)&vh_,   g_vh);
    cudaGetSymbolAddress((void**)&vl_,   g_vl);
    cudaGetSymbolAddress((void**)&cth_,  g_cth);
    cudaGetSymbolAddress((void**)&ctl_,  g_ctl);
    cudaGetSymbolAddress((void**)&aah_,  g_aah);
    cudaGetSymbolAddress((void**)&aal_,  g_aal);
    cudaGetSymbolAddress((void**)&ih_,   g_ih);
    cudaGetSymbolAddress((void**)&il_,   g_il);
    cudaGetSymbolAddress((void**)&wh_,   g_wh);
    cudaGetSymbolAddress((void**)&wl_,   g_wl);
    cudaGetSymbolAddress((void**)&madd_, g_madd);

    cudaFuncSetAttribute(gemm_tc,
                         cudaFuncAttributeMaxDynamicSharedMemorySize, GEMM_SMEM);
    cudaFuncSetAttribute(flashattn,
                         cudaFuncAttributeMaxDynamicSharedMemorySize, FSMEM);

    const int M = BB * SS;  // 2048
    const int n4 = M * HH / 4;
    const int mn4 = BB * SS * SS / 4;

    wtrans_all<<<dim3(3456, 1, NL), 256>>>(Wq, Wk, Wv, Wao, Wi, Wfo, wh_, wl_);
    maskprep<<<(mn4 + 255)/256, 256>>>(mask, madd_, mn4);
    split_kernel<<<(n4 + 255)/256, 256>>>(x, hh_, hl_, n4);

    for (int l = 0; l < NL; l++) {
        const float* hin = (l == 0) ? x : h_;
        size_t lo = (size_t)l * LSTRIDE;

        // QKV -> bf16 hi/lo outputs
        {
            GemmArgs a = {};
            a.ah = hh_; a.al = hl_;
            a.bh0 = wh_+lo+WQOFF; a.bh1 = wh_+lo+WKOFF; a.bh2 = wh_+lo+WVOFF;
            a.bl0 = wl_+lo+WQOFF; a.bl1 = wl_+lo+WKOFF; a.bl2 = wl_+lo+WVOFF;
            a.bias0 = bq + l*HH; a.bias1 = bk + l*HH; a.bias2 = bv + l*HH;
            a.ch0 = qh_; a.cl0 = ql_; a.ch1 = kh_; a.cl1 = kl_; a.ch2 = vh_; a.cl2 = vl_;
            a.K = HH; a.N = HH; a.gelu = 0; a.outbf = 1; a.Kld = HH; a.ksplit = 0;
            gemm_tc<<<dim3(HH/128, M/128, 3), 512, GEMM_SMEM>>>(a);
        }

        flashattn<<<dim3(SS/64, BB*NH), 128, FSMEM>>>(qh_, ql_, kh_, kl_, vh_, vl_,
                                                      madd_, cth_, ctl_);

        // AO proj: split-K=3 -> partials -> fused reduce+LN
        {
            GemmArgs a = {};
            a.ah = cth_; a.al = ctl_;
            a.bh0 = wh_+lo+WAOOFF; a.bh1 = a.bh0; a.bh2 = a.bh0;
            a.bl0 = wl_+lo+WAOOFF; a.bl1 = a.bl0; a.bl2 = a.bl0;
            a.c0 = p0_; a.c1 = p1_; a.c2 = p2_;
            a.K = 256; a.N = HH; a.gelu = 0; a.outbf = 0; a.Kld = HH; a.ksplit = 1;
            gemm_tc<<<dim3(HH/128, M/128, 3), 512, GEMM_SMEM>>>(a);
        }
        reduce_ln<<<M, 256>>>(p0_, p1_, p2_, bao + l*HH, hin,
                              g1 + l*HH, b1 + l*HH, attn_, aah_, aal_);

        // FFN1 (gelu) -> bf16 hi/lo
        {
            GemmArgs a = {};
            a.ah = aah_; a.al = aal_;
            a.bh0 = wh_+lo+WIOFF; a.bh1 = a.bh0; a.bh2 = a.bh0;
            a.bl0 = wl_+lo+WIOFF; a.bl1 = a.bl0; a.bl2 = a.bl0;
            a.bias0 = bi + l*FF; a.bias1 = a.bias0; a.bias2 = a.bias0;
            a.ch0 = ih_; a.cl0 = il_; a.ch1 = ih_; a.cl1 = il_; a.ch2 = ih_; a.cl2 = il_;
            a.K = HH; a.N = FF; a.gelu = 1; a.outbf = 1; a.Kld = HH; a.ksplit = 0;
            gemm_tc<<<dim3(FF/128, M/128, 1), 512, GEMM_SMEM>>>(a);
        }

        // FFN2: split-K=3 -> partials -> fused reduce+LN
        {
            GemmArgs a = {};
            a.ah = ih_; a.al = il_;
            a.bh0 = wh_+lo+WFOOFF; a.bh1 = a.bh0; a.bh2 = a.bh0;
            a.bl0 = wl_+lo+WFOOFF; a.bl1 = a.bl0; a.bl2 = a.bl0;
            a.c0 = p0_; a.c1 = p1_; a.c2 = p2_;
            a.K = 1024; a.N = HH; a.gelu = 0; a.outbf = 0; a.Kld = FF; a.ksplit = 1;
            gemm_tc<<<dim3(HH/128, M/128, 3), 512, GEMM_SMEM>>>(a);
        }
        if (l == NL - 1) {
            reduce_ln<<<M, 256>>>(p0_, p1_, p2_, bfo + l*HH, attn_,
                                  g2 + l*HH, b2 + l*HH, (float*)d_out,
                                  (__nv_bfloat16*)nullptr, (__nv_bfloat16*)nullptr);
        } else {
            reduce_ln<<<M, 256>>>(p0_, p1_, p2_, bfo + l*HH, attn_,
                                  g2 + l*HH, b2 + l*HH, h_, hh_, hl_);
        }
    }
}